// round 6
// baseline (speedup 1.0000x reference)
#include <cuda_runtime.h>
#include <math.h>
#include <float.h>
#include <stdint.h>

#define Bc 4
#define Lc 2048
#define Dc 1024
#define Fc 4096
#define BHc 64
#define Uc 2048
#define TOPK 40
#define MR 8192

// ---------------- scratch --------------------------------------------------
__device__ float g_Q [MR * Dc];
__device__ float g_K [MR * Dc];
__device__ float g_V [MR * Dc];
__device__ float g_Ksg[BHc * Uc * 64];
__device__ float g_AO[MR * Dc];
__device__ float g_X1[MR * Dc];
__device__ float g_Y1[MR * Fc];
__device__ float g_Y2[MR * Dc];
__device__ float g_M [BHc * Lc];
__device__ int   g_Mtop[BHc * TOPK];
__device__ float g_Or[BHc * TOPK * 64];
__device__ float g_Wqt[Dc * Dc];
__device__ float g_Wkt[Dc * Dc];
__device__ float g_Wvt[Dc * Dc];
__device__ float g_W1t[Dc * Fc];
__device__ float g_W2t[Fc * Dc];

// ---------------- helpers --------------------------------------------------
__device__ __forceinline__ uint32_t s2u(const void* p) {
    uint32_t a;
    asm("{ .reg .u64 t; cvta.to.shared.u64 t, %1; cvt.u32.u64 %0, t; }" : "=r"(a) : "l"(p));
    return a;
}
__device__ __forceinline__ float f2t(float a) {
    uint32_t u;
    asm("cvt.rna.tf32.f32 %0, %1;" : "=r"(u) : "f"(a));
    return __uint_as_float(u);
}
__device__ __forceinline__ void split2(float v, uint32_t& h, uint32_t& l) {
    float hf = f2t(v);
    h = __float_as_uint(hf);
    l = __float_as_uint(f2t(v - hf));
}
__device__ __forceinline__ void cpa16(uint32_t dst, const void* src) {
    asm volatile("cp.async.ca.shared.global [%0], [%1], 16;" :: "r"(dst), "l"(src));
}
__device__ __forceinline__ void cpcommit() {
    asm volatile("cp.async.commit_group;");
}
template <int N>
__device__ __forceinline__ void cpwait() {
    asm volatile("cp.async.wait_group %0;" :: "n"(N));
}
// d += a * b  (m16n8k8 tf32)
__device__ __forceinline__ void mma8(float* d, const uint32_t* a, const uint32_t* b) {
    asm volatile(
        "mma.sync.aligned.m16n8k8.row.col.f32.tf32.tf32.f32 "
        "{%0,%1,%2,%3}, {%4,%5,%6,%7}, {%8,%9}, {%0,%1,%2,%3};"
        : "+f"(d[0]), "+f"(d[1]), "+f"(d[2]), "+f"(d[3])
        : "r"(a[0]), "r"(a[1]), "r"(a[2]), "r"(a[3]), "r"(b[0]), "r"(b[1]));
}

// ---------------- 3xTF32 mma.sync GEMM, raw-fp32 staging -------------------
// C[M,N] = A(M x Kd) @ (Bt[N,Kd])^T + bias (opt relu); split to tf32 hi/lo in regs.
// stage s (3 stages, 36864 B each): A at s*36864, B at s*36864+18432; row stride 144B.
#define GST2 36864
__global__ __launch_bounds__(256, 1) void gemm_mma(
    const float* __restrict__ A, const float* __restrict__ Bt,
    const float* __restrict__ bias, float* __restrict__ C,
    int Kd, int Nd, int relu)
{
    extern __shared__ float smem[];
    uint32_t sb = s2u(smem);
    int tid = threadIdx.x, lane = tid & 31, wid = tid >> 5;
    int m0 = blockIdx.y * 128, n0 = blockIdx.x * 128;
    int wr = wid >> 1, wc = wid & 1;          // warp tile 32x64
    int NC = Kd >> 5;

    const float* Ab = A + (size_t)m0 * Kd;
    const float* Bb = Bt + (size_t)n0 * Kd;

    float c[2][8][4];
#pragma unroll
    for (int i = 0; i < 2; i++)
#pragma unroll
        for (int j = 0; j < 8; j++)
#pragma unroll
            for (int r = 0; r < 4; r++) c[i][j][r] = 0.f;

    int rld = tid >> 3, cld = tid & 7;        // 32 rows x 8 segs; 4 passes stride 32

#pragma unroll
    for (int pre = 0; pre < 2; pre++) {       // preload stages 0,1
        int k0 = pre << 5;
        uint32_t st = sb + pre * GST2;
#pragma unroll
        for (int rr = 0; rr < 4; rr++) {
            uint32_t dof = (rld + rr * 32) * 144 + cld * 16;
            cpa16(st + dof,         Ab + (size_t)(rld + rr * 32) * Kd + k0 + cld * 4);
            cpa16(st + 18432 + dof, Bb + (size_t)(rld + rr * 32) * Kd + k0 + cld * 4);
        }
        cpcommit();
    }

    for (int ch = 0; ch < NC; ch++) {
        int s = ch % 3;
        if (ch + 2 < NC) {
            int k0 = (ch + 2) << 5;
            uint32_t st = sb + ((ch + 2) % 3) * GST2;
#pragma unroll
            for (int rr = 0; rr < 4; rr++) {
                uint32_t dof = (rld + rr * 32) * 144 + cld * 16;
                cpa16(st + dof,         Ab + (size_t)(rld + rr * 32) * Kd + k0 + cld * 4);
                cpa16(st + 18432 + dof, Bb + (size_t)(rld + rr * 32) * Kd + k0 + cld * 4);
            }
            cpcommit();
            cpwait<2>();
        } else if (ch + 2 == NC) {
            cpwait<1>();
        } else {
            cpwait<0>();
        }
        __syncthreads();

        const float* sA = smem + (s * GST2) / 4;
        const float* sB = sA + 18432 / 4;
        int ar = wr * 32 + (lane >> 2);
        int bn = wc * 64 + (lane >> 2);
        int kq = lane & 3;

#pragma unroll
        for (int st = 0; st < 4; st++) {
            int k0 = st * 8 + kq;
            uint32_t ah[2][4], al[2][4], bh2[8][2], bl2[8][2];
#pragma unroll
            for (int mt = 0; mt < 2; mt++) {
                int r0 = ar + mt * 16;
                split2(sA[r0 * 36 + k0],           ah[mt][0], al[mt][0]);
                split2(sA[(r0 + 8) * 36 + k0],     ah[mt][1], al[mt][1]);
                split2(sA[r0 * 36 + k0 + 4],       ah[mt][2], al[mt][2]);
                split2(sA[(r0 + 8) * 36 + k0 + 4], ah[mt][3], al[mt][3]);
            }
#pragma unroll
            for (int nt = 0; nt < 8; nt++) {
                int n = bn + nt * 8;
                split2(sB[n * 36 + k0],     bh2[nt][0], bl2[nt][0]);
                split2(sB[n * 36 + k0 + 4], bh2[nt][1], bl2[nt][1]);
            }
#pragma unroll
            for (int mt = 0; mt < 2; mt++)
#pragma unroll
                for (int nt = 0; nt < 8; nt++) {
                    mma8(c[mt][nt], ah[mt], bh2[nt]);
                    mma8(c[mt][nt], ah[mt], bl2[nt]);
                    mma8(c[mt][nt], al[mt], bh2[nt]);
                }
        }
        __syncthreads();
    }

    // epilogue
#pragma unroll
    for (int mt = 0; mt < 2; mt++) {
        int row = m0 + wr * 32 + mt * 16 + (lane >> 2);
#pragma unroll
        for (int nt = 0; nt < 8; nt++) {
            int col = n0 + wc * 64 + nt * 8 + (lane & 3) * 2;
            float b0 = bias[col], b1 = bias[col + 1];
            float2 v0 = make_float2(c[mt][nt][0] + b0, c[mt][nt][1] + b1);
            float2 v1 = make_float2(c[mt][nt][2] + b0, c[mt][nt][3] + b1);
            if (relu) {
                v0.x = fmaxf(v0.x, 0.f); v0.y = fmaxf(v0.y, 0.f);
                v1.x = fmaxf(v1.x, 0.f); v1.y = fmaxf(v1.y, 0.f);
            }
            *(float2*)(C + (size_t)row * Nd + col) = v0;
            *(float2*)(C + (size_t)(row + 8) * Nd + col) = v1;
        }
    }
}

// ---------------- QK stats: M = rowmax - rowsum/L --------------------------
// Q tile fp32 staged, split ONCE into smem hi/lo; K chunks (64 rows) raw staged,
// split in regs. smem floats: sQh 0, sQl 8704, Bst 17408 + s*4352, red 30464.
__global__ __launch_bounds__(256, 1) void qk_mma(
    const float* __restrict__ Qf, const float* __restrict__ Ks,
    float* __restrict__ Mout)
{
    extern __shared__ float smem[];
    uint32_t sb = s2u(smem);
    int tid = threadIdx.x, lane = tid & 31, wid = tid >> 5;
    int m0 = blockIdx.x * 128, bh = blockIdx.y;
    int wr = wid >> 1, wc = wid & 1;

    // stage Q tile (128 x 64) and split to hi/lo smem, row stride 68 floats
    {
        const float* qb = Qf + ((size_t)bh * Lc + m0) * 64;
#pragma unroll
        for (int i = 0; i < 8; i++) {
            int idx = tid + i * 256;
            int r = idx >> 4, cc = idx & 15;
            float4 v = *(const float4*)(qb + (size_t)r * 64 + cc * 4);
            float4 h, l;
            h.x = f2t(v.x); l.x = f2t(v.x - h.x);
            h.y = f2t(v.y); l.y = f2t(v.y - h.y);
            h.z = f2t(v.z); l.z = f2t(v.z - h.z);
            h.w = f2t(v.w); l.w = f2t(v.w - h.w);
            *(float4*)(smem + r * 68 + cc * 4) = h;
            *(float4*)(smem + 8704 + r * 68 + cc * 4) = l;
        }
    }

    const float* kb = Ks + (size_t)bh * Uc * 64;
    int rld = tid >> 2, cld = tid & 3;   // 64 rows x 4 segs, 4 passes (seg stride 4)

#pragma unroll
    for (int pre = 0; pre < 2; pre++) {
        uint32_t st = sb + 69632 + pre * 17408;   // 17408*4? careful: byte offsets
        // byte base: (17408 floats)*4 = 69632 B; stage stride 4352 floats = 17408 B
        const float* src = kb + (size_t)(pre * 64 + rld) * 64 + cld * 4;
        uint32_t d0 = st + rld * 272 + cld * 16;
        cpa16(d0,       src);
        cpa16(d0 + 64,  src + 16);
        cpa16(d0 + 128, src + 32);
        cpa16(d0 + 192, src + 48);
        cpcommit();
    }
    __syncthreads();

    float rmax[2][2], rsum[2][2];
#pragma unroll
    for (int i = 0; i < 2; i++)
#pragma unroll
        for (int j = 0; j < 2; j++) { rmax[i][j] = -FLT_MAX; rsum[i][j] = 0.f; }

    for (int ch = 0; ch < 32; ch++) {
        int s = ch % 3;
        if (ch + 2 < 32) {
            const float* src = kb + (size_t)((ch + 2) * 64 + rld) * 64 + cld * 4;
            uint32_t d0 = sb + 69632 + ((ch + 2) % 3) * 17408 + rld * 272 + cld * 16;
            cpa16(d0,       src);
            cpa16(d0 + 64,  src + 16);
            cpa16(d0 + 128, src + 32);
            cpa16(d0 + 192, src + 48);
            cpcommit();
            cpwait<2>();
        } else if (ch + 2 == 32) {
            cpwait<1>();
        } else {
            cpwait<0>();
        }
        __syncthreads();

        const float* sQh = smem;
        const float* sQl = smem + 8704;
        const float* sB  = smem + 17408 + s * 4352;
        int ar = wr * 32 + (lane >> 2);
        int bn = wc * 32 + (lane >> 2);
        int kq = lane & 3;

        float c[2][4][4];
#pragma unroll
        for (int i = 0; i < 2; i++)
#pragma unroll
            for (int j = 0; j < 4; j++)
#pragma unroll
                for (int r = 0; r < 4; r++) c[i][j][r] = 0.f;

#pragma unroll
        for (int st = 0; st < 8; st++) {
            int k0 = st * 8 + kq;
            uint32_t ah[2][4], al[2][4], bh2[4][2], bl2[4][2];
#pragma unroll
            for (int mt = 0; mt < 2; mt++) {
                int r0 = ar + mt * 16;
                ah[mt][0] = __float_as_uint(sQh[r0 * 68 + k0]);
                ah[mt][1] = __float_as_uint(sQh[(r0 + 8) * 68 + k0]);
                ah[mt][2] = __float_as_uint(sQh[r0 * 68 + k0 + 4]);
                ah[mt][3] = __float_as_uint(sQh[(r0 + 8) * 68 + k0 + 4]);
                al[mt][0] = __float_as_uint(sQl[r0 * 68 + k0]);
                al[mt][1] = __float_as_uint(sQl[(r0 + 8) * 68 + k0]);
                al[mt][2] = __float_as_uint(sQl[r0 * 68 + k0 + 4]);
                al[mt][3] = __float_as_uint(sQl[(r0 + 8) * 68 + k0 + 4]);
            }
#pragma unroll
            for (int nt = 0; nt < 4; nt++) {
                int n = bn + nt * 8;
                split2(sB[n * 68 + k0],     bh2[nt][0], bl2[nt][0]);
                split2(sB[n * 68 + k0 + 4], bh2[nt][1], bl2[nt][1]);
            }
#pragma unroll
            for (int mt = 0; mt < 2; mt++)
#pragma unroll
                for (int nt = 0; nt < 4; nt++) {
                    mma8(c[mt][nt], ah[mt], bh2[nt]);
                    mma8(c[mt][nt], ah[mt], bl2[nt]);
                    mma8(c[mt][nt], al[mt], bh2[nt]);
                }
        }

#pragma unroll
        for (int mt = 0; mt < 2; mt++)
#pragma unroll
            for (int hf = 0; hf < 2; hf++) {
                float mx = -FLT_MAX, sm = 0.f;
#pragma unroll
                for (int nt = 0; nt < 4; nt++) {
                    float v0 = c[mt][nt][hf * 2], v1 = c[mt][nt][hf * 2 + 1];
                    mx = fmaxf(mx, fmaxf(v0, v1));
                    sm += v0 + v1;
                }
                mx = fmaxf(mx, __shfl_xor_sync(0xffffffffu, mx, 1));
                sm += __shfl_xor_sync(0xffffffffu, sm, 1);
                mx = fmaxf(mx, __shfl_xor_sync(0xffffffffu, mx, 2));
                sm += __shfl_xor_sync(0xffffffffu, sm, 2);
                rmax[mt][hf] = fmaxf(rmax[mt][hf], mx);
                rsum[mt][hf] += sm;
            }
        __syncthreads();
    }

    float* red = smem + 30464;   // [2][128][2]
    if ((lane & 3) == 0) {
#pragma unroll
        for (int mt = 0; mt < 2; mt++)
#pragma unroll
            for (int hf = 0; hf < 2; hf++) {
                int row = wr * 32 + mt * 16 + (lane >> 2) + hf * 8;
                red[(wc * 128 + row) * 2 + 0] = rmax[mt][hf];
                red[(wc * 128 + row) * 2 + 1] = rsum[mt][hf];
            }
    }
    __syncthreads();
    if (tid < 128) {
        float m0v = red[tid * 2], s0v = red[tid * 2 + 1];
        float m1v = red[(128 + tid) * 2], s1v = red[(128 + tid) * 2 + 1];
        Mout[(size_t)bh * Lc + m0 + tid] =
            fmaxf(m0v, m1v) - (s0v + s1v) * (1.f / (float)Lc);
    }
}

// ---------------- transpose weights: W[K,N] -> Wt[N,K] ---------------------
__global__ void ttrans_kernel(const float* __restrict__ W, float* __restrict__ Wt,
                              int Kd, int Nd)
{
    __shared__ float t[32][33];
    int x = threadIdx.x, y = threadIdx.y;
    int n0 = blockIdx.x * 32, k0 = blockIdx.y * 32;
#pragma unroll
    for (int i = 0; i < 32; i += 8)
        t[y + i][x] = W[(size_t)(k0 + y + i) * Nd + n0 + x];
    __syncthreads();
#pragma unroll
    for (int i = 0; i < 32; i += 8)
        Wt[(size_t)(n0 + y + i) * Kd + k0 + x] = t[x][y + i];
}

// ---------------- gather sampled keys head-major ---------------------------
__global__ void gather_kernel(const float* __restrict__ K, const int* __restrict__ idx,
                              float* __restrict__ Ksg)
{
    int j = blockIdx.x, b = blockIdx.y, t = threadIdx.x;
    int src = idx[j];
    float4 v = *(const float4*)(K + ((size_t)b * Lc + src) * Dc + t * 4);
    int h = t >> 4, e = (t & 15) * 4;
    *(float4*)(Ksg + (((size_t)(b * 16 + h)) * Uc + j) * 64 + e) = v;
}

// ---------------- top-40 smallest M (ties -> lower index) ------------------
__global__ __launch_bounds__(256) void topk_kernel(const float* __restrict__ Mv,
                                                   int* __restrict__ Mtop)
{
    __shared__ float sv[Lc];
    __shared__ float rv[256];
    __shared__ int   ri[256];
    int bh = blockIdx.x, tid = threadIdx.x;
    for (int i = tid; i < Lc; i += 256) sv[i] = Mv[(size_t)bh * Lc + i];
    __syncthreads();
    for (int it = 0; it < TOPK; it++) {
        float bv = FLT_MAX; int bi = 0x7fffffff;
        for (int i = tid; i < Lc; i += 256) {
            float v = sv[i];
            if (v < bv || (v == bv && i < bi)) { bv = v; bi = i; }
        }
        rv[tid] = bv; ri[tid] = bi;
        __syncthreads();
        for (int s = 128; s > 0; s >>= 1) {
            if (tid < s) {
                float v2 = rv[tid + s]; int i2 = ri[tid + s];
                if (v2 < rv[tid] || (v2 == rv[tid] && i2 < ri[tid])) {
                    rv[tid] = v2; ri[tid] = i2;
                }
            }
            __syncthreads();
        }
        if (tid == 0) { Mtop[bh * TOPK + it] = ri[0]; sv[ri[0]] = FLT_MAX; }
        __syncthreads();
    }
}

// ---------------- sparse attention for one selected query ------------------
__global__ __launch_bounds__(128) void sparse_attn_kernel(
    const float* __restrict__ Q, const float* __restrict__ K, const float* __restrict__ V,
    const int* __restrict__ Mtop, float* __restrict__ outred)
{
    int ui = blockIdx.x, bh = blockIdx.y;
    int b = bh >> 4, h = bh & 15;
    int qi = Mtop[bh * TOPK + ui];
    __shared__ float qsh[64];
    __shared__ float wm[4], ws[4], wa[4][64];
    int tid = threadIdx.x, warp = tid >> 5, lane = tid & 31;
    if (tid < 64) qsh[tid] = Q[((size_t)bh * Lc + qi) * 64 + tid];
    __syncthreads();
    float q0v = qsh[lane], q1v = qsh[lane + 32];
    float m = -FLT_MAX, s = 0.f, a0 = 0.f, a1 = 0.f;
    const float* kb = K + (size_t)b * Lc * Dc + h * 64;
    const float* vb = V + (size_t)b * Lc * Dc + h * 64;
    for (int l = warp * 512; l < warp * 512 + 512; l++) {
        const float* kr = kb + (size_t)l * Dc;
        float p = q0v * kr[lane] + q1v * kr[lane + 32];
#pragma unroll
        for (int off = 16; off > 0; off >>= 1)
            p += __shfl_xor_sync(0xffffffffu, p, off);
        p *= 0.125f;
        float mn = fmaxf(m, p);
        float c = expf(m - mn);
        float w = expf(p - mn);
        const float* vr = vb + (size_t)l * Dc;
        s  = s * c + w;
        a0 = a0 * c + w * vr[lane];
        a1 = a1 * c + w * vr[lane + 32];
        m = mn;
    }
    if (lane == 0) { wm[warp] = m; ws[warp] = s; }
    wa[warp][lane] = a0; wa[warp][lane + 32] = a1;
    __syncthreads();
    if (tid < 64) {
        float gm = fmaxf(fmaxf(wm[0], wm[1]), fmaxf(wm[2], wm[3]));
        float gs = 0.f, ga = 0.f;
#pragma unroll
        for (int w2 = 0; w2 < 4; w2++) {
            float f = expf(wm[w2] - gm);
            gs += ws[w2] * f;
            ga += wa[w2][tid] * f;
        }
        outred[((size_t)bh * TOPK + ui) * 64 + tid] = ga / gs;
    }
}

__global__ void init_bias_kernel(const float* __restrict__ bo, float* __restrict__ AO)
{
    float4 v = *(const float4*)(bo + threadIdx.x * 4);
    *(float4*)(AO + (size_t)blockIdx.x * Dc + threadIdx.x * 4) = v;
}

__global__ __launch_bounds__(256) void sparse_proj_kernel(
    const float* __restrict__ outred, const int* __restrict__ Mtop,
    const float* __restrict__ wo, float* __restrict__ AO)
{
    int ui = blockIdx.x, bh = blockIdx.y;
    int b = bh >> 4, h = bh & 15;
    int l = Mtop[bh * TOPK + ui];
    __shared__ float r[64];
    int tid = threadIdx.x;
    if (tid < 64) r[tid] = outred[((size_t)bh * TOPK + ui) * 64 + tid];
    __syncthreads();
    float a0 = 0.f, a1 = 0.f, a2 = 0.f, a3 = 0.f;
    const float* w = wo + (size_t)h * 64 * Dc + tid;
#pragma unroll 8
    for (int e = 0; e < 64; e++) {
        float re = r[e];
        const float* wr = w + (size_t)e * Dc;
        a0 = fmaf(re, wr[0],   a0);
        a1 = fmaf(re, wr[256], a1);
        a2 = fmaf(re, wr[512], a2);
        a3 = fmaf(re, wr[768], a3);
    }
    float* dst = AO + ((size_t)b * Lc + l) * Dc + tid;
    atomicAdd(dst,       a0);
    atomicAdd(dst + 256, a1);
    atomicAdd(dst + 512, a2);
    atomicAdd(dst + 768, a3);
}

__global__ __launch_bounds__(256) void add_ln_kernel(
    const float* __restrict__ X, const float* __restrict__ Y,
    const float* __restrict__ g, const float* __restrict__ be, float* __restrict__ out)
{
    int row = blockIdx.x, tid = threadIdx.x;
    __shared__ float red[256];
    float v[4];
    float s = 0.f;
#pragma unroll
    for (int c = 0; c < 4; c++) {
        size_t i = (size_t)row * Dc + tid + c * 256;
        v[c] = X[i] + Y[i];
        s += v[c];
    }
    red[tid] = s; __syncthreads();
    for (int st = 128; st > 0; st >>= 1) {
        if (tid < st) red[tid] += red[tid + st];
        __syncthreads();
    }
    float mean = red[0] * (1.f / 1024.f);
    __syncthreads();
    float s2 = 0.f;
#pragma unroll
    for (int c = 0; c < 4; c++) { float t = v[c] - mean; s2 = fmaf(t, t, s2); }
    red[tid] = s2; __syncthreads();
    for (int st = 128; st > 0; st >>= 1) {
        if (tid < st) red[tid] += red[tid + st];
        __syncthreads();
    }
    float var = red[0] * (1.f / 1024.f);
    float rstd = 1.0f / sqrtf(var + 1e-12f);
#pragma unroll
    for (int c = 0; c < 4; c++) {
        int col = tid + c * 256;
        out[(size_t)row * Dc + col] = g[col] * ((v[c] - mean) * rstd) + be[col];
    }
}

// ---------------- launch ---------------------------------------------------
extern "C" void kernel_launch(void* const* d_in, const int* in_sizes, int n_in,
                              void* d_out, int out_size)
{
    const float* x   = (const float*)d_in[0];
    const float* wq  = (const float*)d_in[1];
    const float* bq  = (const float*)d_in[2];
    const float* wk  = (const float*)d_in[3];
    const float* bk  = (const float*)d_in[4];
    const float* wv  = (const float*)d_in[5];
    const float* bv  = (const float*)d_in[6];
    const float* wo  = (const float*)d_in[7];
    const float* bo  = (const float*)d_in[8];
    const float* w1  = (const float*)d_in[9];
    const float* b1  = (const float*)d_in[10];
    const float* w2  = (const float*)d_in[11];
    const float* b2  = (const float*)d_in[12];
    const float* ga1 = (const float*)d_in[13];
    const float* be1 = (const float*)d_in[14];
    const float* ga2 = (const float*)d_in[15];
    const float* be2 = (const float*)d_in[16];
    const int*   idx = (const int*)d_in[17];
    float* out = (float*)d_out;

    float *Q, *K, *V, *Ksg, *AO, *X1, *Y1, *Y2, *Mv, *Or;
    float *Wqt, *Wkt, *Wvt, *W1t, *W2t;
    int* Mt;
    cudaGetSymbolAddress((void**)&Q,   g_Q);
    cudaGetSymbolAddress((void**)&K,   g_K);
    cudaGetSymbolAddress((void**)&V,   g_V);
    cudaGetSymbolAddress((void**)&Ksg, g_Ksg);
    cudaGetSymbolAddress((void**)&AO,  g_AO);
    cudaGetSymbolAddress((void**)&X1,  g_X1);
    cudaGetSymbolAddress((void**)&Y1,  g_Y1);
    cudaGetSymbolAddress((void**)&Y2,  g_Y2);
    cudaGetSymbolAddress((void**)&Mv,  g_M);
    cudaGetSymbolAddress((void**)&Mt,  g_Mtop);
    cudaGetSymbolAddress((void**)&Or,  g_Or);
    cudaGetSymbolAddress((void**)&Wqt, g_Wqt);
    cudaGetSymbolAddress((void**)&Wkt, g_Wkt);
    cudaGetSymbolAddress((void**)&Wvt, g_Wvt);
    cudaGetSymbolAddress((void**)&W1t, g_W1t);
    cudaGetSymbolAddress((void**)&W2t, g_W2t);

    cudaFuncSetAttribute(gemm_mma, cudaFuncAttributeMaxDynamicSharedMemorySize, 3 * GST2);
    cudaFuncSetAttribute(qk_mma,   cudaFuncAttributeMaxDynamicSharedMemorySize, 124928);

    dim3 t32x8(32, 8);
    ttrans_kernel<<<dim3(Dc / 32, Dc / 32), t32x8>>>(wq, Wqt, Dc, Dc);
    ttrans_kernel<<<dim3(Dc / 32, Dc / 32), t32x8>>>(wk, Wkt, Dc, Dc);
    ttrans_kernel<<<dim3(Dc / 32, Dc / 32), t32x8>>>(wv, Wvt, Dc, Dc);
    ttrans_kernel<<<dim3(Fc / 32, Dc / 32), t32x8>>>(w1, W1t, Dc, Fc);
    ttrans_kernel<<<dim3(Dc / 32, Fc / 32), t32x8>>>(w2, W2t, Fc, Dc);

    gemm_mma<<<dim3(8, 64), 256, 3 * GST2>>>(x, Wqt, bq, Q, Dc, Dc, 0);
    gemm_mma<<<dim3(8, 64), 256, 3 * GST2>>>(x, Wkt, bk, K, Dc, Dc, 0);
    gemm_mma<<<dim3(8, 64), 256, 3 * GST2>>>(x, Wvt, bv, V, Dc, Dc, 0);

    gather_kernel<<<dim3(Uc, Bc), 256>>>(K, idx, Ksg);
    qk_mma<<<dim3(Lc / 128, BHc), 256, 124928>>>(Q, Ksg, Mv);
    topk_kernel<<<BHc, 256>>>(Mv, Mt);

    sparse_attn_kernel<<<dim3(TOPK, BHc), 128>>>(Q, K, V, Mt, Or);

    init_bias_kernel<<<MR, 256>>>(bo, AO);
    sparse_proj_kernel<<<dim3(TOPK, BHc), 256>>>(Or, Mt, wo, AO);

    add_ln_kernel<<<MR, 256>>>(x, AO, ga1, be1, X1);

    gemm_mma<<<dim3(32, 64), 256, 3 * GST2>>>(X1, W1t, b1, Y1, Dc, Fc, 1);
    gemm_mma<<<dim3(8, 64), 256, 3 * GST2>>>(Y1, W2t, b2, Y2, Fc, Dc, 0);

    add_ln_kernel<<<MR, 256>>>(X1, Y2, ga2, be2, out);
}

// round 9
// speedup vs baseline: 1.3523x; 1.3523x over previous
#include <cuda_runtime.h>
#include <cuda_bf16.h>
#include <math.h>
#include <float.h>
#include <stdint.h>

#define Bc 4
#define Lc 2048
#define Dc 1024
#define Fc 4096
#define BHc 64
#define Uc 2048
#define TOPK 40
#define MR 8192

typedef __nv_bfloat16 bf16;
typedef __nv_bfloat162 bf162;

// ---------------- scratch (bf16 arrays 16B aligned: 16B vector ops used) -----
__device__ float g_Q [MR * Dc];
__device__ float g_K [MR * Dc];
__device__ float g_V [MR * Dc];
__device__ float g_AO[MR * Dc];
__device__ float g_X1[MR * Dc];
__device__ float g_Y2[MR * Dc];
__device__ float g_M [BHc * Lc];
__device__ int   g_Mtop[BHc * TOPK];
__device__ float g_Or[BHc * TOPK * 64];
__device__ __align__(16) bf16 g_Xbh[MR * Dc],  g_Xbl[MR * Dc];
__device__ __align__(16) bf16 g_Qbh[MR * Dc],  g_Qbl[MR * Dc];
__device__ __align__(16) bf16 g_X1bh[MR * Dc], g_X1bl[MR * Dc];
__device__ __align__(16) bf16 g_Y1bh[MR * Fc], g_Y1bl[MR * Fc];
__device__ __align__(16) bf16 g_Ksbh[BHc * Uc * 64], g_Ksbl[BHc * Uc * 64];
__device__ __align__(16) bf16 g_Wqh[Dc * Dc], g_Wql[Dc * Dc];
__device__ __align__(16) bf16 g_Wkh[Dc * Dc], g_Wkl[Dc * Dc];
__device__ __align__(16) bf16 g_Wvh[Dc * Dc], g_Wvl[Dc * Dc];
__device__ __align__(16) bf16 g_W1h[Dc * Fc], g_W1l[Dc * Fc];
__device__ __align__(16) bf16 g_W2h[Fc * Dc], g_W2l[Fc * Dc];

// ---------------- helpers --------------------------------------------------
__device__ __forceinline__ uint32_t s2u(const void* p) {
    uint32_t a;
    asm("{ .reg .u64 t; cvta.to.shared.u64 t, %1; cvt.u32.u64 %0, t; }" : "=r"(a) : "l"(p));
    return a;
}
__device__ __forceinline__ void cpa16(uint32_t dst, const void* src) {
    asm volatile("cp.async.ca.shared.global [%0], [%1], 16;" :: "r"(dst), "l"(src));
}
__device__ __forceinline__ void cpcommit() {
    asm volatile("cp.async.commit_group;");
}
template <int N>
__device__ __forceinline__ void cpwait() {
    asm volatile("cp.async.wait_group %0;" :: "n"(N));
}
// d += a * b  (m16n8k16 bf16)
__device__ __forceinline__ void mma16(float* d, const uint32_t* a, const uint32_t* b) {
    asm volatile(
        "mma.sync.aligned.m16n8k16.row.col.f32.bf16.bf16.f32 "
        "{%0,%1,%2,%3}, {%4,%5,%6,%7}, {%8,%9}, {%0,%1,%2,%3};"
        : "+f"(d[0]), "+f"(d[1]), "+f"(d[2]), "+f"(d[3])
        : "r"(a[0]), "r"(a[1]), "r"(a[2]), "r"(a[3]), "r"(b[0]), "r"(b[1]));
}
__device__ __forceinline__ void bsplit(float v, bf16& h, bf16& l) {
    h = __float2bfloat16_rn(v);
    l = __float2bfloat16_rn(v - __bfloat162float(h));
}

// ---------------- bf16x3 mma.sync GEMM -------------------------------------
// C[M,N] = (Ah+Al)(M x Kd) @ ((Bh+Bl)[N,Kd])^T + bias (opt relu)
// smem stage (40960 B): Ah +0, Al +10240, Bh +20480, Bl +30720.
// Row stride 80 B (20 u32): 64 B data + 16 B pad -> cp.async-16 aligned,
// 8rows x 4kq fragment loads bank-conflict-free.
#define GSTB 40960
__global__ __launch_bounds__(256, 1) void gemm_bf(
    const bf16* __restrict__ Ah, const bf16* __restrict__ Al,
    const bf16* __restrict__ Bh, const bf16* __restrict__ Bl,
    const float* __restrict__ bias, float* __restrict__ C,
    bf16* __restrict__ Ch, bf16* __restrict__ Cl,
    int Kd, int Nd, int relu)
{
    extern __shared__ uint32_t smem_u[];
    uint32_t sb = s2u(smem_u);
    int tid = threadIdx.x, lane = tid & 31, wid = tid >> 5;
    int m0 = blockIdx.y * 128, n0 = blockIdx.x * 128;
    int wr = wid >> 1, wc = wid & 1;          // warp tile 32x64
    int NC = Kd >> 5;

    const bf16* gsrc[4] = { Ah + (size_t)m0 * Kd, Al + (size_t)m0 * Kd,
                            Bh + (size_t)n0 * Kd, Bl + (size_t)n0 * Kd };

    float c[2][8][4];
#pragma unroll
    for (int i = 0; i < 2; i++)
#pragma unroll
        for (int j = 0; j < 8; j++)
#pragma unroll
            for (int r = 0; r < 4; r++) c[i][j][r] = 0.f;

    int rld = tid >> 1, sgp = tid & 1;        // 128 rows x 2 halves (each 2x16B)

#pragma unroll
    for (int pre = 0; pre < 2; pre++) {
        int k0 = pre << 5;
        uint32_t st = sb + pre * GSTB;
#pragma unroll
        for (int a4 = 0; a4 < 4; a4++) {
            uint32_t dst = st + a4 * 10240 + rld * 80 + sgp * 32;
            const bf16* src = gsrc[a4] + (size_t)rld * Kd + k0 + sgp * 16;
            cpa16(dst, src);
            cpa16(dst + 16, src + 8);
        }
        cpcommit();
    }

    for (int ch = 0; ch < NC; ch++) {
        int s = ch % 3;
        if (ch + 2 < NC) {
            int k0 = (ch + 2) << 5;
            uint32_t st = sb + ((ch + 2) % 3) * GSTB;
#pragma unroll
            for (int a4 = 0; a4 < 4; a4++) {
                uint32_t dst = st + a4 * 10240 + rld * 80 + sgp * 32;
                const bf16* src = gsrc[a4] + (size_t)rld * Kd + k0 + sgp * 16;
                cpa16(dst, src);
                cpa16(dst + 16, src + 8);
            }
            cpcommit();
            cpwait<2>();
        } else if (ch + 2 == NC) {
            cpwait<1>();
        } else {
            cpwait<0>();
        }
        __syncthreads();

        const uint32_t* sAh = smem_u + (s * GSTB) / 4;
        const uint32_t* sAl = sAh + 2560;
        const uint32_t* sBh = sAh + 5120;
        const uint32_t* sBl = sAh + 7680;
        int ar = wr * 32 + (lane >> 2);
        int bn = wc * 64 + (lane >> 2);
        int kq = lane & 3;

#pragma unroll
        for (int st = 0; st < 2; st++) {
            int ko = st * 8 + kq;
            uint32_t ah[2][4], al[2][4], bhf[8][2], blf[8][2];
#pragma unroll
            for (int mt = 0; mt < 2; mt++) {
                int r0 = ar + mt * 16;
                ah[mt][0] = sAh[r0 * 20 + ko];
                ah[mt][1] = sAh[(r0 + 8) * 20 + ko];
                ah[mt][2] = sAh[r0 * 20 + ko + 4];
                ah[mt][3] = sAh[(r0 + 8) * 20 + ko + 4];
                al[mt][0] = sAl[r0 * 20 + ko];
                al[mt][1] = sAl[(r0 + 8) * 20 + ko];
                al[mt][2] = sAl[r0 * 20 + ko + 4];
                al[mt][3] = sAl[(r0 + 8) * 20 + ko + 4];
            }
#pragma unroll
            for (int nt = 0; nt < 8; nt++) {
                int n = bn + nt * 8;
                bhf[nt][0] = sBh[n * 20 + ko];
                bhf[nt][1] = sBh[n * 20 + ko + 4];
                blf[nt][0] = sBl[n * 20 + ko];
                blf[nt][1] = sBl[n * 20 + ko + 4];
            }
#pragma unroll
            for (int mt = 0; mt < 2; mt++)
#pragma unroll
                for (int nt = 0; nt < 8; nt++) {
                    mma16(c[mt][nt], ah[mt], bhf[nt]);
                    mma16(c[mt][nt], ah[mt], blf[nt]);
                    mma16(c[mt][nt], al[mt], bhf[nt]);
                }
        }
        __syncthreads();
    }

    // epilogue
#pragma unroll
    for (int mt = 0; mt < 2; mt++) {
        int row = m0 + wr * 32 + mt * 16 + (lane >> 2);
#pragma unroll
        for (int nt = 0; nt < 8; nt++) {
            int col = n0 + wc * 64 + nt * 8 + (lane & 3) * 2;
            float b0 = bias[col], b1 = bias[col + 1];
            float2 v0 = make_float2(c[mt][nt][0] + b0, c[mt][nt][1] + b1);
            float2 v1 = make_float2(c[mt][nt][2] + b0, c[mt][nt][3] + b1);
            if (relu) {
                v0.x = fmaxf(v0.x, 0.f); v0.y = fmaxf(v0.y, 0.f);
                v1.x = fmaxf(v1.x, 0.f); v1.y = fmaxf(v1.y, 0.f);
            }
            if (C) {
                *(float2*)(C + (size_t)row * Nd + col) = v0;
                *(float2*)(C + (size_t)(row + 8) * Nd + col) = v1;
            }
            if (Ch) {
                bf16 h0, l0, h1, l1;
                bsplit(v0.x, h0, l0); bsplit(v0.y, h1, l1);
                *(bf162*)(Ch + (size_t)row * Nd + col) = bf162(h0, h1);
                *(bf162*)(Cl + (size_t)row * Nd + col) = bf162(l0, l1);
                bsplit(v1.x, h0, l0); bsplit(v1.y, h1, l1);
                *(bf162*)(Ch + (size_t)(row + 8) * Nd + col) = bf162(h0, h1);
                *(bf162*)(Cl + (size_t)(row + 8) * Nd + col) = bf162(l0, l1);
            }
        }
    }
}

// ---------------- QK stats via bf16x3: M = rowmax - rowsum/L ---------------
// Q tile (128x64) hi/lo staged once (144B rows, aligned); K chunks (64 rows)
// triple-buffered (144B rows). smem u32: Qh 0, Ql 4608, B 9216 + s*4608, red 23040.
__global__ __launch_bounds__(256, 1) void qk_bf(
    const bf16* __restrict__ Qh, const bf16* __restrict__ Ql,
    const bf16* __restrict__ Ksh, const bf16* __restrict__ Ksl,
    float* __restrict__ Mout)
{
    extern __shared__ uint32_t smem_u[];
    uint32_t sb = s2u(smem_u);
    int tid = threadIdx.x, lane = tid & 31, wid = tid >> 5;
    int m0 = blockIdx.x * 128, bh = blockIdx.y;
    int wr = wid >> 1, wc = wid & 1;

    // stage Q tile hi/lo: 128 rows x 32 u32 data (stride 36 u32 = 144 B)
    {
        const bf16* qh = Qh + ((size_t)bh * Lc + m0) * 64;
        const bf16* ql = Ql + ((size_t)bh * Lc + m0) * 64;
#pragma unroll
        for (int i = 0; i < 4; i++) {
            int idx = tid + i * 256;           // 0..1023
            int r = idx >> 3, c16 = idx & 7;
            float4 v = *(const float4*)(qh + (size_t)r * 64 + c16 * 8);
            *(float4*)(smem_u + r * 36 + c16 * 4) = v;
            v = *(const float4*)(ql + (size_t)r * 64 + c16 * 8);
            *(float4*)(smem_u + 4608 + r * 36 + c16 * 4) = v;
        }
    }

    const bf16* kh = Ksh + (size_t)bh * Uc * 64;
    const bf16* kl = Ksl + (size_t)bh * Uc * 64;
    int rld = tid >> 2, sgp = tid & 3;        // 64 rows x 4 sixteen-B segs

#pragma unroll
    for (int pre = 0; pre < 2; pre++) {
        uint32_t st = sb + 36864 + pre * 18432;
        const bf16* s0 = kh + (size_t)(pre * 64 + rld) * 64 + sgp * 16;
        const bf16* s1 = kl + (size_t)(pre * 64 + rld) * 64 + sgp * 16;
        uint32_t d0 = st + rld * 144 + sgp * 32;
        cpa16(d0, s0); cpa16(d0 + 16, s0 + 8);
        uint32_t d1 = d0 + 9216;
        cpa16(d1, s1); cpa16(d1 + 16, s1 + 8);
        cpcommit();
    }
    __syncthreads();

    float rmax[2][2], rsum[2][2];
#pragma unroll
    for (int i = 0; i < 2; i++)
#pragma unroll
        for (int j = 0; j < 2; j++) { rmax[i][j] = -FLT_MAX; rsum[i][j] = 0.f; }

    for (int ch = 0; ch < 32; ch++) {
        int s = ch % 3;
        if (ch + 2 < 32) {
            uint32_t st = sb + 36864 + ((ch + 2) % 3) * 18432;
            const bf16* s0 = kh + (size_t)((ch + 2) * 64 + rld) * 64 + sgp * 16;
            const bf16* s1 = kl + (size_t)((ch + 2) * 64 + rld) * 64 + sgp * 16;
            uint32_t d0 = st + rld * 144 + sgp * 32;
            cpa16(d0, s0); cpa16(d0 + 16, s0 + 8);
            uint32_t d1 = d0 + 9216;
            cpa16(d1, s1); cpa16(d1 + 16, s1 + 8);
            cpcommit();
            cpwait<2>();
        } else if (ch + 2 == 32) {
            cpwait<1>();
        } else {
            cpwait<0>();
        }
        __syncthreads();

        const uint32_t* sQh = smem_u;
        const uint32_t* sQl = smem_u + 4608;
        const uint32_t* sBh = smem_u + 9216 + s * 4608;
        const uint32_t* sBl = sBh + 2304;
        int ar = wr * 32 + (lane >> 2);
        int bn = wc * 32 + (lane >> 2);
        int kq = lane & 3;

        float c[2][4][4];
#pragma unroll
        for (int i = 0; i < 2; i++)
#pragma unroll
            for (int j = 0; j < 4; j++)
#pragma unroll
                for (int r = 0; r < 4; r++) c[i][j][r] = 0.f;

#pragma unroll
        for (int st = 0; st < 4; st++) {
            int ko = st * 8 + kq;
            uint32_t ah[2][4], al[2][4], bhf[4][2], blf[4][2];
#pragma unroll
            for (int mt = 0; mt < 2; mt++) {
                int r0 = ar + mt * 16;
                ah[mt][0] = sQh[r0 * 36 + ko];
                ah[mt][1] = sQh[(r0 + 8) * 36 + ko];
                ah[mt][2] = sQh[r0 * 36 + ko + 4];
                ah[mt][3] = sQh[(r0 + 8) * 36 + ko + 4];
                al[mt][0] = sQl[r0 * 36 + ko];
                al[mt][1] = sQl[(r0 + 8) * 36 + ko];
                al[mt][2] = sQl[r0 * 36 + ko + 4];
                al[mt][3] = sQl[(r0 + 8) * 36 + ko + 4];
            }
#pragma unroll
            for (int nt = 0; nt < 4; nt++) {
                int n = bn + nt * 8;
                bhf[nt][0] = sBh[n * 36 + ko];
                bhf[nt][1] = sBh[n * 36 + ko + 4];
                blf[nt][0] = sBl[n * 36 + ko];
                blf[nt][1] = sBl[n * 36 + ko + 4];
            }
#pragma unroll
            for (int mt = 0; mt < 2; mt++)
#pragma unroll
                for (int nt = 0; nt < 4; nt++) {
                    mma16(c[mt][nt], ah[mt], bhf[nt]);
                    mma16(c[mt][nt], ah[mt], blf[nt]);
                    mma16(c[mt][nt], al[mt], bhf[nt]);
                }
        }

#pragma unroll
        for (int mt = 0; mt < 2; mt++)
#pragma unroll
            for (int hf = 0; hf < 2; hf++) {
                float mx = -FLT_MAX, sm = 0.f;
#pragma unroll
                for (int nt = 0; nt < 4; nt++) {
                    float v0 = c[mt][nt][hf * 2], v1 = c[mt][nt][hf * 2 + 1];
                    mx = fmaxf(mx, fmaxf(v0, v1));
                    sm += v0 + v1;
                }
                mx = fmaxf(mx, __shfl_xor_sync(0xffffffffu, mx, 1));
                sm += __shfl_xor_sync(0xffffffffu, sm, 1);
                mx = fmaxf(mx, __shfl_xor_sync(0xffffffffu, mx, 2));
                sm += __shfl_xor_sync(0xffffffffu, sm, 2);
                rmax[mt][hf] = fmaxf(rmax[mt][hf], mx);
                rsum[mt][hf] += sm;
            }
        __syncthreads();
    }

    float* red = (float*)(smem_u + 23040);    // [2][128][2]
    if ((lane & 3) == 0) {
#pragma unroll
        for (int mt = 0; mt < 2; mt++)
#pragma unroll
            for (int hf = 0; hf < 2; hf++) {
                int row = wr * 32 + mt * 16 + (lane >> 2) + hf * 8;
                red[(wc * 128 + row) * 2 + 0] = rmax[mt][hf];
                red[(wc * 128 + row) * 2 + 1] = rsum[mt][hf];
            }
    }
    __syncthreads();
    if (tid < 128) {
        float m0v = red[tid * 2], s0v = red[tid * 2 + 1];
        float m1v = red[(128 + tid) * 2], s1v = red[(128 + tid) * 2 + 1];
        Mout[(size_t)bh * Lc + m0 + tid] =
            fmaxf(m0v, m1v) - (s0v + s1v) * (1.f / (float)Lc);
    }
}

// ---------------- transpose + bf16 split weights: W[K,N] -> [N,K] ----------
__global__ void wsplit_kernel(const float* __restrict__ W, bf16* __restrict__ Wh,
                              bf16* __restrict__ Wl, int Kd, int Nd)
{
    __shared__ float t[32][33];
    int x = threadIdx.x, y = threadIdx.y;
    int n0 = blockIdx.x * 32, k0 = blockIdx.y * 32;
#pragma unroll
    for (int i = 0; i < 32; i += 8)
        t[y + i][x] = W[(size_t)(k0 + y + i) * Nd + n0 + x];
    __syncthreads();
#pragma unroll
    for (int i = 0; i < 32; i += 8) {
        float v = t[x][y + i];
        bf16 h, l;
        bsplit(v, h, l);
        size_t o = (size_t)(n0 + y + i) * Kd + k0 + x;
        Wh[o] = h;
        Wl[o] = l;
    }
}

// ---------------- elementwise fp32 -> bf16 hi/lo ---------------------------
__global__ void xsplit_kernel(const float* __restrict__ src, bf16* __restrict__ hi,
                              bf16* __restrict__ lo)
{
    int i = blockIdx.x * 256 + threadIdx.x;
    float4 v = ((const float4*)src)[i];
    bf16 h0, l0, h1, l1, h2, l2, h3, l3;
    bsplit(v.x, h0, l0); bsplit(v.y, h1, l1);
    bsplit(v.z, h2, l2); bsplit(v.w, h3, l3);
    ((bf162*)hi)[i * 2]     = bf162(h0, h1);
    ((bf162*)hi)[i * 2 + 1] = bf162(h2, h3);
    ((bf162*)lo)[i * 2]     = bf162(l0, l1);
    ((bf162*)lo)[i * 2 + 1] = bf162(l2, l3);
}

// ---------------- gather sampled keys + bf16 split, head-major -------------
__global__ void gather_split_kernel(const float* __restrict__ K, const int* __restrict__ idx,
                                    bf16* __restrict__ Ksh, bf16* __restrict__ Ksl)
{
    int j = blockIdx.x, b = blockIdx.y, t = threadIdx.x;
    int src = idx[j];
    float4 v = *(const float4*)(K + ((size_t)b * Lc + src) * Dc + t * 4);
    int h = t >> 4, e = (t & 15) * 4;
    bf16 h0, l0, h1, l1, h2, l2, h3, l3;
    bsplit(v.x, h0, l0); bsplit(v.y, h1, l1);
    bsplit(v.z, h2, l2); bsplit(v.w, h3, l3);
    size_t o = (((size_t)(b * 16 + h)) * Uc + j) * 64 + e;
    *(bf162*)(Ksh + o)     = bf162(h0, h1);
    *(bf162*)(Ksh + o + 2) = bf162(h2, h3);
    *(bf162*)(Ksl + o)     = bf162(l0, l1);
    *(bf162*)(Ksl + o + 2) = bf162(l2, l3);
}

// ---------------- top-40 smallest M (ties -> lower index) ------------------
__global__ __launch_bounds__(256) void topk_kernel(const float* __restrict__ Mv,
                                                   int* __restrict__ Mtop)
{
    __shared__ float sv[Lc];
    __shared__ float rv[256];
    __shared__ int   ri[256];
    int bh = blockIdx.x, tid = threadIdx.x;
    for (int i = tid; i < Lc; i += 256) sv[i] = Mv[(size_t)bh * Lc + i];
    __syncthreads();
    for (int it = 0; it < TOPK; it++) {
        float bv = FLT_MAX; int bi = 0x7fffffff;
        for (int i = tid; i < Lc; i += 256) {
            float v = sv[i];
            if (v < bv || (v == bv && i < bi)) { bv = v; bi = i; }
        }
        rv[tid] = bv; ri[tid] = bi;
        __syncthreads();
        for (int s = 128; s > 0; s >>= 1) {
            if (tid < s) {
                float v2 = rv[tid + s]; int i2 = ri[tid + s];
                if (v2 < rv[tid] || (v2 == rv[tid] && i2 < ri[tid])) {
                    rv[tid] = v2; ri[tid] = i2;
                }
            }
            __syncthreads();
        }
        if (tid == 0) { Mtop[bh * TOPK + it] = ri[0]; sv[ri[0]] = FLT_MAX; }
        __syncthreads();
    }
}

// ---------------- sparse attention for one selected query ------------------
__global__ __launch_bounds__(128) void sparse_attn_kernel(
    const float* __restrict__ Q, const float* __restrict__ K, const float* __restrict__ V,
    const int* __restrict__ Mtop, float* __restrict__ outred)
{
    int ui = blockIdx.x, bh = blockIdx.y;
    int b = bh >> 4, h = bh & 15;
    int qi = Mtop[bh * TOPK + ui];
    __shared__ float qsh[64];
    __shared__ float wm[4], ws[4], wa[4][64];
    int tid = threadIdx.x, warp = tid >> 5, lane = tid & 31;
    if (tid < 64) qsh[tid] = Q[((size_t)bh * Lc + qi) * 64 + tid];
    __syncthreads();
    float q0v = qsh[lane], q1v = qsh[lane + 32];
    float m = -FLT_MAX, s = 0.f, a0 = 0.f, a1 = 0.f;
    const float* kb = K + (size_t)b * Lc * Dc + h * 64;
    const float* vb = V + (size_t)b * Lc * Dc + h * 64;
    for (int l = warp * 512; l < warp * 512 + 512; l++) {
        const float* kr = kb + (size_t)l * Dc;
        float p = q0v * kr[lane] + q1v * kr[lane + 32];
#pragma unroll
        for (int off = 16; off > 0; off >>= 1)
            p += __shfl_xor_sync(0xffffffffu, p, off);
        p *= 0.125f;
        float mn = fmaxf(m, p);
        float c = expf(m - mn);
        float w = expf(p - mn);
        const float* vr = vb + (size_t)l * Dc;
        s  = s * c + w;
        a0 = a0 * c + w * vr[lane];
        a1 = a1 * c + w * vr[lane + 32];
        m = mn;
    }
    if (lane == 0) { wm[warp] = m; ws[warp] = s; }
    wa[warp][lane] = a0; wa[warp][lane + 32] = a1;
    __syncthreads();
    if (tid < 64) {
        float gm = fmaxf(fmaxf(wm[0], wm[1]), fmaxf(wm[2], wm[3]));
        float gs = 0.f, ga = 0.f;
#pragma unroll
        for (int w2 = 0; w2 < 4; w2++) {
            float f = expf(wm[w2] - gm);
            gs += ws[w2] * f;
            ga += wa[w2][tid] * f;
        }
        outred[((size_t)bh * TOPK + ui) * 64 + tid] = ga / gs;
    }
}

__global__ void init_bias_kernel(const float* __restrict__ bo, float* __restrict__ AO)
{
    float4 v = *(const float4*)(bo + threadIdx.x * 4);
    *(float4*)(AO + (size_t)blockIdx.x * Dc + threadIdx.x * 4) = v;
}

__global__ __launch_bounds__(256) void sparse_proj_kernel(
    const float* __restrict__ outred, const int* __restrict__ Mtop,
    const float* __restrict__ wo, float* __restrict__ AO)
{
    int ui = blockIdx.x, bh = blockIdx.y;
    int b = bh >> 4, h = bh & 15;
    int l = Mtop[bh * TOPK + ui];
    __shared__ float r[64];
    int tid = threadIdx.x;
    if (tid < 64) r[tid] = outred[((size_t)bh * TOPK + ui) * 64 + tid];
    __syncthreads();
    float a0 = 0.f, a1 = 0.f, a2 = 0.f, a3 = 0.f;
    const float* w = wo + (size_t)h * 64 * Dc + tid;
#pragma unroll 8
    for (int e = 0; e < 64; e++) {
        float re = r[e];
        const float* wr = w + (size_t)e * Dc;
        a0 = fmaf(re, wr[0],   a0);
        a1 = fmaf(re, wr[256], a1);
        a2 = fmaf(re, wr[512], a2);
        a3 = fmaf(re, wr[768], a3);
    }
    float* dst = AO + ((size_t)b * Lc + l) * Dc + tid;
    atomicAdd(dst,       a0);
    atomicAdd(dst + 256, a1);
    atomicAdd(dst + 512, a2);
    atomicAdd(dst + 768, a3);
}

// ---------------- residual add + LayerNorm (+opt bf16 split out) -----------
__global__ __launch_bounds__(256) void add_ln_kernel(
    const float* __restrict__ X, const float* __restrict__ Y,
    const float* __restrict__ g, const float* __restrict__ be,
    float* __restrict__ out, bf16* __restrict__ oh, bf16* __restrict__ ol)
{
    int row = blockIdx.x, tid = threadIdx.x;
    __shared__ float red[256];
    float v[4];
    float s = 0.f;
#pragma unroll
    for (int c = 0; c < 4; c++) {
        size_t i = (size_t)row * Dc + tid + c * 256;
        v[c] = X[i] + Y[i];
        s += v[c];
    }
    red[tid] = s; __syncthreads();
    for (int st = 128; st > 0; st >>= 1) {
        if (tid < st) red[tid] += red[tid + st];
        __syncthreads();
    }
    float mean = red[0] * (1.f / 1024.f);
    __syncthreads();
    float s2 = 0.f;
#pragma unroll
    for (int c = 0; c < 4; c++) { float t = v[c] - mean; s2 = fmaf(t, t, s2); }
    red[tid] = s2; __syncthreads();
    for (int st = 128; st > 0; st >>= 1) {
        if (tid < st) red[tid] += red[tid + st];
        __syncthreads();
    }
    float var = red[0] * (1.f / 1024.f);
    float rstd = 1.0f / sqrtf(var + 1e-12f);
#pragma unroll
    for (int c = 0; c < 4; c++) {
        int col = tid + c * 256;
        float o = g[col] * ((v[c] - mean) * rstd) + be[col];
        out[(size_t)row * Dc + col] = o;
        if (oh) {
            bf16 h, l;
            bsplit(o, h, l);
            oh[(size_t)row * Dc + col] = h;
            ol[(size_t)row * Dc + col] = l;
        }
    }
}

// ---------------- launch ---------------------------------------------------
extern "C" void kernel_launch(void* const* d_in, const int* in_sizes, int n_in,
                              void* d_out, int out_size)
{
    const float* x   = (const float*)d_in[0];
    const float* wq  = (const float*)d_in[1];
    const float* bq  = (const float*)d_in[2];
    const float* wk  = (const float*)d_in[3];
    const float* bk  = (const float*)d_in[4];
    const float* wv  = (const float*)d_in[5];
    const float* bv  = (const float*)d_in[6];
    const float* wo  = (const float*)d_in[7];
    const float* bo  = (const float*)d_in[8];
    const float* w1  = (const float*)d_in[9];
    const float* b1  = (const float*)d_in[10];
    const float* w2  = (const float*)d_in[11];
    const float* b2  = (const float*)d_in[12];
    const float* ga1 = (const float*)d_in[13];
    const float* be1 = (const float*)d_in[14];
    const float* ga2 = (const float*)d_in[15];
    const float* be2 = (const float*)d_in[16];
    const int*   idx = (const int*)d_in[17];
    float* out = (float*)d_out;

    float *Q, *K, *V, *AO, *X1, *Y2, *Mv, *Or;
    bf16 *Xbh, *Xbl, *Qbh, *Qbl, *X1bh, *X1bl, *Y1bh, *Y1bl, *Ksbh, *Ksbl;
    bf16 *Wqh, *Wql, *Wkh, *Wkl, *Wvh, *Wvl, *W1h, *W1l, *W2h, *W2l;
    int* Mt;
    cudaGetSymbolAddress((void**)&Q,    g_Q);
    cudaGetSymbolAddress((void**)&K,    g_K);
    cudaGetSymbolAddress((void**)&V,    g_V);
    cudaGetSymbolAddress((void**)&AO,   g_AO);
    cudaGetSymbolAddress((void**)&X1,   g_X1);
    cudaGetSymbolAddress((void**)&Y2,   g_Y2);
    cudaGetSymbolAddress((void**)&Mv,   g_M);
    cudaGetSymbolAddress((void**)&Mt,   g_Mtop);
    cudaGetSymbolAddress((void**)&Or,   g_Or);
    cudaGetSymbolAddress((void**)&Xbh,  g_Xbh);
    cudaGetSymbolAddress((void**)&Xbl,  g_Xbl);
    cudaGetSymbolAddress((void**)&Qbh,  g_Qbh);
    cudaGetSymbolAddress((void**)&Qbl,  g_Qbl);
    cudaGetSymbolAddress((void**)&X1bh, g_X1bh);
    cudaGetSymbolAddress((void**)&X1bl, g_X1bl);
    cudaGetSymbolAddress((void**)&Y1bh, g_Y1bh);
    cudaGetSymbolAddress((void**)&Y1bl, g_Y1bl);
    cudaGetSymbolAddress((void**)&Ksbh, g_Ksbh);
    cudaGetSymbolAddress((void**)&Ksbl, g_Ksbl);
    cudaGetSymbolAddress((void**)&Wqh,  g_Wqh);
    cudaGetSymbolAddress((void**)&Wql,  g_Wql);
    cudaGetSymbolAddress((void**)&Wkh,  g_Wkh);
    cudaGetSymbolAddress((void**)&Wkl,  g_Wkl);
    cudaGetSymbolAddress((void**)&Wvh,  g_Wvh);
    cudaGetSymbolAddress((void**)&Wvl,  g_Wvl);
    cudaGetSymbolAddress((void**)&W1h,  g_W1h);
    cudaGetSymbolAddress((void**)&W1l,  g_W1l);
    cudaGetSymbolAddress((void**)&W2h,  g_W2h);
    cudaGetSymbolAddress((void**)&W2l,  g_W2l);

    cudaFuncSetAttribute(gemm_bf, cudaFuncAttributeMaxDynamicSharedMemorySize, 3 * GSTB);
    cudaFuncSetAttribute(qk_bf,   cudaFuncAttributeMaxDynamicSharedMemorySize, 94208);

    dim3 t32x8(32, 8);
    wsplit_kernel<<<dim3(Dc / 32, Dc / 32), t32x8>>>(wq, Wqh, Wql, Dc, Dc);
    wsplit_kernel<<<dim3(Dc / 32, Dc / 32), t32x8>>>(wk, Wkh, Wkl, Dc, Dc);
    wsplit_kernel<<<dim3(Dc / 32, Dc / 32), t32x8>>>(wv, Wvh, Wvl, Dc, Dc);
    wsplit_kernel<<<dim3(Fc / 32, Dc / 32), t32x8>>>(w1, W1h, W1l, Dc, Fc);
    wsplit_kernel<<<dim3(Dc / 32, Fc / 32), t32x8>>>(w2, W2h, W2l, Fc, Dc);

    xsplit_kernel<<<(MR * Dc / 4) / 256, 256>>>(x, Xbh, Xbl);

    gemm_bf<<<dim3(8, 64), 256, 3 * GSTB>>>(Xbh, Xbl, Wqh, Wql, bq, Q, Qbh, Qbl, Dc, Dc, 0);
    gemm_bf<<<dim3(8, 64), 256, 3 * GSTB>>>(Xbh, Xbl, Wkh, Wkl, bk, K, (bf16*)0, (bf16*)0, Dc, Dc, 0);
    gemm_bf<<<dim3(8, 64), 256, 3 * GSTB>>>(Xbh, Xbl, Wvh, Wvl, bv, V, (bf16*)0, (bf16*)0, Dc, Dc, 0);

    gather_split_kernel<<<dim3(Uc, Bc), 256>>>(K, idx, Ksbh, Ksbl);
    qk_bf<<<dim3(Lc / 128, BHc), 256, 94208>>>(Qbh, Qbl, Ksbh, Ksbl, Mv);
    topk_kernel<<<BHc, 256>>>(Mv, Mt);

    sparse_attn_kernel<<<dim3(TOPK, BHc), 128>>>(Q, K, V, Mt, Or);

    init_bias_kernel<<<MR, 256>>>(bo, AO);
    sparse_proj_kernel<<<dim3(TOPK, BHc), 256>>>(Or, Mt, wo, AO);

    add_ln_kernel<<<MR, 256>>>(x, AO, ga1, be1, X1, X1bh, X1bl);

    gemm_bf<<<dim3(32, 64), 256, 3 * GSTB>>>(X1bh, X1bl, W1h, W1l, b1, (float*)0, Y1bh, Y1bl, Dc, Fc, 1);
    gemm_bf<<<dim3(8, 64), 256, 3 * GSTB>>>(Y1bh, Y1bl, W2h, W2l, b2, Y2, (bf16*)0, (bf16*)0, Fc, Dc, 0);

    add_ln_kernel<<<MR, 256>>>(X1, Y2, ga2, be2, out, (bf16*)0, (bf16*)0);
}

// round 10
// speedup vs baseline: 1.4881x; 1.1004x over previous
#include <cuda_runtime.h>
#include <cuda_bf16.h>
#include <math.h>
#include <float.h>
#include <stdint.h>

#define Bc 4
#define Lc 2048
#define Dc 1024
#define Fc 4096
#define BHc 64
#define Uc 2048
#define TOPK 40
#define MR 8192

typedef __nv_bfloat16 bf16;
typedef __nv_bfloat162 bf162;

// ---------------- scratch (bf16 arrays 16B aligned: 16B vector ops used) -----
__device__ float g_Q [MR * Dc];
__device__ float g_K [MR * Dc];
__device__ float g_V [MR * Dc];
__device__ float g_AO[MR * Dc];
__device__ float g_X1[MR * Dc];
__device__ float g_Y2[MR * Dc];
__device__ float g_M [BHc * Lc];
__device__ int   g_Mtop[BHc * TOPK];
__device__ float g_Or[BHc * TOPK * 64];
__device__ __align__(16) bf16 g_Xbh[MR * Dc],  g_Xbl[MR * Dc];
__device__ __align__(16) bf16 g_Qbh[MR * Dc],  g_Qbl[MR * Dc];
__device__ __align__(16) bf16 g_X1bh[MR * Dc], g_X1bl[MR * Dc];
__device__ __align__(16) bf16 g_Y1bh[MR * Fc], g_Y1bl[MR * Fc];
__device__ __align__(16) bf16 g_Ksbh[BHc * Uc * 64], g_Ksbl[BHc * Uc * 64];
__device__ __align__(16) bf16 g_Wqh[Dc * Dc], g_Wql[Dc * Dc];
__device__ __align__(16) bf16 g_Wkh[Dc * Dc], g_Wkl[Dc * Dc];
__device__ __align__(16) bf16 g_Wvh[Dc * Dc], g_Wvl[Dc * Dc];
__device__ __align__(16) bf16 g_W1h[Dc * Fc], g_W1l[Dc * Fc];
__device__ __align__(16) bf16 g_W2h[Fc * Dc], g_W2l[Fc * Dc];

// ---------------- helpers --------------------------------------------------
__device__ __forceinline__ uint32_t s2u(const void* p) {
    uint32_t a;
    asm("{ .reg .u64 t; cvta.to.shared.u64 t, %1; cvt.u32.u64 %0, t; }" : "=r"(a) : "l"(p));
    return a;
}
__device__ __forceinline__ void cpa16(uint32_t dst, const void* src) {
    asm volatile("cp.async.ca.shared.global [%0], [%1], 16;" :: "r"(dst), "l"(src));
}
__device__ __forceinline__ void cpcommit() {
    asm volatile("cp.async.commit_group;");
}
template <int N>
__device__ __forceinline__ void cpwait() {
    asm volatile("cp.async.wait_group %0;" :: "n"(N));
}
// d += a * b  (m16n8k16 bf16)
__device__ __forceinline__ void mma16(float* d, const uint32_t* a, const uint32_t* b) {
    asm volatile(
        "mma.sync.aligned.m16n8k16.row.col.f32.bf16.bf16.f32 "
        "{%0,%1,%2,%3}, {%4,%5,%6,%7}, {%8,%9}, {%0,%1,%2,%3};"
        : "+f"(d[0]), "+f"(d[1]), "+f"(d[2]), "+f"(d[3])
        : "r"(a[0]), "r"(a[1]), "r"(a[2]), "r"(a[3]), "r"(b[0]), "r"(b[1]));
}
__device__ __forceinline__ void bsplit(float v, bf16& h, bf16& l) {
    h = __float2bfloat16_rn(v);
    l = __float2bfloat16_rn(v - __bfloat162float(h));
}

// ---------------- bf16x3 mma.sync GEMM -------------------------------------
#define GSTB 40960
__global__ __launch_bounds__(256, 1) void gemm_bf(
    const bf16* __restrict__ Ah, const bf16* __restrict__ Al,
    const bf16* __restrict__ Bh, const bf16* __restrict__ Bl,
    const float* __restrict__ bias, float* __restrict__ C,
    bf16* __restrict__ Ch, bf16* __restrict__ Cl,
    int Kd, int Nd, int relu)
{
    extern __shared__ uint32_t smem_u[];
    uint32_t sb = s2u(smem_u);
    int tid = threadIdx.x, lane = tid & 31, wid = tid >> 5;
    int m0 = blockIdx.y * 128, n0 = blockIdx.x * 128;
    int wr = wid >> 1, wc = wid & 1;
    int NC = Kd >> 5;

    const bf16* gsrc[4] = { Ah + (size_t)m0 * Kd, Al + (size_t)m0 * Kd,
                            Bh + (size_t)n0 * Kd, Bl + (size_t)n0 * Kd };

    float c[2][8][4];
#pragma unroll
    for (int i = 0; i < 2; i++)
#pragma unroll
        for (int j = 0; j < 8; j++)
#pragma unroll
            for (int r = 0; r < 4; r++) c[i][j][r] = 0.f;

    int rld = tid >> 1, sgp = tid & 1;

#pragma unroll
    for (int pre = 0; pre < 2; pre++) {
        int k0 = pre << 5;
        uint32_t st = sb + pre * GSTB;
#pragma unroll
        for (int a4 = 0; a4 < 4; a4++) {
            uint32_t dst = st + a4 * 10240 + rld * 80 + sgp * 32;
            const bf16* src = gsrc[a4] + (size_t)rld * Kd + k0 + sgp * 16;
            cpa16(dst, src);
            cpa16(dst + 16, src + 8);
        }
        cpcommit();
    }

    for (int ch = 0; ch < NC; ch++) {
        int s = ch % 3;
        if (ch + 2 < NC) {
            int k0 = (ch + 2) << 5;
            uint32_t st = sb + ((ch + 2) % 3) * GSTB;
#pragma unroll
            for (int a4 = 0; a4 < 4; a4++) {
                uint32_t dst = st + a4 * 10240 + rld * 80 + sgp * 32;
                const bf16* src = gsrc[a4] + (size_t)rld * Kd + k0 + sgp * 16;
                cpa16(dst, src);
                cpa16(dst + 16, src + 8);
            }
            cpcommit();
            cpwait<2>();
        } else if (ch + 2 == NC) {
            cpwait<1>();
        } else {
            cpwait<0>();
        }
        __syncthreads();

        const uint32_t* sAh = smem_u + (s * GSTB) / 4;
        const uint32_t* sAl = sAh + 2560;
        const uint32_t* sBh = sAh + 5120;
        const uint32_t* sBl = sAh + 7680;
        int ar = wr * 32 + (lane >> 2);
        int bn = wc * 64 + (lane >> 2);
        int kq = lane & 3;

#pragma unroll
        for (int st = 0; st < 2; st++) {
            int ko = st * 8 + kq;
            uint32_t ah[2][4], al[2][4], bhf[8][2], blf[8][2];
#pragma unroll
            for (int mt = 0; mt < 2; mt++) {
                int r0 = ar + mt * 16;
                ah[mt][0] = sAh[r0 * 20 + ko];
                ah[mt][1] = sAh[(r0 + 8) * 20 + ko];
                ah[mt][2] = sAh[r0 * 20 + ko + 4];
                ah[mt][3] = sAh[(r0 + 8) * 20 + ko + 4];
                al[mt][0] = sAl[r0 * 20 + ko];
                al[mt][1] = sAl[(r0 + 8) * 20 + ko];
                al[mt][2] = sAl[r0 * 20 + ko + 4];
                al[mt][3] = sAl[(r0 + 8) * 20 + ko + 4];
            }
#pragma unroll
            for (int nt = 0; nt < 8; nt++) {
                int n = bn + nt * 8;
                bhf[nt][0] = sBh[n * 20 + ko];
                bhf[nt][1] = sBh[n * 20 + ko + 4];
                blf[nt][0] = sBl[n * 20 + ko];
                blf[nt][1] = sBl[n * 20 + ko + 4];
            }
#pragma unroll
            for (int mt = 0; mt < 2; mt++)
#pragma unroll
                for (int nt = 0; nt < 8; nt++) {
                    mma16(c[mt][nt], ah[mt], bhf[nt]);
                    mma16(c[mt][nt], ah[mt], blf[nt]);
                    mma16(c[mt][nt], al[mt], bhf[nt]);
                }
        }
        __syncthreads();
    }

#pragma unroll
    for (int mt = 0; mt < 2; mt++) {
        int row = m0 + wr * 32 + mt * 16 + (lane >> 2);
#pragma unroll
        for (int nt = 0; nt < 8; nt++) {
            int col = n0 + wc * 64 + nt * 8 + (lane & 3) * 2;
            float b0 = bias[col], b1 = bias[col + 1];
            float2 v0 = make_float2(c[mt][nt][0] + b0, c[mt][nt][1] + b1);
            float2 v1 = make_float2(c[mt][nt][2] + b0, c[mt][nt][3] + b1);
            if (relu) {
                v0.x = fmaxf(v0.x, 0.f); v0.y = fmaxf(v0.y, 0.f);
                v1.x = fmaxf(v1.x, 0.f); v1.y = fmaxf(v1.y, 0.f);
            }
            if (C) {
                *(float2*)(C + (size_t)row * Nd + col) = v0;
                *(float2*)(C + (size_t)(row + 8) * Nd + col) = v1;
            }
            if (Ch) {
                bf16 h0, l0, h1, l1;
                bsplit(v0.x, h0, l0); bsplit(v0.y, h1, l1);
                *(bf162*)(Ch + (size_t)row * Nd + col) = bf162(h0, h1);
                *(bf162*)(Cl + (size_t)row * Nd + col) = bf162(l0, l1);
                bsplit(v1.x, h0, l0); bsplit(v1.y, h1, l1);
                *(bf162*)(Ch + (size_t)(row + 8) * Nd + col) = bf162(h0, h1);
                *(bf162*)(Cl + (size_t)(row + 8) * Nd + col) = bf162(l0, l1);
            }
        }
    }
}

// ---------------- QK stats via bf16x3: M = rowmax - rowsum/L ---------------
__global__ __launch_bounds__(256, 1) void qk_bf(
    const bf16* __restrict__ Qh, const bf16* __restrict__ Ql,
    const bf16* __restrict__ Ksh, const bf16* __restrict__ Ksl,
    float* __restrict__ Mout)
{
    extern __shared__ uint32_t smem_u[];
    uint32_t sb = s2u(smem_u);
    int tid = threadIdx.x, lane = tid & 31, wid = tid >> 5;
    int m0 = blockIdx.x * 128, bh = blockIdx.y;
    int wr = wid >> 1, wc = wid & 1;

    {
        const bf16* qh = Qh + ((size_t)bh * Lc + m0) * 64;
        const bf16* ql = Ql + ((size_t)bh * Lc + m0) * 64;
#pragma unroll
        for (int i = 0; i < 4; i++) {
            int idx = tid + i * 256;
            int r = idx >> 3, c16 = idx & 7;
            float4 v = *(const float4*)(qh + (size_t)r * 64 + c16 * 8);
            *(float4*)(smem_u + r * 36 + c16 * 4) = v;
            v = *(const float4*)(ql + (size_t)r * 64 + c16 * 8);
            *(float4*)(smem_u + 4608 + r * 36 + c16 * 4) = v;
        }
    }

    const bf16* kh = Ksh + (size_t)bh * Uc * 64;
    const bf16* kl = Ksl + (size_t)bh * Uc * 64;
    int rld = tid >> 2, sgp = tid & 3;

#pragma unroll
    for (int pre = 0; pre < 2; pre++) {
        uint32_t st = sb + 36864 + pre * 18432;
        const bf16* s0 = kh + (size_t)(pre * 64 + rld) * 64 + sgp * 16;
        const bf16* s1 = kl + (size_t)(pre * 64 + rld) * 64 + sgp * 16;
        uint32_t d0 = st + rld * 144 + sgp * 32;
        cpa16(d0, s0); cpa16(d0 + 16, s0 + 8);
        uint32_t d1 = d0 + 9216;
        cpa16(d1, s1); cpa16(d1 + 16, s1 + 8);
        cpcommit();
    }
    __syncthreads();

    float rmax[2][2], rsum[2][2];
#pragma unroll
    for (int i = 0; i < 2; i++)
#pragma unroll
        for (int j = 0; j < 2; j++) { rmax[i][j] = -FLT_MAX; rsum[i][j] = 0.f; }

    for (int ch = 0; ch < 32; ch++) {
        int s = ch % 3;
        if (ch + 2 < 32) {
            uint32_t st = sb + 36864 + ((ch + 2) % 3) * 18432;
            const bf16* s0 = kh + (size_t)((ch + 2) * 64 + rld) * 64 + sgp * 16;
            const bf16* s1 = kl + (size_t)((ch + 2) * 64 + rld) * 64 + sgp * 16;
            uint32_t d0 = st + rld * 144 + sgp * 32;
            cpa16(d0, s0); cpa16(d0 + 16, s0 + 8);
            uint32_t d1 = d0 + 9216;
            cpa16(d1, s1); cpa16(d1 + 16, s1 + 8);
            cpcommit();
            cpwait<2>();
        } else if (ch + 2 == 32) {
            cpwait<1>();
        } else {
            cpwait<0>();
        }
        __syncthreads();

        const uint32_t* sQh = smem_u;
        const uint32_t* sQl = smem_u + 4608;
        const uint32_t* sBh = smem_u + 9216 + s * 4608;
        const uint32_t* sBl = sBh + 2304;
        int ar = wr * 32 + (lane >> 2);
        int bn = wc * 32 + (lane >> 2);
        int kq = lane & 3;

        float c[2][4][4];
#pragma unroll
        for (int i = 0; i < 2; i++)
#pragma unroll
            for (int j = 0; j < 4; j++)
#pragma unroll
                for (int r = 0; r < 4; r++) c[i][j][r] = 0.f;

#pragma unroll
        for (int st = 0; st < 4; st++) {
            int ko = st * 8 + kq;
            uint32_t ah[2][4], al[2][4], bhf[4][2], blf[4][2];
#pragma unroll
            for (int mt = 0; mt < 2; mt++) {
                int r0 = ar + mt * 16;
                ah[mt][0] = sQh[r0 * 36 + ko];
                ah[mt][1] = sQh[(r0 + 8) * 36 + ko];
                ah[mt][2] = sQh[r0 * 36 + ko + 4];
                ah[mt][3] = sQh[(r0 + 8) * 36 + ko + 4];
                al[mt][0] = sQl[r0 * 36 + ko];
                al[mt][1] = sQl[(r0 + 8) * 36 + ko];
                al[mt][2] = sQl[r0 * 36 + ko + 4];
                al[mt][3] = sQl[(r0 + 8) * 36 + ko + 4];
            }
#pragma unroll
            for (int nt = 0; nt < 4; nt++) {
                int n = bn + nt * 8;
                bhf[nt][0] = sBh[n * 36 + ko];
                bhf[nt][1] = sBh[n * 36 + ko + 4];
                blf[nt][0] = sBl[n * 36 + ko];
                blf[nt][1] = sBl[n * 36 + ko + 4];
            }
#pragma unroll
            for (int mt = 0; mt < 2; mt++)
#pragma unroll
                for (int nt = 0; nt < 4; nt++) {
                    mma16(c[mt][nt], ah[mt], bhf[nt]);
                    mma16(c[mt][nt], ah[mt], blf[nt]);
                    mma16(c[mt][nt], al[mt], bhf[nt]);
                }
        }

#pragma unroll
        for (int mt = 0; mt < 2; mt++)
#pragma unroll
            for (int hf = 0; hf < 2; hf++) {
                float mx = -FLT_MAX, sm = 0.f;
#pragma unroll
                for (int nt = 0; nt < 4; nt++) {
                    float v0 = c[mt][nt][hf * 2], v1 = c[mt][nt][hf * 2 + 1];
                    mx = fmaxf(mx, fmaxf(v0, v1));
                    sm += v0 + v1;
                }
                mx = fmaxf(mx, __shfl_xor_sync(0xffffffffu, mx, 1));
                sm += __shfl_xor_sync(0xffffffffu, sm, 1);
                mx = fmaxf(mx, __shfl_xor_sync(0xffffffffu, mx, 2));
                sm += __shfl_xor_sync(0xffffffffu, sm, 2);
                rmax[mt][hf] = fmaxf(rmax[mt][hf], mx);
                rsum[mt][hf] += sm;
            }
        __syncthreads();
    }

    float* red = (float*)(smem_u + 23040);
    if ((lane & 3) == 0) {
#pragma unroll
        for (int mt = 0; mt < 2; mt++)
#pragma unroll
            for (int hf = 0; hf < 2; hf++) {
                int row = wr * 32 + mt * 16 + (lane >> 2) + hf * 8;
                red[(wc * 128 + row) * 2 + 0] = rmax[mt][hf];
                red[(wc * 128 + row) * 2 + 1] = rsum[mt][hf];
            }
    }
    __syncthreads();
    if (tid < 128) {
        float m0v = red[tid * 2], s0v = red[tid * 2 + 1];
        float m1v = red[(128 + tid) * 2], s1v = red[(128 + tid) * 2 + 1];
        Mout[(size_t)bh * Lc + m0 + tid] =
            fmaxf(m0v, m1v) - (s0v + s1v) * (1.f / (float)Lc);
    }
}

// ---------------- transpose + bf16 split weights ---------------------------
__global__ void wsplit_kernel(const float* __restrict__ W, bf16* __restrict__ Wh,
                              bf16* __restrict__ Wl, int Kd, int Nd)
{
    __shared__ float t[32][33];
    int x = threadIdx.x, y = threadIdx.y;
    int n0 = blockIdx.x * 32, k0 = blockIdx.y * 32;
#pragma unroll
    for (int i = 0; i < 32; i += 8)
        t[y + i][x] = W[(size_t)(k0 + y + i) * Nd + n0 + x];
    __syncthreads();
#pragma unroll
    for (int i = 0; i < 32; i += 8) {
        float v = t[x][y + i];
        bf16 h, l;
        bsplit(v, h, l);
        size_t o = (size_t)(n0 + y + i) * Kd + k0 + x;
        Wh[o] = h;
        Wl[o] = l;
    }
}

// ---------------- elementwise fp32 -> bf16 hi/lo ---------------------------
__global__ void xsplit_kernel(const float* __restrict__ src, bf16* __restrict__ hi,
                              bf16* __restrict__ lo)
{
    int i = blockIdx.x * 256 + threadIdx.x;
    float4 v = ((const float4*)src)[i];
    bf16 h0, l0, h1, l1, h2, l2, h3, l3;
    bsplit(v.x, h0, l0); bsplit(v.y, h1, l1);
    bsplit(v.z, h2, l2); bsplit(v.w, h3, l3);
    ((bf162*)hi)[i * 2]     = bf162(h0, h1);
    ((bf162*)hi)[i * 2 + 1] = bf162(h2, h3);
    ((bf162*)lo)[i * 2]     = bf162(l0, l1);
    ((bf162*)lo)[i * 2 + 1] = bf162(l2, l3);
}

// ---------------- gather sampled keys + bf16 split, head-major -------------
__global__ void gather_split_kernel(const float* __restrict__ K, const int* __restrict__ idx,
                                    bf16* __restrict__ Ksh, bf16* __restrict__ Ksl)
{
    int j = blockIdx.x, b = blockIdx.y, t = threadIdx.x;
    int src = idx[j];
    float4 v = *(const float4*)(K + ((size_t)b * Lc + src) * Dc + t * 4);
    int h = t >> 4, e = (t & 15) * 4;
    bf16 h0, l0, h1, l1, h2, l2, h3, l3;
    bsplit(v.x, h0, l0); bsplit(v.y, h1, l1);
    bsplit(v.z, h2, l2); bsplit(v.w, h3, l3);
    size_t o = (((size_t)(b * 16 + h)) * Uc + j) * 64 + e;
    *(bf162*)(Ksh + o)     = bf162(h0, h1);
    *(bf162*)(Ksh + o + 2) = bf162(h2, h3);
    *(bf162*)(Ksl + o)     = bf162(l0, l1);
    *(bf162*)(Ksl + o + 2) = bf162(l2, l3);
}

// ---------------- top-40 smallest M (ties -> lower index) ------------------
__global__ __launch_bounds__(256) void topk_kernel(const float* __restrict__ Mv,
                                                   int* __restrict__ Mtop)
{
    __shared__ float sv[Lc];
    __shared__ float rv[256];
    __shared__ int   ri[256];
    int bh = blockIdx.x, tid = threadIdx.x;
    for (int i = tid; i < Lc; i += 256) sv[i] = Mv[(size_t)bh * Lc + i];
    __syncthreads();
    for (int it = 0; it < TOPK; it++) {
        float bv = FLT_MAX; int bi = 0x7fffffff;
        for (int i = tid; i < Lc; i += 256) {
            float v = sv[i];
            if (v < bv || (v == bv && i < bi)) { bv = v; bi = i; }
        }
        rv[tid] = bv; ri[tid] = bi;
        __syncthreads();
        for (int s = 128; s > 0; s >>= 1) {
            if (tid < s) {
                float v2 = rv[tid + s]; int i2 = ri[tid + s];
                if (v2 < rv[tid] || (v2 == rv[tid] && i2 < ri[tid])) {
                    rv[tid] = v2; ri[tid] = i2;
                }
            }
            __syncthreads();
        }
        if (tid == 0) { Mtop[bh * TOPK + it] = ri[0]; sv[ri[0]] = FLT_MAX; }
        __syncthreads();
    }
}

// ---------------- sparse attention: one block per (b,h), all 40 queries ----
// smem floats: qs[40][64] @0 (2560), ks[64][65] @2560 (4160, K transposed+pad),
// vs[64][64] @6720 (4096), wbuf[8][5][64] @10816 (2560). total 13376 floats = 53504 B.
__global__ __launch_bounds__(256, 1) void sparse_attn2(
    const float* __restrict__ Q, const float* __restrict__ K, const float* __restrict__ V,
    const int* __restrict__ Mtop, float* __restrict__ outred)
{
    extern __shared__ float sm[];
    float* qs   = sm;            // [40][64]
    float* ks   = sm + 2560;     // [64][65] : ks[d*65 + key]
    float* vs   = sm + 6720;     // [64][64] : vs[key*64 + d]
    float* wbuf = sm + 10816;    // [warp][5][64]

    int bh = blockIdx.x;
    int b = bh >> 4, h = bh & 15;
    int tid = threadIdx.x, lane = tid & 31, warp = tid >> 5;

    // load 40 selected queries
    for (int i = tid; i < TOPK * 64; i += 256) {
        int q = i >> 6, d = i & 63;
        int qi = Mtop[bh * TOPK + q];
        qs[i] = Q[((size_t)bh * Lc + qi) * 64 + d];
    }

    const float* kb = K + (size_t)b * Lc * Dc + h * 64;
    const float* vb = V + (size_t)b * Lc * Dc + h * 64;

    float m[5], sum[5], acc0[5], acc1[5];
#pragma unroll
    for (int q = 0; q < 5; q++) {
        m[q] = -FLT_MAX; sum[q] = 0.f; acc0[q] = 0.f; acc1[q] = 0.f;
    }
    float* wq = wbuf + warp * 320;

    for (int l0 = 0; l0 < Lc; l0 += 64) {
        __syncthreads();
        // load K chunk transposed, V chunk natural
        for (int i = tid; i < 64 * 64; i += 256) {
            int row = i >> 6, d = i & 63;
            ks[d * 65 + row] = kb[(size_t)(l0 + row) * Dc + d];
            vs[i] = vb[(size_t)(l0 + row) * Dc + d];
        }
        __syncthreads();

#pragma unroll
        for (int q = 0; q < 5; q++) {
            const float* qrow = qs + (warp * 5 + q) * 64;
            float s0 = 0.f, s1 = 0.f;
#pragma unroll
            for (int d = 0; d < 64; d++) {
                float qv = qrow[d];
                s0 = fmaf(qv, ks[d * 65 + lane], s0);
                s1 = fmaf(qv, ks[d * 65 + lane + 32], s1);
            }
            s0 *= 0.125f; s1 *= 0.125f;
            // chunk max
            float cmx = fmaxf(s0, s1);
#pragma unroll
            for (int off = 16; off > 0; off >>= 1)
                cmx = fmaxf(cmx, __shfl_xor_sync(0xffffffffu, cmx, off));
            float nm = fmaxf(m[q], cmx);
            float scale = expf(m[q] - nm);
            float w0 = expf(s0 - nm), w1 = expf(s1 - nm);
            float csum = w0 + w1;
#pragma unroll
            for (int off = 16; off > 0; off >>= 1)
                csum += __shfl_xor_sync(0xffffffffu, csum, off);
            sum[q] = sum[q] * scale + csum;
            m[q] = nm;
            wq[q * 64 + lane] = w0;
            wq[q * 64 + lane + 32] = w1;
            __syncwarp();
            float a0 = acc0[q] * scale, a1 = acc1[q] * scale;
#pragma unroll
            for (int k = 0; k < 64; k++) {
                float wv = wq[q * 64 + k];
                a0 = fmaf(wv, vs[k * 64 + lane], a0);
                a1 = fmaf(wv, vs[k * 64 + lane + 32], a1);
            }
            acc0[q] = a0; acc1[q] = a1;
            __syncwarp();
        }
    }

#pragma unroll
    for (int q = 0; q < 5; q++) {
        float inv = 1.0f / sum[q];
        size_t o = ((size_t)bh * TOPK + warp * 5 + q) * 64;
        outred[o + lane] = acc0[q] * inv;
        outred[o + lane + 32] = acc1[q] * inv;
    }
}

__global__ void init_bias_kernel(const float* __restrict__ bo, float* __restrict__ AO)
{
    float4 v = *(const float4*)(bo + threadIdx.x * 4);
    *(float4*)(AO + (size_t)blockIdx.x * Dc + threadIdx.x * 4) = v;
}

__global__ __launch_bounds__(256) void sparse_proj_kernel(
    const float* __restrict__ outred, const int* __restrict__ Mtop,
    const float* __restrict__ wo, float* __restrict__ AO)
{
    int ui = blockIdx.x, bh = blockIdx.y;
    int b = bh >> 4, h = bh & 15;
    int l = Mtop[bh * TOPK + ui];
    __shared__ float r[64];
    int tid = threadIdx.x;
    if (tid < 64) r[tid] = outred[((size_t)bh * TOPK + ui) * 64 + tid];
    __syncthreads();
    float a0 = 0.f, a1 = 0.f, a2 = 0.f, a3 = 0.f;
    const float* w = wo + (size_t)h * 64 * Dc + tid;
#pragma unroll 8
    for (int e = 0; e < 64; e++) {
        float re = r[e];
        const float* wr = w + (size_t)e * Dc;
        a0 = fmaf(re, wr[0],   a0);
        a1 = fmaf(re, wr[256], a1);
        a2 = fmaf(re, wr[512], a2);
        a3 = fmaf(re, wr[768], a3);
    }
    float* dst = AO + ((size_t)b * Lc + l) * Dc + tid;
    atomicAdd(dst,       a0);
    atomicAdd(dst + 256, a1);
    atomicAdd(dst + 512, a2);
    atomicAdd(dst + 768, a3);
}

// ---------------- residual add + LayerNorm (+opt bf16 split out) -----------
__global__ __launch_bounds__(256) void add_ln_kernel(
    const float* __restrict__ X, const float* __restrict__ Y,
    const float* __restrict__ g, const float* __restrict__ be,
    float* __restrict__ out, bf16* __restrict__ oh, bf16* __restrict__ ol)
{
    int row = blockIdx.x, tid = threadIdx.x;
    __shared__ float red[256];
    float v[4];
    float s = 0.f;
#pragma unroll
    for (int c = 0; c < 4; c++) {
        size_t i = (size_t)row * Dc + tid + c * 256;
        v[c] = X[i] + Y[i];
        s += v[c];
    }
    red[tid] = s; __syncthreads();
    for (int st = 128; st > 0; st >>= 1) {
        if (tid < st) red[tid] += red[tid + st];
        __syncthreads();
    }
    float mean = red[0] * (1.f / 1024.f);
    __syncthreads();
    float s2 = 0.f;
#pragma unroll
    for (int c = 0; c < 4; c++) { float t = v[c] - mean; s2 = fmaf(t, t, s2); }
    red[tid] = s2; __syncthreads();
    for (int st = 128; st > 0; st >>= 1) {
        if (tid < st) red[tid] += red[tid + st];
        __syncthreads();
    }
    float var = red[0] * (1.f / 1024.f);
    float rstd = 1.0f / sqrtf(var + 1e-12f);
#pragma unroll
    for (int c = 0; c < 4; c++) {
        int col = tid + c * 256;
        float o = g[col] * ((v[c] - mean) * rstd) + be[col];
        out[(size_t)row * Dc + col] = o;
        if (oh) {
            bf16 h, l;
            bsplit(o, h, l);
            oh[(size_t)row * Dc + col] = h;
            ol[(size_t)row * Dc + col] = l;
        }
    }
}

// ---------------- launch ---------------------------------------------------
extern "C" void kernel_launch(void* const* d_in, const int* in_sizes, int n_in,
                              void* d_out, int out_size)
{
    const float* x   = (const float*)d_in[0];
    const float* wq  = (const float*)d_in[1];
    const float* bq  = (const float*)d_in[2];
    const float* wk  = (const float*)d_in[3];
    const float* bk  = (const float*)d_in[4];
    const float* wv  = (const float*)d_in[5];
    const float* bv  = (const float*)d_in[6];
    const float* wo  = (const float*)d_in[7];
    const float* bo  = (const float*)d_in[8];
    const float* w1  = (const float*)d_in[9];
    const float* b1  = (const float*)d_in[10];
    const float* w2  = (const float*)d_in[11];
    const float* b2  = (const float*)d_in[12];
    const float* ga1 = (const float*)d_in[13];
    const float* be1 = (const float*)d_in[14];
    const float* ga2 = (const float*)d_in[15];
    const float* be2 = (const float*)d_in[16];
    const int*   idx = (const int*)d_in[17];
    float* out = (float*)d_out;

    float *Q, *K, *V, *AO, *X1, *Y2, *Mv, *Or;
    bf16 *Xbh, *Xbl, *Qbh, *Qbl, *X1bh, *X1bl, *Y1bh, *Y1bl, *Ksbh, *Ksbl;
    bf16 *Wqh, *Wql, *Wkh, *Wkl, *Wvh, *Wvl, *W1h, *W1l, *W2h, *W2l;
    int* Mt;
    cudaGetSymbolAddress((void**)&Q,    g_Q);
    cudaGetSymbolAddress((void**)&K,    g_K);
    cudaGetSymbolAddress((void**)&V,    g_V);
    cudaGetSymbolAddress((void**)&AO,   g_AO);
    cudaGetSymbolAddress((void**)&X1,   g_X1);
    cudaGetSymbolAddress((void**)&Y2,   g_Y2);
    cudaGetSymbolAddress((void**)&Mv,   g_M);
    cudaGetSymbolAddress((void**)&Mt,   g_Mtop);
    cudaGetSymbolAddress((void**)&Or,   g_Or);
    cudaGetSymbolAddress((void**)&Xbh,  g_Xbh);
    cudaGetSymbolAddress((void**)&Xbl,  g_Xbl);
    cudaGetSymbolAddress((void**)&Qbh,  g_Qbh);
    cudaGetSymbolAddress((void**)&Qbl,  g_Qbl);
    cudaGetSymbolAddress((void**)&X1bh, g_X1bh);
    cudaGetSymbolAddress((void**)&X1bl, g_X1bl);
    cudaGetSymbolAddress((void**)&Y1bh, g_Y1bh);
    cudaGetSymbolAddress((void**)&Y1bl, g_Y1bl);
    cudaGetSymbolAddress((void**)&Ksbh, g_Ksbh);
    cudaGetSymbolAddress((void**)&Ksbl, g_Ksbl);
    cudaGetSymbolAddress((void**)&Wqh,  g_Wqh);
    cudaGetSymbolAddress((void**)&Wql,  g_Wql);
    cudaGetSymbolAddress((void**)&Wkh,  g_Wkh);
    cudaGetSymbolAddress((void**)&Wkl,  g_Wkl);
    cudaGetSymbolAddress((void**)&Wvh,  g_Wvh);
    cudaGetSymbolAddress((void**)&Wvl,  g_Wvl);
    cudaGetSymbolAddress((void**)&W1h,  g_W1h);
    cudaGetSymbolAddress((void**)&W1l,  g_W1l);
    cudaGetSymbolAddress((void**)&W2h,  g_W2h);
    cudaGetSymbolAddress((void**)&W2l,  g_W2l);

    cudaFuncSetAttribute(gemm_bf, cudaFuncAttributeMaxDynamicSharedMemorySize, 3 * GSTB);
    cudaFuncSetAttribute(qk_bf,   cudaFuncAttributeMaxDynamicSharedMemorySize, 94208);
    cudaFuncSetAttribute(sparse_attn2, cudaFuncAttributeMaxDynamicSharedMemorySize, 53504);

    dim3 t32x8(32, 8);
    wsplit_kernel<<<dim3(Dc / 32, Dc / 32), t32x8>>>(wq, Wqh, Wql, Dc, Dc);
    wsplit_kernel<<<dim3(Dc / 32, Dc / 32), t32x8>>>(wk, Wkh, Wkl, Dc, Dc);
    wsplit_kernel<<<dim3(Dc / 32, Dc / 32), t32x8>>>(wv, Wvh, Wvl, Dc, Dc);
    wsplit_kernel<<<dim3(Fc / 32, Dc / 32), t32x8>>>(w1, W1h, W1l, Dc, Fc);
    wsplit_kernel<<<dim3(Dc / 32, Fc / 32), t32x8>>>(w2, W2h, W2l, Fc, Dc);

    xsplit_kernel<<<(MR * Dc / 4) / 256, 256>>>(x, Xbh, Xbl);

    gemm_bf<<<dim3(8, 64), 256, 3 * GSTB>>>(Xbh, Xbl, Wqh, Wql, bq, Q, Qbh, Qbl, Dc, Dc, 0);
    gemm_bf<<<dim3(8, 64), 256, 3 * GSTB>>>(Xbh, Xbl, Wkh, Wkl, bk, K, (bf16*)0, (bf16*)0, Dc, Dc, 0);
    gemm_bf<<<dim3(8, 64), 256, 3 * GSTB>>>(Xbh, Xbl, Wvh, Wvl, bv, V, (bf16*)0, (bf16*)0, Dc, Dc, 0);

    gather_split_kernel<<<dim3(Uc, Bc), 256>>>(K, idx, Ksbh, Ksbl);
    qk_bf<<<dim3(Lc / 128, BHc), 256, 94208>>>(Qbh, Qbl, Ksbh, Ksbl, Mv);
    topk_kernel<<<BHc, 256>>>(Mv, Mt);

    sparse_attn2<<<BHc, 256, 53504>>>(Q, K, V, Mt, Or);

    init_bias_kernel<<<MR, 256>>>(bo, AO);
    sparse_proj_kernel<<<dim3(TOPK, BHc), 256>>>(Or, Mt, wo, AO);

    add_ln_kernel<<<MR, 256>>>(x, AO, ga1, be1, X1, X1bh, X1bl);

    gemm_bf<<<dim3(32, 64), 256, 3 * GSTB>>>(X1bh, X1bl, W1h, W1l, b1, (float*)0, Y1bh, Y1bl, Dc, Fc, 1);
    gemm_bf<<<dim3(8, 64), 256, 3 * GSTB>>>(Y1bh, Y1bl, W2h, W2l, b2, Y2, (bf16*)0, (bf16*)0, Fc, Dc, 0);

    add_ln_kernel<<<MR, 256>>>(X1, Y2, ga2, be2, out, (bf16*)0, (bf16*)0);
}

// round 11
// speedup vs baseline: 1.5726x; 1.0567x over previous
#include <cuda_runtime.h>
#include <cuda_bf16.h>
#include <math.h>
#include <float.h>
#include <stdint.h>

#define Bc 4
#define Lc 2048
#define Dc 1024
#define Fc 4096
#define BHc 64
#define Uc 2048
#define TOPK 40
#define MR 8192

typedef __nv_bfloat16 bf16;
typedef __nv_bfloat162 bf162;

// ---------------- scratch (bf16 arrays 16B aligned: 16B vector ops used) -----
__device__ float g_Q [MR * Dc];
__device__ float g_K [MR * Dc];
__device__ float g_V [MR * Dc];
__device__ float g_AO[MR * Dc];
__device__ float g_X1[MR * Dc];
__device__ float g_Y2[MR * Dc];
__device__ float g_M [BHc * Lc];
__device__ int   g_Mtop[BHc * TOPK];
__device__ float g_Or[BHc * TOPK * 64];
__device__ __align__(16) bf16 g_Xbh[MR * Dc],  g_Xbl[MR * Dc];
__device__ __align__(16) bf16 g_Qbh[MR * Dc],  g_Qbl[MR * Dc];
__device__ __align__(16) bf16 g_X1bh[MR * Dc], g_X1bl[MR * Dc];
__device__ __align__(16) bf16 g_Y1bh[MR * Fc], g_Y1bl[MR * Fc];
__device__ __align__(16) bf16 g_Ksbh[BHc * Uc * 64], g_Ksbl[BHc * Uc * 64];
__device__ __align__(16) bf16 g_Wqh[Dc * Dc], g_Wql[Dc * Dc];
__device__ __align__(16) bf16 g_Wkh[Dc * Dc], g_Wkl[Dc * Dc];
__device__ __align__(16) bf16 g_Wvh[Dc * Dc], g_Wvl[Dc * Dc];
__device__ __align__(16) bf16 g_W1h[Dc * Fc], g_W1l[Dc * Fc];
__device__ __align__(16) bf16 g_W2h[Fc * Dc], g_W2l[Fc * Dc];

// ---------------- helpers --------------------------------------------------
__device__ __forceinline__ uint32_t s2u(const void* p) {
    uint32_t a;
    asm("{ .reg .u64 t; cvta.to.shared.u64 t, %1; cvt.u32.u64 %0, t; }" : "=r"(a) : "l"(p));
    return a;
}
__device__ __forceinline__ void cpa16(uint32_t dst, const void* src) {
    asm volatile("cp.async.ca.shared.global [%0], [%1], 16;" :: "r"(dst), "l"(src));
}
__device__ __forceinline__ void cpcommit() {
    asm volatile("cp.async.commit_group;");
}
template <int N>
__device__ __forceinline__ void cpwait() {
    asm volatile("cp.async.wait_group %0;" :: "n"(N));
}
// d += a * b  (m16n8k16 bf16)
__device__ __forceinline__ void mma16(float* d, const uint32_t* a, const uint32_t* b) {
    asm volatile(
        "mma.sync.aligned.m16n8k16.row.col.f32.bf16.bf16.f32 "
        "{%0,%1,%2,%3}, {%4,%5,%6,%7}, {%8,%9}, {%0,%1,%2,%3};"
        : "+f"(d[0]), "+f"(d[1]), "+f"(d[2]), "+f"(d[3])
        : "r"(a[0]), "r"(a[1]), "r"(a[2]), "r"(a[3]), "r"(b[0]), "r"(b[1]));
}
__device__ __forceinline__ void bsplit(float v, bf16& h, bf16& l) {
    h = __float2bfloat16_rn(v);
    l = __float2bfloat16_rn(v - __bfloat162float(h));
}

// ---------------- bf16x3 mma.sync GEMM, 2 stages, occupancy 2 ---------------
// C[M,N] = (Ah+Al)(M x Kd) @ ((Bh+Bl)[N,Kd])^T + bias (opt relu)
// smem stage (40960 B): Ah +0, Al +10240, Bh +20480, Bl +30720; row 80 B.
#define GSTB 40960
__global__ __launch_bounds__(256, 2) void gemm_bf(
    const bf16* __restrict__ Ah, const bf16* __restrict__ Al,
    const bf16* __restrict__ Bh, const bf16* __restrict__ Bl,
    const float* __restrict__ bias, float* __restrict__ C,
    bf16* __restrict__ Ch, bf16* __restrict__ Cl,
    int Kd, int Nd, int relu)
{
    extern __shared__ uint32_t smem_u[];
    uint32_t sb = s2u(smem_u);
    int tid = threadIdx.x, lane = tid & 31, wid = tid >> 5;
    int m0 = blockIdx.y * 128, n0 = blockIdx.x * 128;
    int wr = wid >> 1, wc = wid & 1;
    int NC = Kd >> 5;

    const bf16* gsrc[4] = { Ah + (size_t)m0 * Kd, Al + (size_t)m0 * Kd,
                            Bh + (size_t)n0 * Kd, Bl + (size_t)n0 * Kd };

    float c[2][8][4];
#pragma unroll
    for (int i = 0; i < 2; i++)
#pragma unroll
        for (int j = 0; j < 8; j++)
#pragma unroll
            for (int r = 0; r < 4; r++) c[i][j][r] = 0.f;

    int rld = tid >> 1, sgp = tid & 1;

    // preload stage 0
    {
        uint32_t st = sb;
#pragma unroll
        for (int a4 = 0; a4 < 4; a4++) {
            uint32_t dst = st + a4 * 10240 + rld * 80 + sgp * 32;
            const bf16* src = gsrc[a4] + (size_t)rld * Kd + sgp * 16;
            cpa16(dst, src);
            cpa16(dst + 16, src + 8);
        }
        cpcommit();
    }

    for (int ch = 0; ch < NC; ch++) {
        int s = ch & 1;
        if (ch + 1 < NC) {
            int k0 = (ch + 1) << 5;
            uint32_t st = sb + ((ch + 1) & 1) * GSTB;
#pragma unroll
            for (int a4 = 0; a4 < 4; a4++) {
                uint32_t dst = st + a4 * 10240 + rld * 80 + sgp * 32;
                const bf16* src = gsrc[a4] + (size_t)rld * Kd + k0 + sgp * 16;
                cpa16(dst, src);
                cpa16(dst + 16, src + 8);
            }
            cpcommit();
            cpwait<1>();
        } else {
            cpwait<0>();
        }
        __syncthreads();

        const uint32_t* sAh = smem_u + (s * GSTB) / 4;
        const uint32_t* sAl = sAh + 2560;
        const uint32_t* sBh = sAh + 5120;
        const uint32_t* sBl = sAh + 7680;
        int ar = wr * 32 + (lane >> 2);
        int bn = wc * 64 + (lane >> 2);
        int kq = lane & 3;

#pragma unroll
        for (int st2 = 0; st2 < 2; st2++) {
            int ko = st2 * 8 + kq;
            uint32_t ah[2][4], al[2][4], bhf[8][2], blf[8][2];
#pragma unroll
            for (int mt = 0; mt < 2; mt++) {
                int r0 = ar + mt * 16;
                ah[mt][0] = sAh[r0 * 20 + ko];
                ah[mt][1] = sAh[(r0 + 8) * 20 + ko];
                ah[mt][2] = sAh[r0 * 20 + ko + 4];
                ah[mt][3] = sAh[(r0 + 8) * 20 + ko + 4];
                al[mt][0] = sAl[r0 * 20 + ko];
                al[mt][1] = sAl[(r0 + 8) * 20 + ko];
                al[mt][2] = sAl[r0 * 20 + ko + 4];
                al[mt][3] = sAl[(r0 + 8) * 20 + ko + 4];
            }
#pragma unroll
            for (int nt = 0; nt < 8; nt++) {
                int n = bn + nt * 8;
                bhf[nt][0] = sBh[n * 20 + ko];
                bhf[nt][1] = sBh[n * 20 + ko + 4];
                blf[nt][0] = sBl[n * 20 + ko];
                blf[nt][1] = sBl[n * 20 + ko + 4];
            }
#pragma unroll
            for (int mt = 0; mt < 2; mt++)
#pragma unroll
                for (int nt = 0; nt < 8; nt++) {
                    mma16(c[mt][nt], ah[mt], bhf[nt]);
                    mma16(c[mt][nt], ah[mt], blf[nt]);
                    mma16(c[mt][nt], al[mt], bhf[nt]);
                }
        }
        __syncthreads();
    }

#pragma unroll
    for (int mt = 0; mt < 2; mt++) {
        int row = m0 + wr * 32 + mt * 16 + (lane >> 2);
#pragma unroll
        for (int nt = 0; nt < 8; nt++) {
            int col = n0 + wc * 64 + nt * 8 + (lane & 3) * 2;
            float b0 = bias[col], b1 = bias[col + 1];
            float2 v0 = make_float2(c[mt][nt][0] + b0, c[mt][nt][1] + b1);
            float2 v1 = make_float2(c[mt][nt][2] + b0, c[mt][nt][3] + b1);
            if (relu) {
                v0.x = fmaxf(v0.x, 0.f); v0.y = fmaxf(v0.y, 0.f);
                v1.x = fmaxf(v1.x, 0.f); v1.y = fmaxf(v1.y, 0.f);
            }
            if (C) {
                *(float2*)(C + (size_t)row * Nd + col) = v0;
                *(float2*)(C + (size_t)(row + 8) * Nd + col) = v1;
            }
            if (Ch) {
                bf16 h0, l0, h1, l1;
                bsplit(v0.x, h0, l0); bsplit(v0.y, h1, l1);
                *(bf162*)(Ch + (size_t)row * Nd + col) = bf162(h0, h1);
                *(bf162*)(Cl + (size_t)row * Nd + col) = bf162(l0, l1);
                bsplit(v1.x, h0, l0); bsplit(v1.y, h1, l1);
                *(bf162*)(Ch + (size_t)(row + 8) * Nd + col) = bf162(h0, h1);
                *(bf162*)(Cl + (size_t)(row + 8) * Nd + col) = bf162(l0, l1);
            }
        }
    }
}

// ---------------- QK stats via bf16x3: M = rowmax - rowsum/L ---------------
__global__ __launch_bounds__(256, 1) void qk_bf(
    const bf16* __restrict__ Qh, const bf16* __restrict__ Ql,
    const bf16* __restrict__ Ksh, const bf16* __restrict__ Ksl,
    float* __restrict__ Mout)
{
    extern __shared__ uint32_t smem_u[];
    uint32_t sb = s2u(smem_u);
    int tid = threadIdx.x, lane = tid & 31, wid = tid >> 5;
    int m0 = blockIdx.x * 128, bh = blockIdx.y;
    int wr = wid >> 1, wc = wid & 1;

    {
        const bf16* qh = Qh + ((size_t)bh * Lc + m0) * 64;
        const bf16* ql = Ql + ((size_t)bh * Lc + m0) * 64;
#pragma unroll
        for (int i = 0; i < 4; i++) {
            int idx = tid + i * 256;
            int r = idx >> 3, c16 = idx & 7;
            float4 v = *(const float4*)(qh + (size_t)r * 64 + c16 * 8);
            *(float4*)(smem_u + r * 36 + c16 * 4) = v;
            v = *(const float4*)(ql + (size_t)r * 64 + c16 * 8);
            *(float4*)(smem_u + 4608 + r * 36 + c16 * 4) = v;
        }
    }

    const bf16* kh = Ksh + (size_t)bh * Uc * 64;
    const bf16* kl = Ksl + (size_t)bh * Uc * 64;
    int rld = tid >> 2, sgp = tid & 3;

#pragma unroll
    for (int pre = 0; pre < 2; pre++) {
        uint32_t st = sb + 36864 + pre * 18432;
        const bf16* s0 = kh + (size_t)(pre * 64 + rld) * 64 + sgp * 16;
        const bf16* s1 = kl + (size_t)(pre * 64 + rld) * 64 + sgp * 16;
        uint32_t d0 = st + rld * 144 + sgp * 32;
        cpa16(d0, s0); cpa16(d0 + 16, s0 + 8);
        uint32_t d1 = d0 + 9216;
        cpa16(d1, s1); cpa16(d1 + 16, s1 + 8);
        cpcommit();
    }
    __syncthreads();

    float rmax[2][2], rsum[2][2];
#pragma unroll
    for (int i = 0; i < 2; i++)
#pragma unroll
        for (int j = 0; j < 2; j++) { rmax[i][j] = -FLT_MAX; rsum[i][j] = 0.f; }

    for (int ch = 0; ch < 32; ch++) {
        int s = ch % 3;
        if (ch + 2 < 32) {
            uint32_t st = sb + 36864 + ((ch + 2) % 3) * 18432;
            const bf16* s0 = kh + (size_t)((ch + 2) * 64 + rld) * 64 + sgp * 16;
            const bf16* s1 = kl + (size_t)((ch + 2) * 64 + rld) * 64 + sgp * 16;
            uint32_t d0 = st + rld * 144 + sgp * 32;
            cpa16(d0, s0); cpa16(d0 + 16, s0 + 8);
            uint32_t d1 = d0 + 9216;
            cpa16(d1, s1); cpa16(d1 + 16, s1 + 8);
            cpcommit();
            cpwait<2>();
        } else if (ch + 2 == 32) {
            cpwait<1>();
        } else {
            cpwait<0>();
        }
        __syncthreads();

        const uint32_t* sQh = smem_u;
        const uint32_t* sQl = smem_u + 4608;
        const uint32_t* sBh = smem_u + 9216 + s * 4608;
        const uint32_t* sBl = sBh + 2304;
        int ar = wr * 32 + (lane >> 2);
        int bn = wc * 32 + (lane >> 2);
        int kq = lane & 3;

        float c[2][4][4];
#pragma unroll
        for (int i = 0; i < 2; i++)
#pragma unroll
            for (int j = 0; j < 4; j++)
#pragma unroll
                for (int r = 0; r < 4; r++) c[i][j][r] = 0.f;

#pragma unroll
        for (int st = 0; st < 4; st++) {
            int ko = st * 8 + kq;
            uint32_t ah[2][4], al[2][4], bhf[4][2], blf[4][2];
#pragma unroll
            for (int mt = 0; mt < 2; mt++) {
                int r0 = ar + mt * 16;
                ah[mt][0] = sQh[r0 * 36 + ko];
                ah[mt][1] = sQh[(r0 + 8) * 36 + ko];
                ah[mt][2] = sQh[r0 * 36 + ko + 4];
                ah[mt][3] = sQh[(r0 + 8) * 36 + ko + 4];
                al[mt][0] = sQl[r0 * 36 + ko];
                al[mt][1] = sQl[(r0 + 8) * 36 + ko];
                al[mt][2] = sQl[r0 * 36 + ko + 4];
                al[mt][3] = sQl[(r0 + 8) * 36 + ko + 4];
            }
#pragma unroll
            for (int nt = 0; nt < 4; nt++) {
                int n = bn + nt * 8;
                bhf[nt][0] = sBh[n * 36 + ko];
                bhf[nt][1] = sBh[n * 36 + ko + 4];
                blf[nt][0] = sBl[n * 36 + ko];
                blf[nt][1] = sBl[n * 36 + ko + 4];
            }
#pragma unroll
            for (int mt = 0; mt < 2; mt++)
#pragma unroll
                for (int nt = 0; nt < 4; nt++) {
                    mma16(c[mt][nt], ah[mt], bhf[nt]);
                    mma16(c[mt][nt], ah[mt], blf[nt]);
                    mma16(c[mt][nt], al[mt], bhf[nt]);
                }
        }

#pragma unroll
        for (int mt = 0; mt < 2; mt++)
#pragma unroll
            for (int hf = 0; hf < 2; hf++) {
                float mx = -FLT_MAX, sm = 0.f;
#pragma unroll
                for (int nt = 0; nt < 4; nt++) {
                    float v0 = c[mt][nt][hf * 2], v1 = c[mt][nt][hf * 2 + 1];
                    mx = fmaxf(mx, fmaxf(v0, v1));
                    sm += v0 + v1;
                }
                mx = fmaxf(mx, __shfl_xor_sync(0xffffffffu, mx, 1));
                sm += __shfl_xor_sync(0xffffffffu, sm, 1);
                mx = fmaxf(mx, __shfl_xor_sync(0xffffffffu, mx, 2));
                sm += __shfl_xor_sync(0xffffffffu, sm, 2);
                rmax[mt][hf] = fmaxf(rmax[mt][hf], mx);
                rsum[mt][hf] += sm;
            }
        __syncthreads();
    }

    float* red = (float*)(smem_u + 23040);
    if ((lane & 3) == 0) {
#pragma unroll
        for (int mt = 0; mt < 2; mt++)
#pragma unroll
            for (int hf = 0; hf < 2; hf++) {
                int row = wr * 32 + mt * 16 + (lane >> 2) + hf * 8;
                red[(wc * 128 + row) * 2 + 0] = rmax[mt][hf];
                red[(wc * 128 + row) * 2 + 1] = rsum[mt][hf];
            }
    }
    __syncthreads();
    if (tid < 128) {
        float m0v = red[tid * 2], s0v = red[tid * 2 + 1];
        float m1v = red[(128 + tid) * 2], s1v = red[(128 + tid) * 2 + 1];
        Mout[(size_t)bh * Lc + m0 + tid] =
            fmaxf(m0v, m1v) - (s0v + s1v) * (1.f / (float)Lc);
    }
}

// ---------------- transpose + bf16 split weights ---------------------------
__global__ void wsplit_kernel(const float* __restrict__ W, bf16* __restrict__ Wh,
                              bf16* __restrict__ Wl, int Kd, int Nd)
{
    __shared__ float t[32][33];
    int x = threadIdx.x, y = threadIdx.y;
    int n0 = blockIdx.x * 32, k0 = blockIdx.y * 32;
#pragma unroll
    for (int i = 0; i < 32; i += 8)
        t[y + i][x] = W[(size_t)(k0 + y + i) * Nd + n0 + x];
    __syncthreads();
#pragma unroll
    for (int i = 0; i < 32; i += 8) {
        float v = t[x][y + i];
        bf16 h, l;
        bsplit(v, h, l);
        size_t o = (size_t)(n0 + y + i) * Kd + k0 + x;
        Wh[o] = h;
        Wl[o] = l;
    }
}

// ---------------- elementwise fp32 -> bf16 hi/lo ---------------------------
__global__ void xsplit_kernel(const float* __restrict__ src, bf16* __restrict__ hi,
                              bf16* __restrict__ lo)
{
    int i = blockIdx.x * 256 + threadIdx.x;
    float4 v = ((const float4*)src)[i];
    bf16 h0, l0, h1, l1, h2, l2, h3, l3;
    bsplit(v.x, h0, l0); bsplit(v.y, h1, l1);
    bsplit(v.z, h2, l2); bsplit(v.w, h3, l3);
    ((bf162*)hi)[i * 2]     = bf162(h0, h1);
    ((bf162*)hi)[i * 2 + 1] = bf162(h2, h3);
    ((bf162*)lo)[i * 2]     = bf162(l0, l1);
    ((bf162*)lo)[i * 2 + 1] = bf162(l2, l3);
}

// ---------------- gather sampled keys + bf16 split, head-major -------------
__global__ void gather_split_kernel(const float* __restrict__ K, const int* __restrict__ idx,
                                    bf16* __restrict__ Ksh, bf16* __restrict__ Ksl)
{
    int j = blockIdx.x, b = blockIdx.y, t = threadIdx.x;
    int src = idx[j];
    float4 v = *(const float4*)(K + ((size_t)b * Lc + src) * Dc + t * 4);
    int h = t >> 4, e = (t & 15) * 4;
    bf16 h0, l0, h1, l1, h2, l2, h3, l3;
    bsplit(v.x, h0, l0); bsplit(v.y, h1, l1);
    bsplit(v.z, h2, l2); bsplit(v.w, h3, l3);
    size_t o = (((size_t)(b * 16 + h)) * Uc + j) * 64 + e;
    *(bf162*)(Ksh + o)     = bf162(h0, h1);
    *(bf162*)(Ksh + o + 2) = bf162(h2, h3);
    *(bf162*)(Ksl + o)     = bf162(l0, l1);
    *(bf162*)(Ksl + o + 2) = bf162(l2, l3);
}

// ---------------- top-40 smallest M (ties -> lower index) ------------------
__global__ __launch_bounds__(256) void topk_kernel(const float* __restrict__ Mv,
                                                   int* __restrict__ Mtop)
{
    __shared__ float sv[Lc];
    __shared__ float rv[256];
    __shared__ int   ri[256];
    int bh = blockIdx.x, tid = threadIdx.x;
    for (int i = tid; i < Lc; i += 256) sv[i] = Mv[(size_t)bh * Lc + i];
    __syncthreads();
    for (int it = 0; it < TOPK; it++) {
        float bv = FLT_MAX; int bi = 0x7fffffff;
        for (int i = tid; i < Lc; i += 256) {
            float v = sv[i];
            if (v < bv || (v == bv && i < bi)) { bv = v; bi = i; }
        }
        rv[tid] = bv; ri[tid] = bi;
        __syncthreads();
        for (int s = 128; s > 0; s >>= 1) {
            if (tid < s) {
                float v2 = rv[tid + s]; int i2 = ri[tid + s];
                if (v2 < rv[tid] || (v2 == rv[tid] && i2 < ri[tid])) {
                    rv[tid] = v2; ri[tid] = i2;
                }
            }
            __syncthreads();
        }
        if (tid == 0) { Mtop[bh * TOPK + it] = ri[0]; sv[ri[0]] = FLT_MAX; }
        __syncthreads();
    }
}

// ---------------- sparse attention: one block per (b,h), all 40 queries ----
__global__ __launch_bounds__(256, 1) void sparse_attn2(
    const float* __restrict__ Q, const float* __restrict__ K, const float* __restrict__ V,
    const int* __restrict__ Mtop, float* __restrict__ outred)
{
    extern __shared__ float sm[];
    float* qs   = sm;            // [40][64]
    float* ks   = sm + 2560;     // [64][65]
    float* vs   = sm + 6720;     // [64][64]
    float* wbuf = sm + 10816;    // [warp][5][64]

    int bh = blockIdx.x;
    int b = bh >> 4, h = bh & 15;
    int tid = threadIdx.x, lane = tid & 31, warp = tid >> 5;

    for (int i = tid; i < TOPK * 64; i += 256) {
        int q = i >> 6, d = i & 63;
        int qi = Mtop[bh * TOPK + q];
        qs[i] = Q[((size_t)bh * Lc + qi) * 64 + d];
    }

    const float* kb = K + (size_t)b * Lc * Dc + h * 64;
    const float* vb = V + (size_t)b * Lc * Dc + h * 64;

    float m[5], sum[5], acc0[5], acc1[5];
#pragma unroll
    for (int q = 0; q < 5; q++) {
        m[q] = -FLT_MAX; sum[q] = 0.f; acc0[q] = 0.f; acc1[q] = 0.f;
    }
    float* wq = wbuf + warp * 320;

    for (int l0 = 0; l0 < Lc; l0 += 64) {
        __syncthreads();
        for (int i = tid; i < 64 * 64; i += 256) {
            int row = i >> 6, d = i & 63;
            ks[d * 65 + row] = kb[(size_t)(l0 + row) * Dc + d];
            vs[i] = vb[(size_t)(l0 + row) * Dc + d];
        }
        __syncthreads();

#pragma unroll
        for (int q = 0; q < 5; q++) {
            const float* qrow = qs + (warp * 5 + q) * 64;
            float s0 = 0.f, s1 = 0.f;
#pragma unroll
            for (int d = 0; d < 64; d++) {
                float qv = qrow[d];
                s0 = fmaf(qv, ks[d * 65 + lane], s0);
                s1 = fmaf(qv, ks[d * 65 + lane + 32], s1);
            }
            s0 *= 0.125f; s1 *= 0.125f;
            float cmx = fmaxf(s0, s1);
#pragma unroll
            for (int off = 16; off > 0; off >>= 1)
                cmx = fmaxf(cmx, __shfl_xor_sync(0xffffffffu, cmx, off));
            float nm = fmaxf(m[q], cmx);
            float scale = expf(m[q] - nm);
            float w0 = expf(s0 - nm), w1 = expf(s1 - nm);
            float csum = w0 + w1;
#pragma unroll
            for (int off = 16; off > 0; off >>= 1)
                csum += __shfl_xor_sync(0xffffffffu, csum, off);
            sum[q] = sum[q] * scale + csum;
            m[q] = nm;
            wq[q * 64 + lane] = w0;
            wq[q * 64 + lane + 32] = w1;
            __syncwarp();
            float a0 = acc0[q] * scale, a1 = acc1[q] * scale;
#pragma unroll
            for (int k = 0; k < 64; k++) {
                float wv = wq[q * 64 + k];
                a0 = fmaf(wv, vs[k * 64 + lane], a0);
                a1 = fmaf(wv, vs[k * 64 + lane + 32], a1);
            }
            acc0[q] = a0; acc1[q] = a1;
            __syncwarp();
        }
    }

#pragma unroll
    for (int q = 0; q < 5; q++) {
        float inv = 1.0f / sum[q];
        size_t o = ((size_t)bh * TOPK + warp * 5 + q) * 64;
        outred[o + lane] = acc0[q] * inv;
        outred[o + lane + 32] = acc1[q] * inv;
    }
}

__global__ void init_bias_kernel(const float* __restrict__ bo, float* __restrict__ AO)
{
    float4 v = *(const float4*)(bo + threadIdx.x * 4);
    *(float4*)(AO + (size_t)blockIdx.x * Dc + threadIdx.x * 4) = v;
}

__global__ __launch_bounds__(256) void sparse_proj_kernel(
    const float* __restrict__ outred, const int* __restrict__ Mtop,
    const float* __restrict__ wo, float* __restrict__ AO)
{
    int ui = blockIdx.x, bh = blockIdx.y;
    int b = bh >> 4, h = bh & 15;
    int l = Mtop[bh * TOPK + ui];
    __shared__ float r[64];
    int tid = threadIdx.x;
    if (tid < 64) r[tid] = outred[((size_t)bh * TOPK + ui) * 64 + tid];
    __syncthreads();
    float a0 = 0.f, a1 = 0.f, a2 = 0.f, a3 = 0.f;
    const float* w = wo + (size_t)h * 64 * Dc + tid;
#pragma unroll 8
    for (int e = 0; e < 64; e++) {
        float re = r[e];
        const float* wr = w + (size_t)e * Dc;
        a0 = fmaf(re, wr[0],   a0);
        a1 = fmaf(re, wr[256], a1);
        a2 = fmaf(re, wr[512], a2);
        a3 = fmaf(re, wr[768], a3);
    }
    float* dst = AO + ((size_t)b * Lc + l) * Dc + tid;
    atomicAdd(dst,       a0);
    atomicAdd(dst + 256, a1);
    atomicAdd(dst + 512, a2);
    atomicAdd(dst + 768, a3);
}

// ---------------- residual add + LayerNorm (+opt bf16 split out) -----------
__global__ __launch_bounds__(256) void add_ln_kernel(
    const float* __restrict__ X, const float* __restrict__ Y,
    const float* __restrict__ g, const float* __restrict__ be,
    float* __restrict__ out, bf16* __restrict__ oh, bf16* __restrict__ ol)
{
    int row = blockIdx.x, tid = threadIdx.x;
    __shared__ float red[256];
    float v[4];
    float s = 0.f;
#pragma unroll
    for (int c = 0; c < 4; c++) {
        size_t i = (size_t)row * Dc + tid + c * 256;
        v[c] = X[i] + Y[i];
        s += v[c];
    }
    red[tid] = s; __syncthreads();
    for (int st = 128; st > 0; st >>= 1) {
        if (tid < st) red[tid] += red[tid + st];
        __syncthreads();
    }
    float mean = red[0] * (1.f / 1024.f);
    __syncthreads();
    float s2 = 0.f;
#pragma unroll
    for (int c = 0; c < 4; c++) { float t = v[c] - mean; s2 = fmaf(t, t, s2); }
    red[tid] = s2; __syncthreads();
    for (int st = 128; st > 0; st >>= 1) {
        if (tid < st) red[tid] += red[tid + st];
        __syncthreads();
    }
    float var = red[0] * (1.f / 1024.f);
    float rstd = 1.0f / sqrtf(var + 1e-12f);
#pragma unroll
    for (int c = 0; c < 4; c++) {
        int col = tid + c * 256;
        float o = g[col] * ((v[c] - mean) * rstd) + be[col];
        out[(size_t)row * Dc + col] = o;
        if (oh) {
            bf16 h, l;
            bsplit(o, h, l);
            oh[(size_t)row * Dc + col] = h;
            ol[(size_t)row * Dc + col] = l;
        }
    }
}

// ---------------- launch ---------------------------------------------------
extern "C" void kernel_launch(void* const* d_in, const int* in_sizes, int n_in,
                              void* d_out, int out_size)
{
    const float* x   = (const float*)d_in[0];
    const float* wq  = (const float*)d_in[1];
    const float* bq  = (const float*)d_in[2];
    const float* wk  = (const float*)d_in[3];
    const float* bk  = (const float*)d_in[4];
    const float* wv  = (const float*)d_in[5];
    const float* bv  = (const float*)d_in[6];
    const float* wo  = (const float*)d_in[7];
    const float* bo  = (const float*)d_in[8];
    const float* w1  = (const float*)d_in[9];
    const float* b1  = (const float*)d_in[10];
    const float* w2  = (const float*)d_in[11];
    const float* b2  = (const float*)d_in[12];
    const float* ga1 = (const float*)d_in[13];
    const float* be1 = (const float*)d_in[14];
    const float* ga2 = (const float*)d_in[15];
    const float* be2 = (const float*)d_in[16];
    const int*   idx = (const int*)d_in[17];
    float* out = (float*)d_out;

    float *Q, *K, *V, *AO, *X1, *Y2, *Mv, *Or;
    bf16 *Xbh, *Xbl, *Qbh, *Qbl, *X1bh, *X1bl, *Y1bh, *Y1bl, *Ksbh, *Ksbl;
    bf16 *Wqh, *Wql, *Wkh, *Wkl, *Wvh, *Wvl, *W1h, *W1l, *W2h, *W2l;
    int* Mt;
    cudaGetSymbolAddress((void**)&Q,    g_Q);
    cudaGetSymbolAddress((void**)&K,    g_K);
    cudaGetSymbolAddress((void**)&V,    g_V);
    cudaGetSymbolAddress((void**)&AO,   g_AO);
    cudaGetSymbolAddress((void**)&X1,   g_X1);
    cudaGetSymbolAddress((void**)&Y2,   g_Y2);
    cudaGetSymbolAddress((void**)&Mv,   g_M);
    cudaGetSymbolAddress((void**)&Mt,   g_Mtop);
    cudaGetSymbolAddress((void**)&Or,   g_Or);
    cudaGetSymbolAddress((void**)&Xbh,  g_Xbh);
    cudaGetSymbolAddress((void**)&Xbl,  g_Xbl);
    cudaGetSymbolAddress((void**)&Qbh,  g_Qbh);
    cudaGetSymbolAddress((void**)&Qbl,  g_Qbl);
    cudaGetSymbolAddress((void**)&X1bh, g_X1bh);
    cudaGetSymbolAddress((void**)&X1bl, g_X1bl);
    cudaGetSymbolAddress((void**)&Y1bh, g_Y1bh);
    cudaGetSymbolAddress((void**)&Y1bl, g_Y1bl);
    cudaGetSymbolAddress((void**)&Ksbh, g_Ksbh);
    cudaGetSymbolAddress((void**)&Ksbl, g_Ksbl);
    cudaGetSymbolAddress((void**)&Wqh,  g_Wqh);
    cudaGetSymbolAddress((void**)&Wql,  g_Wql);
    cudaGetSymbolAddress((void**)&Wkh,  g_Wkh);
    cudaGetSymbolAddress((void**)&Wkl,  g_Wkl);
    cudaGetSymbolAddress((void**)&Wvh,  g_Wvh);
    cudaGetSymbolAddress((void**)&Wvl,  g_Wvl);
    cudaGetSymbolAddress((void**)&W1h,  g_W1h);
    cudaGetSymbolAddress((void**)&W1l,  g_W1l);
    cudaGetSymbolAddress((void**)&W2h,  g_W2h);
    cudaGetSymbolAddress((void**)&W2l,  g_W2l);

    cudaFuncSetAttribute(gemm_bf, cudaFuncAttributeMaxDynamicSharedMemorySize, 2 * GSTB);
    cudaFuncSetAttribute(qk_bf,   cudaFuncAttributeMaxDynamicSharedMemorySize, 94208);
    cudaFuncSetAttribute(sparse_attn2, cudaFuncAttributeMaxDynamicSharedMemorySize, 53504);

    dim3 t32x8(32, 8);
    wsplit_kernel<<<dim3(Dc / 32, Dc / 32), t32x8>>>(wq, Wqh, Wql, Dc, Dc);
    wsplit_kernel<<<dim3(Dc / 32, Dc / 32), t32x8>>>(wk, Wkh, Wkl, Dc, Dc);
    wsplit_kernel<<<dim3(Dc / 32, Dc / 32), t32x8>>>(wv, Wvh, Wvl, Dc, Dc);
    wsplit_kernel<<<dim3(Fc / 32, Dc / 32), t32x8>>>(w1, W1h, W1l, Dc, Fc);
    wsplit_kernel<<<dim3(Dc / 32, Fc / 32), t32x8>>>(w2, W2h, W2l, Fc, Dc);

    xsplit_kernel<<<(MR * Dc / 4) / 256, 256>>>(x, Xbh, Xbl);

    gemm_bf<<<dim3(8, 64), 256, 2 * GSTB>>>(Xbh, Xbl, Wqh, Wql, bq, Q, Qbh, Qbl, Dc, Dc, 0);
    gemm_bf<<<dim3(8, 64), 256, 2 * GSTB>>>(Xbh, Xbl, Wkh, Wkl, bk, K, (bf16*)0, (bf16*)0, Dc, Dc, 0);
    gemm_bf<<<dim3(8, 64), 256, 2 * GSTB>>>(Xbh, Xbl, Wvh, Wvl, bv, V, (bf16*)0, (bf16*)0, Dc, Dc, 0);

    gather_split_kernel<<<dim3(Uc, Bc), 256>>>(K, idx, Ksbh, Ksbl);
    qk_bf<<<dim3(Lc / 128, BHc), 256, 94208>>>(Qbh, Qbl, Ksbh, Ksbl, Mv);
    topk_kernel<<<BHc, 256>>>(Mv, Mt);

    sparse_attn2<<<BHc, 256, 53504>>>(Q, K, V, Mt, Or);

    init_bias_kernel<<<MR, 256>>>(bo, AO);
    sparse_proj_kernel<<<dim3(TOPK, BHc), 256>>>(Or, Mt, wo, AO);

    add_ln_kernel<<<MR, 256>>>(x, AO, ga1, be1, X1, X1bh, X1bl);

    gemm_bf<<<dim3(32, 64), 256, 2 * GSTB>>>(X1bh, X1bl, W1h, W1l, b1, (float*)0, Y1bh, Y1bl, Dc, Fc, 1);
    gemm_bf<<<dim3(8, 64), 256, 2 * GSTB>>>(Y1bh, Y1bl, W2h, W2l, b2, Y2, (bf16*)0, (bf16*)0, Fc, Dc, 0);

    add_ln_kernel<<<MR, 256>>>(X1, Y2, ga2, be2, out, (bf16*)0, (bf16*)0);
}

// round 12
// speedup vs baseline: 1.8295x; 1.1634x over previous
#include <cuda_runtime.h>
#include <cuda_bf16.h>
#include <math.h>
#include <float.h>
#include <stdint.h>

#define Bc 4
#define Lc 2048
#define Dc 1024
#define Fc 4096
#define BHc 64
#define Uc 2048
#define TOPK 40
#define MR 8192

typedef __nv_bfloat16 bf16;
typedef __nv_bfloat162 bf162;

// ---------------- scratch ---------------------------------------------------
__device__ float g_Q [MR * Dc];
__device__ float g_K [MR * Dc];
__device__ float g_V [MR * Dc];
__device__ float g_AO[MR * Dc];
__device__ float g_X1[MR * Dc];
__device__ float g_Y2[MR * Dc];
__device__ float g_M [BHc * Lc];
__device__ int   g_Mtop[BHc * TOPK];
__device__ float g_Or[BHc * TOPK * 64];
__device__ __align__(16) bf16 g_Xbh[MR * Dc],  g_Xbl[MR * Dc];
__device__ __align__(16) bf16 g_Qbh[MR * Dc],  g_Qbl[MR * Dc];
__device__ __align__(16) bf16 g_X1bh[MR * Dc], g_X1bl[MR * Dc];
__device__ __align__(16) bf16 g_Y1bh[MR * Fc], g_Y1bl[MR * Fc];
__device__ __align__(16) bf16 g_Ksbh[BHc * Uc * 64], g_Ksbl[BHc * Uc * 64];
__device__ __align__(16) bf16 g_Wqh[Dc * Dc], g_Wql[Dc * Dc];
__device__ __align__(16) bf16 g_Wkh[Dc * Dc], g_Wkl[Dc * Dc];
__device__ __align__(16) bf16 g_Wvh[Dc * Dc], g_Wvl[Dc * Dc];
__device__ __align__(16) bf16 g_W1h[Dc * Fc], g_W1l[Dc * Fc];
__device__ __align__(16) bf16 g_W2h[Fc * Dc], g_W2l[Fc * Dc];

// ---------------- helpers ---------------------------------------------------
__device__ __forceinline__ uint32_t s2u(const void* p) {
    uint32_t a;
    asm("{ .reg .u64 t; cvta.to.shared.u64 t, %1; cvt.u32.u64 %0, t; }" : "=r"(a) : "l"(p));
    return a;
}
__device__ __forceinline__ void cpa16(uint32_t dst, const void* src) {
    asm volatile("cp.async.ca.shared.global [%0], [%1], 16;" :: "r"(dst), "l"(src));
}
__device__ __forceinline__ void cpcommit() {
    asm volatile("cp.async.commit_group;");
}
template <int N>
__device__ __forceinline__ void cpwait() {
    asm volatile("cp.async.wait_group %0;" :: "n"(N));
}
__device__ __forceinline__ void mma16(float* d, const uint32_t* a, const uint32_t* b) {
    asm volatile(
        "mma.sync.aligned.m16n8k16.row.col.f32.bf16.bf16.f32 "
        "{%0,%1,%2,%3}, {%4,%5,%6,%7}, {%8,%9}, {%0,%1,%2,%3};"
        : "+f"(d[0]), "+f"(d[1]), "+f"(d[2]), "+f"(d[3])
        : "r"(a[0]), "r"(a[1]), "r"(a[2]), "r"(a[3]), "r"(b[0]), "r"(b[1]));
}
__device__ __forceinline__ void ldsm4(uint32_t* r, uint32_t addr) {
    asm volatile("ldmatrix.sync.aligned.m8n8.x4.shared.b16 {%0,%1,%2,%3}, [%4];"
        : "=r"(r[0]), "=r"(r[1]), "=r"(r[2]), "=r"(r[3]) : "r"(addr));
}
__device__ __forceinline__ void bsplit(float v, bf16& h, bf16& l) {
    h = __float2bfloat16_rn(v);
    l = __float2bfloat16_rn(v - __bfloat162float(h));
}

// ---------------- bf16x3 mma.sync GEMM, ldmatrix frags, occ 2 ---------------
// smem stage (40960 B): Ah +0, Al +10240, Bh +20480, Bl +30720; row 80 B.
#define GSTB 40960
__global__ __launch_bounds__(256, 2) void gemm_bf(
    const bf16* __restrict__ Ah, const bf16* __restrict__ Al,
    const bf16* __restrict__ Bh, const bf16* __restrict__ Bl,
    const float* __restrict__ bias, float* __restrict__ C,
    bf16* __restrict__ Ch, bf16* __restrict__ Cl,
    int Kd, int Nd, int relu)
{
    extern __shared__ uint32_t smem_u[];
    uint32_t sb = s2u(smem_u);
    int tid = threadIdx.x, lane = tid & 31, wid = tid >> 5;
    int m0 = blockIdx.y * 128, n0 = blockIdx.x * 128;
    int wr = wid >> 1, wc = wid & 1;
    int NC = Kd >> 5;

    const bf16* gsrc[4] = { Ah + (size_t)m0 * Kd, Al + (size_t)m0 * Kd,
                            Bh + (size_t)n0 * Kd, Bl + (size_t)n0 * Kd };

    float c[2][8][4];
#pragma unroll
    for (int i = 0; i < 2; i++)
#pragma unroll
        for (int j = 0; j < 8; j++)
#pragma unroll
            for (int r = 0; r < 4; r++) c[i][j][r] = 0.f;

    int rld = tid >> 1, sgp = tid & 1;

    // ldmatrix lane offsets (bit3/bit4 select row-half / k-half per operand)
    uint32_t aoff = (uint32_t)(wr * 32 + (lane & 7) + ((lane >> 3) & 1) * 8) * 80
                  + ((lane >> 4) & 1) * 16;
    uint32_t boff = (uint32_t)(wc * 64 + ((lane >> 4) & 1) * 8 + (lane & 7)) * 80
                  + ((lane >> 3) & 1) * 16;

    {   // preload stage 0
        uint32_t st = sb;
#pragma unroll
        for (int a4 = 0; a4 < 4; a4++) {
            uint32_t dst = st + a4 * 10240 + rld * 80 + sgp * 32;
            const bf16* src = gsrc[a4] + (size_t)rld * Kd + sgp * 16;
            cpa16(dst, src);
            cpa16(dst + 16, src + 8);
        }
        cpcommit();
    }

    for (int ch = 0; ch < NC; ch++) {
        int s = ch & 1;
        if (ch + 1 < NC) {
            int k0 = (ch + 1) << 5;
            uint32_t st = sb + ((ch + 1) & 1) * GSTB;
#pragma unroll
            for (int a4 = 0; a4 < 4; a4++) {
                uint32_t dst = st + a4 * 10240 + rld * 80 + sgp * 32;
                const bf16* src = gsrc[a4] + (size_t)rld * Kd + k0 + sgp * 16;
                cpa16(dst, src);
                cpa16(dst + 16, src + 8);
            }
            cpcommit();
            cpwait<1>();
        } else {
            cpwait<0>();
        }
        __syncthreads();

        uint32_t sbase = sb + s * GSTB;
#pragma unroll
        for (int st2 = 0; st2 < 2; st2++) {
            uint32_t kb = st2 * 32;
            uint32_t ah[2][4], al[2][4], bh4[4][4], bl4[4][4];
            ldsm4(ah[0], sbase + aoff + kb);
            ldsm4(ah[1], sbase + aoff + 16 * 80 + kb);
            ldsm4(al[0], sbase + 10240 + aoff + kb);
            ldsm4(al[1], sbase + 10240 + aoff + 16 * 80 + kb);
#pragma unroll
            for (int p = 0; p < 4; p++) {
                ldsm4(bh4[p], sbase + 20480 + boff + p * 16 * 80 + kb);
                ldsm4(bl4[p], sbase + 30720 + boff + p * 16 * 80 + kb);
            }
#pragma unroll
            for (int mt = 0; mt < 2; mt++)
#pragma unroll
                for (int nt = 0; nt < 8; nt++) {
                    const uint32_t* bh = &bh4[nt >> 1][(nt & 1) * 2];
                    const uint32_t* bl = &bl4[nt >> 1][(nt & 1) * 2];
                    mma16(c[mt][nt], ah[mt], bh);
                    mma16(c[mt][nt], ah[mt], bl);
                    mma16(c[mt][nt], al[mt], bh);
                }
        }
        __syncthreads();
    }

#pragma unroll
    for (int mt = 0; mt < 2; mt++) {
        int row = m0 + wr * 32 + mt * 16 + (lane >> 2);
#pragma unroll
        for (int nt = 0; nt < 8; nt++) {
            int col = n0 + wc * 64 + nt * 8 + (lane & 3) * 2;
            float b0 = bias[col], b1 = bias[col + 1];
            float2 v0 = make_float2(c[mt][nt][0] + b0, c[mt][nt][1] + b1);
            float2 v1 = make_float2(c[mt][nt][2] + b0, c[mt][nt][3] + b1);
            if (relu) {
                v0.x = fmaxf(v0.x, 0.f); v0.y = fmaxf(v0.y, 0.f);
                v1.x = fmaxf(v1.x, 0.f); v1.y = fmaxf(v1.y, 0.f);
            }
            if (C) {
                *(float2*)(C + (size_t)row * Nd + col) = v0;
                *(float2*)(C + (size_t)(row + 8) * Nd + col) = v1;
            }
            if (Ch) {
                bf16 h0, l0, h1, l1;
                bsplit(v0.x, h0, l0); bsplit(v0.y, h1, l1);
                *(bf162*)(Ch + (size_t)row * Nd + col) = bf162(h0, h1);
                *(bf162*)(Cl + (size_t)row * Nd + col) = bf162(l0, l1);
                bsplit(v1.x, h0, l0); bsplit(v1.y, h1, l1);
                *(bf162*)(Ch + (size_t)(row + 8) * Nd + col) = bf162(h0, h1);
                *(bf162*)(Cl + (size_t)(row + 8) * Nd + col) = bf162(l0, l1);
            }
        }
    }
}

// ---------------- QK stats via bf16x3 + ldmatrix ----------------------------
// Q rows stride 144 B; K-chunk rows stride 144 B.
__global__ __launch_bounds__(256, 1) void qk_bf(
    const bf16* __restrict__ Qh, const bf16* __restrict__ Ql,
    const bf16* __restrict__ Ksh, const bf16* __restrict__ Ksl,
    float* __restrict__ Mout)
{
    extern __shared__ uint32_t smem_u[];
    uint32_t sb = s2u(smem_u);
    int tid = threadIdx.x, lane = tid & 31, wid = tid >> 5;
    int m0 = blockIdx.x * 128, bh = blockIdx.y;
    int wr = wid >> 1, wc = wid & 1;

    {
        const bf16* qh = Qh + ((size_t)bh * Lc + m0) * 64;
        const bf16* ql = Ql + ((size_t)bh * Lc + m0) * 64;
#pragma unroll
        for (int i = 0; i < 4; i++) {
            int idx = tid + i * 256;
            int r = idx >> 3, c16 = idx & 7;
            float4 v = *(const float4*)(qh + (size_t)r * 64 + c16 * 8);
            *(float4*)(smem_u + r * 36 + c16 * 4) = v;
            v = *(const float4*)(ql + (size_t)r * 64 + c16 * 8);
            *(float4*)(smem_u + 4608 + r * 36 + c16 * 4) = v;
        }
    }

    const bf16* kh = Ksh + (size_t)bh * Uc * 64;
    const bf16* kl = Ksl + (size_t)bh * Uc * 64;
    int rld = tid >> 2, sgp = tid & 3;

    uint32_t aoff = (uint32_t)(wr * 32 + (lane & 7) + ((lane >> 3) & 1) * 8) * 144
                  + ((lane >> 4) & 1) * 16;
    uint32_t boff = (uint32_t)(wc * 32 + ((lane >> 4) & 1) * 8 + (lane & 7)) * 144
                  + ((lane >> 3) & 1) * 16;

#pragma unroll
    for (int pre = 0; pre < 2; pre++) {
        uint32_t st = sb + 36864 + pre * 18432;
        const bf16* s0 = kh + (size_t)(pre * 64 + rld) * 64 + sgp * 16;
        const bf16* s1 = kl + (size_t)(pre * 64 + rld) * 64 + sgp * 16;
        uint32_t d0 = st + rld * 144 + sgp * 32;
        cpa16(d0, s0); cpa16(d0 + 16, s0 + 8);
        uint32_t d1 = d0 + 9216;
        cpa16(d1, s1); cpa16(d1 + 16, s1 + 8);
        cpcommit();
    }
    __syncthreads();

    float rmax[2][2], rsum[2][2];
#pragma unroll
    for (int i = 0; i < 2; i++)
#pragma unroll
        for (int j = 0; j < 2; j++) { rmax[i][j] = -FLT_MAX; rsum[i][j] = 0.f; }

    for (int ch = 0; ch < 32; ch++) {
        int s = ch % 3;
        if (ch + 2 < 32) {
            uint32_t st = sb + 36864 + ((ch + 2) % 3) * 18432;
            const bf16* s0 = kh + (size_t)((ch + 2) * 64 + rld) * 64 + sgp * 16;
            const bf16* s1 = kl + (size_t)((ch + 2) * 64 + rld) * 64 + sgp * 16;
            uint32_t d0 = st + rld * 144 + sgp * 32;
            cpa16(d0, s0); cpa16(d0 + 16, s0 + 8);
            uint32_t d1 = d0 + 9216;
            cpa16(d1, s1); cpa16(d1 + 16, s1 + 8);
            cpcommit();
            cpwait<2>();
        } else if (ch + 2 == 32) {
            cpwait<1>();
        } else {
            cpwait<0>();
        }
        __syncthreads();

        uint32_t qbase = sb;
        uint32_t bbase = sb + 36864 + s * 18432;

        float c[2][4][4];
#pragma unroll
        for (int i = 0; i < 2; i++)
#pragma unroll
            for (int j = 0; j < 4; j++)
#pragma unroll
                for (int r = 0; r < 4; r++) c[i][j][r] = 0.f;

#pragma unroll
        for (int st = 0; st < 4; st++) {
            uint32_t kb = st * 32;
            uint32_t ah[2][4], al[2][4], bh4[2][4], bl4[2][4];
            ldsm4(ah[0], qbase + aoff + kb);
            ldsm4(ah[1], qbase + aoff + 16 * 144 + kb);
            ldsm4(al[0], qbase + 18432 + aoff + kb);
            ldsm4(al[1], qbase + 18432 + aoff + 16 * 144 + kb);
#pragma unroll
            for (int p = 0; p < 2; p++) {
                ldsm4(bh4[p], bbase + boff + p * 16 * 144 + kb);
                ldsm4(bl4[p], bbase + 9216 + boff + p * 16 * 144 + kb);
            }
#pragma unroll
            for (int mt = 0; mt < 2; mt++)
#pragma unroll
                for (int nt = 0; nt < 4; nt++) {
                    const uint32_t* bhp = &bh4[nt >> 1][(nt & 1) * 2];
                    const uint32_t* blp = &bl4[nt >> 1][(nt & 1) * 2];
                    mma16(c[mt][nt], ah[mt], bhp);
                    mma16(c[mt][nt], ah[mt], blp);
                    mma16(c[mt][nt], al[mt], bhp);
                }
        }

#pragma unroll
        for (int mt = 0; mt < 2; mt++)
#pragma unroll
            for (int hf = 0; hf < 2; hf++) {
                float mx = -FLT_MAX, sm = 0.f;
#pragma unroll
                for (int nt = 0; nt < 4; nt++) {
                    float v0 = c[mt][nt][hf * 2], v1 = c[mt][nt][hf * 2 + 1];
                    mx = fmaxf(mx, fmaxf(v0, v1));
                    sm += v0 + v1;
                }
                mx = fmaxf(mx, __shfl_xor_sync(0xffffffffu, mx, 1));
                sm += __shfl_xor_sync(0xffffffffu, sm, 1);
                mx = fmaxf(mx, __shfl_xor_sync(0xffffffffu, mx, 2));
                sm += __shfl_xor_sync(0xffffffffu, sm, 2);
                rmax[mt][hf] = fmaxf(rmax[mt][hf], mx);
                rsum[mt][hf] += sm;
            }
        __syncthreads();
    }

    float* red = (float*)(smem_u + 23040);
    if ((lane & 3) == 0) {
#pragma unroll
        for (int mt = 0; mt < 2; mt++)
#pragma unroll
            for (int hf = 0; hf < 2; hf++) {
                int row = wr * 32 + mt * 16 + (lane >> 2) + hf * 8;
                red[(wc * 128 + row) * 2 + 0] = rmax[mt][hf];
                red[(wc * 128 + row) * 2 + 1] = rsum[mt][hf];
            }
    }
    __syncthreads();
    if (tid < 128) {
        float m0v = red[tid * 2], s0v = red[tid * 2 + 1];
        float m1v = red[(128 + tid) * 2], s1v = red[(128 + tid) * 2 + 1];
        Mout[(size_t)bh * Lc + m0 + tid] =
            fmaxf(m0v, m1v) - (s0v + s1v) * (1.f / (float)Lc);
    }
}

// ---------------- transpose + bf16 split weights ----------------------------
__global__ void wsplit_kernel(const float* __restrict__ W, bf16* __restrict__ Wh,
                              bf16* __restrict__ Wl, int Kd, int Nd)
{
    __shared__ float t[32][33];
    int x = threadIdx.x, y = threadIdx.y;
    int n0 = blockIdx.x * 32, k0 = blockIdx.y * 32;
#pragma unroll
    for (int i = 0; i < 32; i += 8)
        t[y + i][x] = W[(size_t)(k0 + y + i) * Nd + n0 + x];
    __syncthreads();
#pragma unroll
    for (int i = 0; i < 32; i += 8) {
        float v = t[x][y + i];
        bf16 h, l;
        bsplit(v, h, l);
        size_t o = (size_t)(n0 + y + i) * Kd + k0 + x;
        Wh[o] = h;
        Wl[o] = l;
    }
}

// ---------------- elementwise fp32 -> bf16 hi/lo ----------------------------
__global__ void xsplit_kernel(const float* __restrict__ src, bf16* __restrict__ hi,
                              bf16* __restrict__ lo)
{
    int i = blockIdx.x * 256 + threadIdx.x;
    float4 v = ((const float4*)src)[i];
    bf16 h0, l0, h1, l1, h2, l2, h3, l3;
    bsplit(v.x, h0, l0); bsplit(v.y, h1, l1);
    bsplit(v.z, h2, l2); bsplit(v.w, h3, l3);
    ((bf162*)hi)[i * 2]     = bf162(h0, h1);
    ((bf162*)hi)[i * 2 + 1] = bf162(h2, h3);
    ((bf162*)lo)[i * 2]     = bf162(l0, l1);
    ((bf162*)lo)[i * 2 + 1] = bf162(l2, l3);
}

// ---------------- gather sampled keys + bf16 split, head-major --------------
__global__ void gather_split_kernel(const float* __restrict__ K, const int* __restrict__ idx,
                                    bf16* __restrict__ Ksh, bf16* __restrict__ Ksl)
{
    int j = blockIdx.x, b = blockIdx.y, t = threadIdx.x;
    int src = idx[j];
    float4 v = *(const float4*)(K + ((size_t)b * Lc + src) * Dc + t * 4);
    int h = t >> 4, e = (t & 15) * 4;
    bf16 h0, l0, h1, l1, h2, l2, h3, l3;
    bsplit(v.x, h0, l0); bsplit(v.y, h1, l1);
    bsplit(v.z, h2, l2); bsplit(v.w, h3, l3);
    size_t o = (((size_t)(b * 16 + h)) * Uc + j) * 64 + e;
    *(bf162*)(Ksh + o)     = bf162(h0, h1);
    *(bf162*)(Ksh + o + 2) = bf162(h2, h3);
    *(bf162*)(Ksl + o)     = bf162(l0, l1);
    *(bf162*)(Ksl + o + 2) = bf162(l2, l3);
}

// ---------------- top-40 smallest M (ties -> lower index) -------------------
__global__ __launch_bounds__(256) void topk_kernel(const float* __restrict__ Mv,
                                                   int* __restrict__ Mtop)
{
    __shared__ float sv[Lc];
    __shared__ float rv[256];
    __shared__ int   ri[256];
    int bh = blockIdx.x, tid = threadIdx.x;
    for (int i = tid; i < Lc; i += 256) sv[i] = Mv[(size_t)bh * Lc + i];
    __syncthreads();
    for (int it = 0; it < TOPK; it++) {
        float bv = FLT_MAX; int bi = 0x7fffffff;
        for (int i = tid; i < Lc; i += 256) {
            float v = sv[i];
            if (v < bv || (v == bv && i < bi)) { bv = v; bi = i; }
        }
        rv[tid] = bv; ri[tid] = bi;
        __syncthreads();
        for (int s = 128; s > 0; s >>= 1) {
            if (tid < s) {
                float v2 = rv[tid + s]; int i2 = ri[tid + s];
                if (v2 < rv[tid] || (v2 == rv[tid] && i2 < ri[tid])) {
                    rv[tid] = v2; ri[tid] = i2;
                }
            }
            __syncthreads();
        }
        if (tid == 0) { Mtop[bh * TOPK + it] = ri[0]; sv[ri[0]] = FLT_MAX; }
        __syncthreads();
    }
}

// ---------------- sparse attention: one block per (b,h) ---------------------
__global__ __launch_bounds__(256, 1) void sparse_attn2(
    const float* __restrict__ Q, const float* __restrict__ K, const float* __restrict__ V,
    const int* __restrict__ Mtop, float* __restrict__ outred)
{
    extern __shared__ float sm[];
    float* qs   = sm;            // [40][64]
    float* ks   = sm + 2560;     // [64][65]
    float* vs   = sm + 6720;     // [64][64]
    float* wbuf = sm + 10816;    // [warp][5][64]

    int bh = blockIdx.x;
    int b = bh >> 4, h = bh & 15;
    int tid = threadIdx.x, lane = tid & 31, warp = tid >> 5;

    for (int i = tid; i < TOPK * 64; i += 256) {
        int q = i >> 6, d = i & 63;
        int qi = Mtop[bh * TOPK + q];
        qs[i] = Q[((size_t)bh * Lc + qi) * 64 + d];
    }

    const float* kb = K + (size_t)b * Lc * Dc + h * 64;
    const float* vb = V + (size_t)b * Lc * Dc + h * 64;

    float m[5], sum[5], acc0[5], acc1[5];
#pragma unroll
    for (int q = 0; q < 5; q++) {
        m[q] = -FLT_MAX; sum[q] = 0.f; acc0[q] = 0.f; acc1[q] = 0.f;
    }
    float* wq = wbuf + warp * 320;

    for (int l0 = 0; l0 < Lc; l0 += 64) {
        __syncthreads();
        for (int i = tid; i < 64 * 64; i += 256) {
            int row = i >> 6, d = i & 63;
            ks[d * 65 + row] = kb[(size_t)(l0 + row) * Dc + d];
            vs[i] = vb[(size_t)(l0 + row) * Dc + d];
        }
        __syncthreads();

#pragma unroll
        for (int q = 0; q < 5; q++) {
            const float* qrow = qs + (warp * 5 + q) * 64;
            float s0 = 0.f, s1 = 0.f;
#pragma unroll
            for (int d = 0; d < 64; d++) {
                float qv = qrow[d];
                s0 = fmaf(qv, ks[d * 65 + lane], s0);
                s1 = fmaf(qv, ks[d * 65 + lane + 32], s1);
            }
            s0 *= 0.125f; s1 *= 0.125f;
            float cmx = fmaxf(s0, s1);
#pragma unroll
            for (int off = 16; off > 0; off >>= 1)
                cmx = fmaxf(cmx, __shfl_xor_sync(0xffffffffu, cmx, off));
            float nm = fmaxf(m[q], cmx);
            float scale = expf(m[q] - nm);
            float w0 = expf(s0 - nm), w1 = expf(s1 - nm);
            float csum = w0 + w1;
#pragma unroll
            for (int off = 16; off > 0; off >>= 1)
                csum += __shfl_xor_sync(0xffffffffu, csum, off);
            sum[q] = sum[q] * scale + csum;
            m[q] = nm;
            wq[q * 64 + lane] = w0;
            wq[q * 64 + lane + 32] = w1;
            __syncwarp();
            float a0 = acc0[q] * scale, a1 = acc1[q] * scale;
#pragma unroll
            for (int k = 0; k < 64; k++) {
                float wv = wq[q * 64 + k];
                a0 = fmaf(wv, vs[k * 64 + lane], a0);
                a1 = fmaf(wv, vs[k * 64 + lane + 32], a1);
            }
            acc0[q] = a0; acc1[q] = a1;
            __syncwarp();
        }
    }

#pragma unroll
    for (int q = 0; q < 5; q++) {
        float inv = 1.0f / sum[q];
        size_t o = ((size_t)bh * TOPK + warp * 5 + q) * 64;
        outred[o + lane] = acc0[q] * inv;
        outred[o + lane + 32] = acc1[q] * inv;
    }
}

__global__ void init_bias_kernel(const float* __restrict__ bo, float* __restrict__ AO)
{
    float4 v = *(const float4*)(bo + threadIdx.x * 4);
    *(float4*)(AO + (size_t)blockIdx.x * Dc + threadIdx.x * 4) = v;
}

__global__ __launch_bounds__(256) void sparse_proj_kernel(
    const float* __restrict__ outred, const int* __restrict__ Mtop,
    const float* __restrict__ wo, float* __restrict__ AO)
{
    int ui = blockIdx.x, bh = blockIdx.y;
    int b = bh >> 4, h = bh & 15;
    int l = Mtop[bh * TOPK + ui];
    __shared__ float r[64];
    int tid = threadIdx.x;
    if (tid < 64) r[tid] = outred[((size_t)bh * TOPK + ui) * 64 + tid];
    __syncthreads();
    float a0 = 0.f, a1 = 0.f, a2 = 0.f, a3 = 0.f;
    const float* w = wo + (size_t)h * 64 * Dc + tid;
#pragma unroll 8
    for (int e = 0; e < 64; e++) {
        float re = r[e];
        const float* wr = w + (size_t)e * Dc;
        a0 = fmaf(re, wr[0],   a0);
        a1 = fmaf(re, wr[256], a1);
        a2 = fmaf(re, wr[512], a2);
        a3 = fmaf(re, wr[768], a3);
    }
    float* dst = AO + ((size_t)b * Lc + l) * Dc + tid;
    atomicAdd(dst,       a0);
    atomicAdd(dst + 256, a1);
    atomicAdd(dst + 512, a2);
    atomicAdd(dst + 768, a3);
}

// ---------------- residual add + LayerNorm (+opt bf16 split out) ------------
__global__ __launch_bounds__(256) void add_ln_kernel(
    const float* __restrict__ X, const float* __restrict__ Y,
    const float* __restrict__ g, const float* __restrict__ be,
    float* __restrict__ out, bf16* __restrict__ oh, bf16* __restrict__ ol)
{
    int row = blockIdx.x, tid = threadIdx.x;
    __shared__ float red[256];
    float v[4];
    float s = 0.f;
#pragma unroll
    for (int c = 0; c < 4; c++) {
        size_t i = (size_t)row * Dc + tid + c * 256;
        v[c] = X[i] + Y[i];
        s += v[c];
    }
    red[tid] = s; __syncthreads();
    for (int st = 128; st > 0; st >>= 1) {
        if (tid < st) red[tid] += red[tid + st];
        __syncthreads();
    }
    float mean = red[0] * (1.f / 1024.f);
    __syncthreads();
    float s2 = 0.f;
#pragma unroll
    for (int c = 0; c < 4; c++) { float t = v[c] - mean; s2 = fmaf(t, t, s2); }
    red[tid] = s2; __syncthreads();
    for (int st = 128; st > 0; st >>= 1) {
        if (tid < st) red[tid] += red[tid + st];
        __syncthreads();
    }
    float var = red[0] * (1.f / 1024.f);
    float rstd = 1.0f / sqrtf(var + 1e-12f);
#pragma unroll
    for (int c = 0; c < 4; c++) {
        int col = tid + c * 256;
        float o = g[col] * ((v[c] - mean) * rstd) + be[col];
        out[(size_t)row * Dc + col] = o;
        if (oh) {
            bf16 h, l;
            bsplit(o, h, l);
            oh[(size_t)row * Dc + col] = h;
            ol[(size_t)row * Dc + col] = l;
        }
    }
}

// ---------------- launch ----------------------------------------------------
extern "C" void kernel_launch(void* const* d_in, const int* in_sizes, int n_in,
                              void* d_out, int out_size)
{
    const float* x   = (const float*)d_in[0];
    const float* wq  = (const float*)d_in[1];
    const float* bq  = (const float*)d_in[2];
    const float* wk  = (const float*)d_in[3];
    const float* bk  = (const float*)d_in[4];
    const float* wv  = (const float*)d_in[5];
    const float* bv  = (const float*)d_in[6];
    const float* wo  = (const float*)d_in[7];
    const float* bo  = (const float*)d_in[8];
    const float* w1  = (const float*)d_in[9];
    const float* b1  = (const float*)d_in[10];
    const float* w2  = (const float*)d_in[11];
    const float* b2  = (const float*)d_in[12];
    const float* ga1 = (const float*)d_in[13];
    const float* be1 = (const float*)d_in[14];
    const float* ga2 = (const float*)d_in[15];
    const float* be2 = (const float*)d_in[16];
    const int*   idx = (const int*)d_in[17];
    float* out = (float*)d_out;

    float *Q, *K, *V, *AO, *X1, *Y2, *Mv, *Or;
    bf16 *Xbh, *Xbl, *Qbh, *Qbl, *X1bh, *X1bl, *Y1bh, *Y1bl, *Ksbh, *Ksbl;
    bf16 *Wqh, *Wql, *Wkh, *Wkl, *Wvh, *Wvl, *W1h, *W1l, *W2h, *W2l;
    int* Mt;
    cudaGetSymbolAddress((void**)&Q,    g_Q);
    cudaGetSymbolAddress((void**)&K,    g_K);
    cudaGetSymbolAddress((void**)&V,    g_V);
    cudaGetSymbolAddress((void**)&AO,   g_AO);
    cudaGetSymbolAddress((void**)&X1,   g_X1);
    cudaGetSymbolAddress((void**)&Y2,   g_Y2);
    cudaGetSymbolAddress((void**)&Mv,   g_M);
    cudaGetSymbolAddress((void**)&Mt,   g_Mtop);
    cudaGetSymbolAddress((void**)&Or,   g_Or);
    cudaGetSymbolAddress((void**)&Xbh,  g_Xbh);
    cudaGetSymbolAddress((void**)&Xbl,  g_Xbl);
    cudaGetSymbolAddress((void**)&Qbh,  g_Qbh);
    cudaGetSymbolAddress((void**)&Qbl,  g_Qbl);
    cudaGetSymbolAddress((void**)&X1bh, g_X1bh);
    cudaGetSymbolAddress((void**)&X1bl, g_X1bl);
    cudaGetSymbolAddress((void**)&Y1bh, g_Y1bh);
    cudaGetSymbolAddress((void**)&Y1bl, g_Y1bl);
    cudaGetSymbolAddress((void**)&Ksbh, g_Ksbh);
    cudaGetSymbolAddress((void**)&Ksbl, g_Ksbl);
    cudaGetSymbolAddress((void**)&Wqh,  g_Wqh);
    cudaGetSymbolAddress((void**)&Wql,  g_Wql);
    cudaGetSymbolAddress((void**)&Wkh,  g_Wkh);
    cudaGetSymbolAddress((void**)&Wkl,  g_Wkl);
    cudaGetSymbolAddress((void**)&Wvh,  g_Wvh);
    cudaGetSymbolAddress((void**)&Wvl,  g_Wvl);
    cudaGetSymbolAddress((void**)&W1h,  g_W1h);
    cudaGetSymbolAddress((void**)&W1l,  g_W1l);
    cudaGetSymbolAddress((void**)&W2h,  g_W2h);
    cudaGetSymbolAddress((void**)&W2l,  g_W2l);

    cudaFuncSetAttribute(gemm_bf, cudaFuncAttributeMaxDynamicSharedMemorySize, 2 * GSTB);
    cudaFuncSetAttribute(qk_bf,   cudaFuncAttributeMaxDynamicSharedMemorySize, 94208);
    cudaFuncSetAttribute(sparse_attn2, cudaFuncAttributeMaxDynamicSharedMemorySize, 53504);

    dim3 t32x8(32, 8);
    wsplit_kernel<<<dim3(Dc / 32, Dc / 32), t32x8>>>(wq, Wqh, Wql, Dc, Dc);
    wsplit_kernel<<<dim3(Dc / 32, Dc / 32), t32x8>>>(wk, Wkh, Wkl, Dc, Dc);
    wsplit_kernel<<<dim3(Dc / 32, Dc / 32), t32x8>>>(wv, Wvh, Wvl, Dc, Dc);
    wsplit_kernel<<<dim3(Fc / 32, Dc / 32), t32x8>>>(w1, W1h, W1l, Dc, Fc);
    wsplit_kernel<<<dim3(Dc / 32, Fc / 32), t32x8>>>(w2, W2h, W2l, Fc, Dc);

    xsplit_kernel<<<(MR * Dc / 4) / 256, 256>>>(x, Xbh, Xbl);

    gemm_bf<<<dim3(8, 64), 256, 2 * GSTB>>>(Xbh, Xbl, Wqh, Wql, bq, Q, Qbh, Qbl, Dc, Dc, 0);
    gemm_bf<<<dim3(8, 64), 256, 2 * GSTB>>>(Xbh, Xbl, Wkh, Wkl, bk, K, (bf16*)0, (bf16*)0, Dc, Dc, 0);
    gemm_bf<<<dim3(8, 64), 256, 2 * GSTB>>>(Xbh, Xbl, Wvh, Wvl, bv, V, (bf16*)0, (bf16*)0, Dc, Dc, 0);

    gather_split_kernel<<<dim3(Uc, Bc), 256>>>(K, idx, Ksbh, Ksbl);
    qk_bf<<<dim3(Lc / 128, BHc), 256, 94208>>>(Qbh, Qbl, Ksbh, Ksbl, Mv);
    topk_kernel<<<BHc, 256>>>(Mv, Mt);

    sparse_attn2<<<BHc, 256, 53504>>>(Q, K, V, Mt, Or);

    init_bias_kernel<<<MR, 256>>>(bo, AO);
    sparse_proj_kernel<<<dim3(TOPK, BHc), 256>>>(Or, Mt, wo, AO);

    add_ln_kernel<<<MR, 256>>>(x, AO, ga1, be1, X1, X1bh, X1bl);

    gemm_bf<<<dim3(32, 64), 256, 2 * GSTB>>>(X1bh, X1bl, W1h, W1l, b1, (float*)0, Y1bh, Y1bl, Dc, Fc, 1);
    gemm_bf<<<dim3(8, 64), 256, 2 * GSTB>>>(Y1bh, Y1bl, W2h, W2l, b2, Y2, (bf16*)0, (bf16*)0, Fc, Dc, 0);

    add_ln_kernel<<<MR, 256>>>(X1, Y2, ga2, be2, out, (bf16*)0, (bf16*)0);
}

// round 13
// speedup vs baseline: 1.8584x; 1.0158x over previous
#include <cuda_runtime.h>
#include <cuda_bf16.h>
#include <math.h>
#include <float.h>
#include <stdint.h>

#define Bc 4
#define Lc 2048
#define Dc 1024
#define Fc 4096
#define BHc 64
#define Uc 2048
#define TOPK 40
#define MR 8192

typedef __nv_bfloat16 bf16;
typedef __nv_bfloat162 bf162;

// ---------------- scratch ---------------------------------------------------
__device__ float g_Q [MR * Dc];
__device__ float g_K [MR * Dc];
__device__ float g_V [MR * Dc];
__device__ float g_AO[MR * Dc];
__device__ float g_X1[MR * Dc];
__device__ float g_Y2[MR * Dc];
__device__ float g_M [BHc * Lc];
__device__ int   g_Mtop[BHc * TOPK];
__device__ float g_Or[BHc * TOPK * 64];
__device__ __align__(16) bf16 g_Xbh[MR * Dc],  g_Xbl[MR * Dc];
__device__ __align__(16) bf16 g_Qbh[MR * Dc],  g_Qbl[MR * Dc];
__device__ __align__(16) bf16 g_X1bh[MR * Dc], g_X1bl[MR * Dc];
__device__ __align__(16) bf16 g_Y1bh[MR * Fc], g_Y1bl[MR * Fc];
__device__ __align__(16) bf16 g_Ksbh[BHc * Uc * 64], g_Ksbl[BHc * Uc * 64];
__device__ __align__(16) bf16 g_Wqh[Dc * Dc], g_Wql[Dc * Dc];
__device__ __align__(16) bf16 g_Wkh[Dc * Dc], g_Wkl[Dc * Dc];
__device__ __align__(16) bf16 g_Wvh[Dc * Dc], g_Wvl[Dc * Dc];
__device__ __align__(16) bf16 g_W1h[Dc * Fc], g_W1l[Dc * Fc];
__device__ __align__(16) bf16 g_W2h[Fc * Dc], g_W2l[Fc * Dc];

// ---------------- helpers ---------------------------------------------------
__device__ __forceinline__ uint32_t s2u(const void* p) {
    uint32_t a;
    asm("{ .reg .u64 t; cvta.to.shared.u64 t, %1; cvt.u32.u64 %0, t; }" : "=r"(a) : "l"(p));
    return a;
}
__device__ __forceinline__ void cpa16(uint32_t dst, const void* src) {
    asm volatile("cp.async.ca.shared.global [%0], [%1], 16;" :: "r"(dst), "l"(src));
}
__device__ __forceinline__ void cpcommit() {
    asm volatile("cp.async.commit_group;");
}
template <int N>
__device__ __forceinline__ void cpwait() {
    asm volatile("cp.async.wait_group %0;" :: "n"(N));
}
__device__ __forceinline__ void mma16(float* d, const uint32_t* a, const uint32_t* b) {
    asm volatile(
        "mma.sync.aligned.m16n8k16.row.col.f32.bf16.bf16.f32 "
        "{%0,%1,%2,%3}, {%4,%5,%6,%7}, {%8,%9}, {%0,%1,%2,%3};"
        : "+f"(d[0]), "+f"(d[1]), "+f"(d[2]), "+f"(d[3])
        : "r"(a[0]), "r"(a[1]), "r"(a[2]), "r"(a[3]), "r"(b[0]), "r"(b[1]));
}
__device__ __forceinline__ void ldsm4(uint32_t* r, uint32_t addr) {
    asm volatile("ldmatrix.sync.aligned.m8n8.x4.shared.b16 {%0,%1,%2,%3}, [%4];"
        : "=r"(r[0]), "=r"(r[1]), "=r"(r[2]), "=r"(r[3]) : "r"(addr));
}
__device__ __forceinline__ void bsplit(float v, bf16& h, bf16& l) {
    h = __float2bfloat16_rn(v);
    l = __float2bfloat16_rn(v - __bfloat162float(h));
}

// ---------------- bf16x3 mma.sync GEMM, ldmatrix frags, occ 2 ---------------
#define GSTB 40960
__global__ __launch_bounds__(256, 2) void gemm_bf(
    const bf16* __restrict__ Ah, const bf16* __restrict__ Al,
    const bf16* __restrict__ Bh, const bf16* __restrict__ Bl,
    const float* __restrict__ bias, float* __restrict__ C,
    bf16* __restrict__ Ch, bf16* __restrict__ Cl,
    int Kd, int Nd, int relu)
{
    extern __shared__ uint32_t smem_u[];
    uint32_t sb = s2u(smem_u);
    int tid = threadIdx.x, lane = tid & 31, wid = tid >> 5;
    int m0 = blockIdx.y * 128, n0 = blockIdx.x * 128;
    int wr = wid >> 1, wc = wid & 1;
    int NC = Kd >> 5;

    const bf16* gsrc[4] = { Ah + (size_t)m0 * Kd, Al + (size_t)m0 * Kd,
                            Bh + (size_t)n0 * Kd, Bl + (size_t)n0 * Kd };

    float c[2][8][4];
#pragma unroll
    for (int i = 0; i < 2; i++)
#pragma unroll
        for (int j = 0; j < 8; j++)
#pragma unroll
            for (int r = 0; r < 4; r++) c[i][j][r] = 0.f;

    int rld = tid >> 1, sgp = tid & 1;

    uint32_t aoff = (uint32_t)(wr * 32 + (lane & 7) + ((lane >> 3) & 1) * 8) * 80
                  + ((lane >> 4) & 1) * 16;
    uint32_t boff = (uint32_t)(wc * 64 + ((lane >> 4) & 1) * 8 + (lane & 7)) * 80
                  + ((lane >> 3) & 1) * 16;

    {   // preload stage 0
        uint32_t st = sb;
#pragma unroll
        for (int a4 = 0; a4 < 4; a4++) {
            uint32_t dst = st + a4 * 10240 + rld * 80 + sgp * 32;
            const bf16* src = gsrc[a4] + (size_t)rld * Kd + sgp * 16;
            cpa16(dst, src);
            cpa16(dst + 16, src + 8);
        }
        cpcommit();
    }

    for (int ch = 0; ch < NC; ch++) {
        int s = ch & 1;
        if (ch + 1 < NC) {
            int k0 = (ch + 1) << 5;
            uint32_t st = sb + ((ch + 1) & 1) * GSTB;
#pragma unroll
            for (int a4 = 0; a4 < 4; a4++) {
                uint32_t dst = st + a4 * 10240 + rld * 80 + sgp * 32;
                const bf16* src = gsrc[a4] + (size_t)rld * Kd + k0 + sgp * 16;
                cpa16(dst, src);
                cpa16(dst + 16, src + 8);
            }
            cpcommit();
            cpwait<1>();
        } else {
            cpwait<0>();
        }
        __syncthreads();

        uint32_t sbase = sb + s * GSTB;
#pragma unroll
        for (int st2 = 0; st2 < 2; st2++) {
            uint32_t kb = st2 * 32;
            uint32_t ah[2][4], al[2][4], bh4[4][4], bl4[4][4];
            ldsm4(ah[0], sbase + aoff + kb);
            ldsm4(ah[1], sbase + aoff + 16 * 80 + kb);
            ldsm4(al[0], sbase + 10240 + aoff + kb);
            ldsm4(al[1], sbase + 10240 + aoff + 16 * 80 + kb);
#pragma unroll
            for (int p = 0; p < 4; p++) {
                ldsm4(bh4[p], sbase + 20480 + boff + p * 16 * 80 + kb);
                ldsm4(bl4[p], sbase + 30720 + boff + p * 16 * 80 + kb);
            }
#pragma unroll
            for (int mt = 0; mt < 2; mt++)
#pragma unroll
                for (int nt = 0; nt < 8; nt++) {
                    const uint32_t* bh = &bh4[nt >> 1][(nt & 1) * 2];
                    const uint32_t* bl = &bl4[nt >> 1][(nt & 1) * 2];
                    mma16(c[mt][nt], ah[mt], bh);
                    mma16(c[mt][nt], ah[mt], bl);
                    mma16(c[mt][nt], al[mt], bh);
                }
        }
        __syncthreads();
    }

#pragma unroll
    for (int mt = 0; mt < 2; mt++) {
        int row = m0 + wr * 32 + mt * 16 + (lane >> 2);
#pragma unroll
        for (int nt = 0; nt < 8; nt++) {
            int col = n0 + wc * 64 + nt * 8 + (lane & 3) * 2;
            float b0 = bias[col], b1 = bias[col + 1];
            float2 v0 = make_float2(c[mt][nt][0] + b0, c[mt][nt][1] + b1);
            float2 v1 = make_float2(c[mt][nt][2] + b0, c[mt][nt][3] + b1);
            if (relu) {
                v0.x = fmaxf(v0.x, 0.f); v0.y = fmaxf(v0.y, 0.f);
                v1.x = fmaxf(v1.x, 0.f); v1.y = fmaxf(v1.y, 0.f);
            }
            if (C) {
                *(float2*)(C + (size_t)row * Nd + col) = v0;
                *(float2*)(C + (size_t)(row + 8) * Nd + col) = v1;
            }
            if (Ch) {
                bf16 h0, l0, h1, l1;
                bsplit(v0.x, h0, l0); bsplit(v0.y, h1, l1);
                *(bf162*)(Ch + (size_t)row * Nd + col) = bf162(h0, h1);
                *(bf162*)(Cl + (size_t)row * Nd + col) = bf162(l0, l1);
                bsplit(v1.x, h0, l0); bsplit(v1.y, h1, l1);
                *(bf162*)(Ch + (size_t)(row + 8) * Nd + col) = bf162(h0, h1);
                *(bf162*)(Cl + (size_t)(row + 8) * Nd + col) = bf162(l0, l1);
            }
        }
    }
}

// ---------------- QK stats via bf16x3 + ldmatrix ----------------------------
__global__ __launch_bounds__(256, 1) void qk_bf(
    const bf16* __restrict__ Qh, const bf16* __restrict__ Ql,
    const bf16* __restrict__ Ksh, const bf16* __restrict__ Ksl,
    float* __restrict__ Mout)
{
    extern __shared__ uint32_t smem_u[];
    uint32_t sb = s2u(smem_u);
    int tid = threadIdx.x, lane = tid & 31, wid = tid >> 5;
    int m0 = blockIdx.x * 128, bh = blockIdx.y;
    int wr = wid >> 1, wc = wid & 1;

    {
        const bf16* qh = Qh + ((size_t)bh * Lc + m0) * 64;
        const bf16* ql = Ql + ((size_t)bh * Lc + m0) * 64;
#pragma unroll
        for (int i = 0; i < 4; i++) {
            int idx = tid + i * 256;
            int r = idx >> 3, c16 = idx & 7;
            float4 v = *(const float4*)(qh + (size_t)r * 64 + c16 * 8);
            *(float4*)(smem_u + r * 36 + c16 * 4) = v;
            v = *(const float4*)(ql + (size_t)r * 64 + c16 * 8);
            *(float4*)(smem_u + 4608 + r * 36 + c16 * 4) = v;
        }
    }

    const bf16* kh = Ksh + (size_t)bh * Uc * 64;
    const bf16* kl = Ksl + (size_t)bh * Uc * 64;
    int rld = tid >> 2, sgp = tid & 3;

    uint32_t aoff = (uint32_t)(wr * 32 + (lane & 7) + ((lane >> 3) & 1) * 8) * 144
                  + ((lane >> 4) & 1) * 16;
    uint32_t boff = (uint32_t)(wc * 32 + ((lane >> 4) & 1) * 8 + (lane & 7)) * 144
                  + ((lane >> 3) & 1) * 16;

#pragma unroll
    for (int pre = 0; pre < 2; pre++) {
        uint32_t st = sb + 36864 + pre * 18432;
        const bf16* s0 = kh + (size_t)(pre * 64 + rld) * 64 + sgp * 16;
        const bf16* s1 = kl + (size_t)(pre * 64 + rld) * 64 + sgp * 16;
        uint32_t d0 = st + rld * 144 + sgp * 32;
        cpa16(d0, s0); cpa16(d0 + 16, s0 + 8);
        uint32_t d1 = d0 + 9216;
        cpa16(d1, s1); cpa16(d1 + 16, s1 + 8);
        cpcommit();
    }
    __syncthreads();

    float rmax[2][2], rsum[2][2];
#pragma unroll
    for (int i = 0; i < 2; i++)
#pragma unroll
        for (int j = 0; j < 2; j++) { rmax[i][j] = -FLT_MAX; rsum[i][j] = 0.f; }

    for (int ch = 0; ch < 32; ch++) {
        int s = ch % 3;
        if (ch + 2 < 32) {
            uint32_t st = sb + 36864 + ((ch + 2) % 3) * 18432;
            const bf16* s0 = kh + (size_t)((ch + 2) * 64 + rld) * 64 + sgp * 16;
            const bf16* s1 = kl + (size_t)((ch + 2) * 64 + rld) * 64 + sgp * 16;
            uint32_t d0 = st + rld * 144 + sgp * 32;
            cpa16(d0, s0); cpa16(d0 + 16, s0 + 8);
            uint32_t d1 = d0 + 9216;
            cpa16(d1, s1); cpa16(d1 + 16, s1 + 8);
            cpcommit();
            cpwait<2>();
        } else if (ch + 2 == 32) {
            cpwait<1>();
        } else {
            cpwait<0>();
        }
        __syncthreads();

        uint32_t qbase = sb;
        uint32_t bbase = sb + 36864 + s * 18432;

        float c[2][4][4];
#pragma unroll
        for (int i = 0; i < 2; i++)
#pragma unroll
            for (int j = 0; j < 4; j++)
#pragma unroll
                for (int r = 0; r < 4; r++) c[i][j][r] = 0.f;

#pragma unroll
        for (int st = 0; st < 4; st++) {
            uint32_t kb = st * 32;
            uint32_t ah[2][4], al[2][4], bh4[2][4], bl4[2][4];
            ldsm4(ah[0], qbase + aoff + kb);
            ldsm4(ah[1], qbase + aoff + 16 * 144 + kb);
            ldsm4(al[0], qbase + 18432 + aoff + kb);
            ldsm4(al[1], qbase + 18432 + aoff + 16 * 144 + kb);
#pragma unroll
            for (int p = 0; p < 2; p++) {
                ldsm4(bh4[p], bbase + boff + p * 16 * 144 + kb);
                ldsm4(bl4[p], bbase + 9216 + boff + p * 16 * 144 + kb);
            }
#pragma unroll
            for (int mt = 0; mt < 2; mt++)
#pragma unroll
                for (int nt = 0; nt < 4; nt++) {
                    const uint32_t* bhp = &bh4[nt >> 1][(nt & 1) * 2];
                    const uint32_t* blp = &bl4[nt >> 1][(nt & 1) * 2];
                    mma16(c[mt][nt], ah[mt], bhp);
                    mma16(c[mt][nt], ah[mt], blp);
                    mma16(c[mt][nt], al[mt], bhp);
                }
        }

#pragma unroll
        for (int mt = 0; mt < 2; mt++)
#pragma unroll
            for (int hf = 0; hf < 2; hf++) {
                float mx = -FLT_MAX, sm = 0.f;
#pragma unroll
                for (int nt = 0; nt < 4; nt++) {
                    float v0 = c[mt][nt][hf * 2], v1 = c[mt][nt][hf * 2 + 1];
                    mx = fmaxf(mx, fmaxf(v0, v1));
                    sm += v0 + v1;
                }
                mx = fmaxf(mx, __shfl_xor_sync(0xffffffffu, mx, 1));
                sm += __shfl_xor_sync(0xffffffffu, sm, 1);
                mx = fmaxf(mx, __shfl_xor_sync(0xffffffffu, mx, 2));
                sm += __shfl_xor_sync(0xffffffffu, sm, 2);
                rmax[mt][hf] = fmaxf(rmax[mt][hf], mx);
                rsum[mt][hf] += sm;
            }
        __syncthreads();
    }

    float* red = (float*)(smem_u + 23040);
    if ((lane & 3) == 0) {
#pragma unroll
        for (int mt = 0; mt < 2; mt++)
#pragma unroll
            for (int hf = 0; hf < 2; hf++) {
                int row = wr * 32 + mt * 16 + (lane >> 2) + hf * 8;
                red[(wc * 128 + row) * 2 + 0] = rmax[mt][hf];
                red[(wc * 128 + row) * 2 + 1] = rsum[mt][hf];
            }
    }
    __syncthreads();
    if (tid < 128) {
        float m0v = red[tid * 2], s0v = red[tid * 2 + 1];
        float m1v = red[(128 + tid) * 2], s1v = red[(128 + tid) * 2 + 1];
        Mout[(size_t)bh * Lc + m0 + tid] =
            fmaxf(m0v, m1v) - (s0v + s1v) * (1.f / (float)Lc);
    }
}

// ---------------- merged transpose + bf16 split for all 5 weights -----------
// flat grid: [0,1024) wq | [1024,2048) wk | [2048,3072) wv |
// [3072,7168) w1 (128x32) | [7168,11264) w2 (32x128)
__global__ void wsplit_all(
    const float* __restrict__ wq, const float* __restrict__ wk,
    const float* __restrict__ wv, const float* __restrict__ w1,
    const float* __restrict__ w2,
    bf16* __restrict__ Wqh, bf16* __restrict__ Wql,
    bf16* __restrict__ Wkh, bf16* __restrict__ Wkl,
    bf16* __restrict__ Wvh, bf16* __restrict__ Wvl,
    bf16* __restrict__ W1h, bf16* __restrict__ W1l,
    bf16* __restrict__ W2h, bf16* __restrict__ W2l)
{
    int bid = blockIdx.x;
    const float* W; bf16 *Wh, *Wl; int Kd, Nd, bx, by;
    if (bid < 3072) {
        int w = bid >> 10, local = bid & 1023;
        W = (w == 0) ? wq : (w == 1) ? wk : wv;
        Wh = (w == 0) ? Wqh : (w == 1) ? Wkh : Wvh;
        Wl = (w == 0) ? Wql : (w == 1) ? Wkl : Wvl;
        Kd = Dc; Nd = Dc; bx = local & 31; by = local >> 5;
    } else if (bid < 7168) {
        int local = bid - 3072;
        W = w1; Wh = W1h; Wl = W1l;
        Kd = Dc; Nd = Fc; bx = local & 127; by = local >> 7;
    } else {
        int local = bid - 7168;
        W = w2; Wh = W2h; Wl = W2l;
        Kd = Fc; Nd = Dc; bx = local & 31; by = local >> 5;
    }
    __shared__ float t[32][33];
    int x = threadIdx.x, y = threadIdx.y;
    int n0 = bx * 32, k0 = by * 32;
#pragma unroll
    for (int i = 0; i < 32; i += 8)
        t[y + i][x] = W[(size_t)(k0 + y + i) * Nd + n0 + x];
    __syncthreads();
#pragma unroll
    for (int i = 0; i < 32; i += 8) {
        float v = t[x][y + i];
        bf16 h, l;
        bsplit(v, h, l);
        size_t o = (size_t)(n0 + y + i) * Kd + k0 + x;
        Wh[o] = h;
        Wl[o] = l;
    }
}

// ---------------- elementwise fp32 -> bf16 hi/lo ----------------------------
__global__ void xsplit_kernel(const float* __restrict__ src, bf16* __restrict__ hi,
                              bf16* __restrict__ lo)
{
    int i = blockIdx.x * 256 + threadIdx.x;
    float4 v = ((const float4*)src)[i];
    bf16 h0, l0, h1, l1, h2, l2, h3, l3;
    bsplit(v.x, h0, l0); bsplit(v.y, h1, l1);
    bsplit(v.z, h2, l2); bsplit(v.w, h3, l3);
    ((bf162*)hi)[i * 2]     = bf162(h0, h1);
    ((bf162*)hi)[i * 2 + 1] = bf162(h2, h3);
    ((bf162*)lo)[i * 2]     = bf162(l0, l1);
    ((bf162*)lo)[i * 2 + 1] = bf162(l2, l3);
}

// ---------------- gather sampled keys + bf16 split --------------------------
__global__ void gather_split_kernel(const float* __restrict__ K, const int* __restrict__ idx,
                                    bf16* __restrict__ Ksh, bf16* __restrict__ Ksl)
{
    int j = blockIdx.x, b = blockIdx.y, t = threadIdx.x;
    int src = idx[j];
    float4 v = *(const float4*)(K + ((size_t)b * Lc + src) * Dc + t * 4);
    int h = t >> 4, e = (t & 15) * 4;
    bf16 h0, l0, h1, l1, h2, l2, h3, l3;
    bsplit(v.x, h0, l0); bsplit(v.y, h1, l1);
    bsplit(v.z, h2, l2); bsplit(v.w, h3, l3);
    size_t o = (((size_t)(b * 16 + h)) * Uc + j) * 64 + e;
    *(bf162*)(Ksh + o)     = bf162(h0, h1);
    *(bf162*)(Ksh + o + 2) = bf162(h2, h3);
    *(bf162*)(Ksl + o)     = bf162(l0, l1);
    *(bf162*)(Ksl + o + 2) = bf162(l2, l3);
}

// ---------------- top-40 smallest M -----------------------------------------
__global__ __launch_bounds__(256) void topk_kernel(const float* __restrict__ Mv,
                                                   int* __restrict__ Mtop)
{
    __shared__ float sv[Lc];
    __shared__ float rv[256];
    __shared__ int   ri[256];
    int bh = blockIdx.x, tid = threadIdx.x;
    for (int i = tid; i < Lc; i += 256) sv[i] = Mv[(size_t)bh * Lc + i];
    __syncthreads();
    for (int it = 0; it < TOPK; it++) {
        float bv = FLT_MAX; int bi = 0x7fffffff;
        for (int i = tid; i < Lc; i += 256) {
            float v = sv[i];
            if (v < bv || (v == bv && i < bi)) { bv = v; bi = i; }
        }
        rv[tid] = bv; ri[tid] = bi;
        __syncthreads();
        for (int s = 128; s > 0; s >>= 1) {
            if (tid < s) {
                float v2 = rv[tid + s]; int i2 = ri[tid + s];
                if (v2 < rv[tid] || (v2 == rv[tid] && i2 < ri[tid])) {
                    rv[tid] = v2; ri[tid] = i2;
                }
            }
            __syncthreads();
        }
        if (tid == 0) { Mtop[bh * TOPK + it] = ri[0]; sv[ri[0]] = FLT_MAX; }
        __syncthreads();
    }
}

// ---------------- sparse attention: 2 blocks per (b,h), 20 queries each -----
// smem floats: qs[20][64] @0, ks[64][65] @1280, vs[64][64] @5440, wbuf[4][5][64] @9536
// total 10816 floats = 43264 B
__global__ __launch_bounds__(128, 1) void sparse_attn2(
    const float* __restrict__ Q, const float* __restrict__ K, const float* __restrict__ V,
    const int* __restrict__ Mtop, float* __restrict__ outred)
{
    extern __shared__ float sm[];
    float* qs   = sm;
    float* ks   = sm + 1280;
    float* vs   = sm + 5440;
    float* wbuf = sm + 9536;

    int half = blockIdx.x, bh = blockIdx.y;
    int b = bh >> 4, h = bh & 15;
    int tid = threadIdx.x, lane = tid & 31, warp = tid >> 5;
    int qb = half * 20;

    for (int i = tid; i < 20 * 64; i += 128) {
        int q = i >> 6, d = i & 63;
        int qi = Mtop[bh * TOPK + qb + q];
        qs[i] = Q[((size_t)bh * Lc + qi) * 64 + d];
    }

    const float* kb = K + (size_t)b * Lc * Dc + h * 64;
    const float* vb = V + (size_t)b * Lc * Dc + h * 64;

    float m[5], sum[5], acc0[5], acc1[5];
#pragma unroll
    for (int q = 0; q < 5; q++) {
        m[q] = -FLT_MAX; sum[q] = 0.f; acc0[q] = 0.f; acc1[q] = 0.f;
    }
    float* wq = wbuf + warp * 320;

    for (int l0 = 0; l0 < Lc; l0 += 64) {
        __syncthreads();
        for (int i = tid; i < 64 * 64; i += 128) {
            int row = i >> 6, d = i & 63;
            ks[d * 65 + row] = kb[(size_t)(l0 + row) * Dc + d];
            vs[i] = vb[(size_t)(l0 + row) * Dc + d];
        }
        __syncthreads();

#pragma unroll
        for (int q = 0; q < 5; q++) {
            const float* qrow = qs + (warp * 5 + q) * 64;
            float s0 = 0.f, s1 = 0.f;
#pragma unroll
            for (int d = 0; d < 64; d++) {
                float qv = qrow[d];
                s0 = fmaf(qv, ks[d * 65 + lane], s0);
                s1 = fmaf(qv, ks[d * 65 + lane + 32], s1);
            }
            s0 *= 0.125f; s1 *= 0.125f;
            float cmx = fmaxf(s0, s1);
#pragma unroll
            for (int off = 16; off > 0; off >>= 1)
                cmx = fmaxf(cmx, __shfl_xor_sync(0xffffffffu, cmx, off));
            float nm = fmaxf(m[q], cmx);
            float scale = expf(m[q] - nm);
            float w0 = expf(s0 - nm), w1 = expf(s1 - nm);
            float csum = w0 + w1;
#pragma unroll
            for (int off = 16; off > 0; off >>= 1)
                csum += __shfl_xor_sync(0xffffffffu, csum, off);
            sum[q] = sum[q] * scale + csum;
            m[q] = nm;
            wq[q * 64 + lane] = w0;
            wq[q * 64 + lane + 32] = w1;
            __syncwarp();
            float a0 = acc0[q] * scale, a1 = acc1[q] * scale;
#pragma unroll
            for (int k = 0; k < 64; k++) {
                float wv = wq[q * 64 + k];
                a0 = fmaf(wv, vs[k * 64 + lane], a0);
                a1 = fmaf(wv, vs[k * 64 + lane + 32], a1);
            }
            acc0[q] = a0; acc1[q] = a1;
            __syncwarp();
        }
    }

#pragma unroll
    for (int q = 0; q < 5; q++) {
        float inv = 1.0f / sum[q];
        size_t o = ((size_t)bh * TOPK + qb + warp * 5 + q) * 64;
        outred[o + lane] = acc0[q] * inv;
        outred[o + lane + 32] = acc1[q] * inv;
    }
}

__global__ void init_bias_kernel(const float* __restrict__ bo, float* __restrict__ AO)
{
    float4 v = *(const float4*)(bo + threadIdx.x * 4);
    *(float4*)(AO + (size_t)blockIdx.x * Dc + threadIdx.x * 4) = v;
}

__global__ __launch_bounds__(256) void sparse_proj_kernel(
    const float* __restrict__ outred, const int* __restrict__ Mtop,
    const float* __restrict__ wo, float* __restrict__ AO)
{
    int ui = blockIdx.x, bh = blockIdx.y;
    int b = bh >> 4, h = bh & 15;
    int l = Mtop[bh * TOPK + ui];
    __shared__ float r[64];
    int tid = threadIdx.x;
    if (tid < 64) r[tid] = outred[((size_t)bh * TOPK + ui) * 64 + tid];
    __syncthreads();
    float a0 = 0.f, a1 = 0.f, a2 = 0.f, a3 = 0.f;
    const float* w = wo + (size_t)h * 64 * Dc + tid;
#pragma unroll 8
    for (int e = 0; e < 64; e++) {
        float re = r[e];
        const float* wr = w + (size_t)e * Dc;
        a0 = fmaf(re, wr[0],   a0);
        a1 = fmaf(re, wr[256], a1);
        a2 = fmaf(re, wr[512], a2);
        a3 = fmaf(re, wr[768], a3);
    }
    float* dst = AO + ((size_t)b * Lc + l) * Dc + tid;
    atomicAdd(dst,       a0);
    atomicAdd(dst + 256, a1);
    atomicAdd(dst + 512, a2);
    atomicAdd(dst + 768, a3);
}

// ---------------- residual add + LayerNorm (+opt bf16 split out) ------------
__global__ __launch_bounds__(256) void add_ln_kernel(
    const float* __restrict__ X, const float* __restrict__ Y,
    const float* __restrict__ g, const float* __restrict__ be,
    float* __restrict__ out, bf16* __restrict__ oh, bf16* __restrict__ ol)
{
    int row = blockIdx.x, tid = threadIdx.x;
    __shared__ float red[256];
    float v[4];
    float s = 0.f;
#pragma unroll
    for (int c = 0; c < 4; c++) {
        size_t i = (size_t)row * Dc + tid + c * 256;
        v[c] = X[i] + Y[i];
        s += v[c];
    }
    red[tid] = s; __syncthreads();
    for (int st = 128; st > 0; st >>= 1) {
        if (tid < st) red[tid] += red[tid + st];
        __syncthreads();
    }
    float mean = red[0] * (1.f / 1024.f);
    __syncthreads();
    float s2 = 0.f;
#pragma unroll
    for (int c = 0; c < 4; c++) { float t = v[c] - mean; s2 = fmaf(t, t, s2); }
    red[tid] = s2; __syncthreads();
    for (int st = 128; st > 0; st >>= 1) {
        if (tid < st) red[tid] += red[tid + st];
        __syncthreads();
    }
    float var = red[0] * (1.f / 1024.f);
    float rstd = 1.0f / sqrtf(var + 1e-12f);
#pragma unroll
    for (int c = 0; c < 4; c++) {
        int col = tid + c * 256;
        float o = g[col] * ((v[c] - mean) * rstd) + be[col];
        out[(size_t)row * Dc + col] = o;
        if (oh) {
            bf16 h, l;
            bsplit(o, h, l);
            oh[(size_t)row * Dc + col] = h;
            ol[(size_t)row * Dc + col] = l;
        }
    }
}

// ---------------- launch ----------------------------------------------------
extern "C" void kernel_launch(void* const* d_in, const int* in_sizes, int n_in,
                              void* d_out, int out_size)
{
    const float* x   = (const float*)d_in[0];
    const float* wq  = (const float*)d_in[1];
    const float* bq  = (const float*)d_in[2];
    const float* wk  = (const float*)d_in[3];
    const float* bk  = (const float*)d_in[4];
    const float* wv  = (const float*)d_in[5];
    const float* bv  = (const float*)d_in[6];
    const float* wo  = (const float*)d_in[7];
    const float* bo  = (const float*)d_in[8];
    const float* w1  = (const float*)d_in[9];
    const float* b1  = (const float*)d_in[10];
    const float* w2  = (const float*)d_in[11];
    const float* b2  = (const float*)d_in[12];
    const float* ga1 = (const float*)d_in[13];
    const float* be1 = (const float*)d_in[14];
    const float* ga2 = (const float*)d_in[15];
    const float* be2 = (const float*)d_in[16];
    const int*   idx = (const int*)d_in[17];
    float* out = (float*)d_out;

    float *Q, *K, *V, *AO, *X1, *Y2, *Mv, *Or;
    bf16 *Xbh, *Xbl, *Qbh, *Qbl, *X1bh, *X1bl, *Y1bh, *Y1bl, *Ksbh, *Ksbl;
    bf16 *Wqh, *Wql, *Wkh, *Wkl, *Wvh, *Wvl, *W1h, *W1l, *W2h, *W2l;
    int* Mt;
    cudaGetSymbolAddress((void**)&Q,    g_Q);
    cudaGetSymbolAddress((void**)&K,    g_K);
    cudaGetSymbolAddress((void**)&V,    g_V);
    cudaGetSymbolAddress((void**)&AO,   g_AO);
    cudaGetSymbolAddress((void**)&X1,   g_X1);
    cudaGetSymbolAddress((void**)&Y2,   g_Y2);
    cudaGetSymbolAddress((void**)&Mv,   g_M);
    cudaGetSymbolAddress((void**)&Mt,   g_Mtop);
    cudaGetSymbolAddress((void**)&Or,   g_Or);
    cudaGetSymbolAddress((void**)&Xbh,  g_Xbh);
    cudaGetSymbolAddress((void**)&Xbl,  g_Xbl);
    cudaGetSymbolAddress((void**)&Qbh,  g_Qbh);
    cudaGetSymbolAddress((void**)&Qbl,  g_Qbl);
    cudaGetSymbolAddress((void**)&X1bh, g_X1bh);
    cudaGetSymbolAddress((void**)&X1bl, g_X1bl);
    cudaGetSymbolAddress((void**)&Y1bh, g_Y1bh);
    cudaGetSymbolAddress((void**)&Y1bl, g_Y1bl);
    cudaGetSymbolAddress((void**)&Ksbh, g_Ksbh);
    cudaGetSymbolAddress((void**)&Ksbl, g_Ksbl);
    cudaGetSymbolAddress((void**)&Wqh,  g_Wqh);
    cudaGetSymbolAddress((void**)&Wql,  g_Wql);
    cudaGetSymbolAddress((void**)&Wkh,  g_Wkh);
    cudaGetSymbolAddress((void**)&Wkl,  g_Wkl);
    cudaGetSymbolAddress((void**)&Wvh,  g_Wvh);
    cudaGetSymbolAddress((void**)&Wvl,  g_Wvl);
    cudaGetSymbolAddress((void**)&W1h,  g_W1h);
    cudaGetSymbolAddress((void**)&W1l,  g_W1l);
    cudaGetSymbolAddress((void**)&W2h,  g_W2h);
    cudaGetSymbolAddress((void**)&W2l,  g_W2l);

    static cudaStream_t s_aux = 0;
    static cudaEvent_t evA = 0, evV = 0;
    if (!s_aux) {
        cudaStreamCreateWithFlags(&s_aux, cudaStreamNonBlocking);
        cudaEventCreateWithFlags(&evA, cudaEventDisableTiming);
        cudaEventCreateWithFlags(&evV, cudaEventDisableTiming);
    }

    cudaFuncSetAttribute(gemm_bf, cudaFuncAttributeMaxDynamicSharedMemorySize, 2 * GSTB);
    cudaFuncSetAttribute(qk_bf,   cudaFuncAttributeMaxDynamicSharedMemorySize, 94208);
    cudaFuncSetAttribute(sparse_attn2, cudaFuncAttributeMaxDynamicSharedMemorySize, 43264);

    dim3 t32x8(32, 8);
    wsplit_all<<<11264, t32x8>>>(wq, wk, wv, w1, w2,
                                 Wqh, Wql, Wkh, Wkl, Wvh, Wvl, W1h, W1l, W2h, W2l);
    xsplit_kernel<<<(MR * Dc / 4) / 256, 256>>>(x, Xbh, Xbl);

    // fork: aux stream does AO init + V GEMM while main does Q,K,gather,qk,topk
    cudaEventRecord(evA, 0);
    cudaStreamWaitEvent(s_aux, evA, 0);
    init_bias_kernel<<<MR, 256, 0, s_aux>>>(bo, AO);
    gemm_bf<<<dim3(8, 64), 256, 2 * GSTB, s_aux>>>(Xbh, Xbl, Wvh, Wvl, bv, V,
                                                   (bf16*)0, (bf16*)0, Dc, Dc, 0);
    cudaEventRecord(evV, s_aux);

    gemm_bf<<<dim3(8, 64), 256, 2 * GSTB>>>(Xbh, Xbl, Wqh, Wql, bq, Q, Qbh, Qbl, Dc, Dc, 0);
    gemm_bf<<<dim3(8, 64), 256, 2 * GSTB>>>(Xbh, Xbl, Wkh, Wkl, bk, K, (bf16*)0, (bf16*)0, Dc, Dc, 0);
    gather_split_kernel<<<dim3(Uc, Bc), 256>>>(K, idx, Ksbh, Ksbl);
    qk_bf<<<dim3(Lc / 128, BHc), 256, 94208>>>(Qbh, Qbl, Ksbh, Ksbl, Mv);
    topk_kernel<<<BHc, 256>>>(Mv, Mt);

    // join: need V + AO before attn/proj
    cudaStreamWaitEvent(0, evV, 0);
    sparse_attn2<<<dim3(2, BHc), 128, 43264>>>(Q, K, V, Mt, Or);
    sparse_proj_kernel<<<dim3(TOPK, BHc), 256>>>(Or, Mt, wo, AO);

    add_ln_kernel<<<MR, 256>>>(x, AO, ga1, be1, X1, X1bh, X1bl);

    gemm_bf<<<dim3(32, 64), 256, 2 * GSTB>>>(X1bh, X1bl, W1h, W1l, b1, (float*)0, Y1bh, Y1bl, Dc, Fc, 1);
    gemm_bf<<<dim3(8, 64), 256, 2 * GSTB>>>(Y1bh, Y1bl, W2h, W2l, b2, Y2, (bf16*)0, (bf16*)0, Fc, Dc, 0);

    add_ln_kernel<<<MR, 256>>>(X1, Y2, ga2, be2, out, (bf16*)0, (bf16*)0);
}

// round 14
// speedup vs baseline: 1.8660x; 1.0041x over previous
#include <cuda_runtime.h>
#include <cuda_bf16.h>
#include <math.h>
#include <float.h>
#include <stdint.h>

#define Bc 4
#define Lc 2048
#define Dc 1024
#define Fc 4096
#define BHc 64
#define Uc 2048
#define TOPK 40
#define MR 8192

typedef __nv_bfloat16 bf16;
typedef __nv_bfloat162 bf162;

// ---------------- scratch ---------------------------------------------------
__device__ float g_Q [MR * Dc];
__device__ float g_K [MR * Dc];
__device__ float g_V [MR * Dc];
__device__ float g_AO[MR * Dc];
__device__ float g_X1[MR * Dc];
__device__ float g_Y2[MR * Dc];
__device__ float g_M [BHc * Lc];
__device__ int   g_Mtop[BHc * TOPK];
__device__ float g_Or[BHc * TOPK * 64];
__device__ float g_bqkv[3 * Dc];
__device__ __align__(16) bf16 g_Xbh[MR * Dc],  g_Xbl[MR * Dc];
__device__ __align__(16) bf16 g_Qbh[MR * Dc],  g_Qbl[MR * Dc];
__device__ __align__(16) bf16 g_X1bh[MR * Dc], g_X1bl[MR * Dc];
__device__ __align__(16) bf16 g_Y1bh[MR * Fc], g_Y1bl[MR * Fc];
__device__ __align__(16) bf16 g_Ksbh[BHc * Uc * 64], g_Ksbl[BHc * Uc * 64];
__device__ __align__(16) bf16 g_Wqkvh[3 * Dc * Dc], g_Wqkvl[3 * Dc * Dc];
__device__ __align__(16) bf16 g_W1h[Dc * Fc], g_W1l[Dc * Fc];
__device__ __align__(16) bf16 g_W2h[Fc * Dc], g_W2l[Fc * Dc];

// ---------------- helpers ---------------------------------------------------
__device__ __forceinline__ uint32_t s2u(const void* p) {
    uint32_t a;
    asm("{ .reg .u64 t; cvta.to.shared.u64 t, %1; cvt.u32.u64 %0, t; }" : "=r"(a) : "l"(p));
    return a;
}
__device__ __forceinline__ void cpa16(uint32_t dst, const void* src) {
    asm volatile("cp.async.ca.shared.global [%0], [%1], 16;" :: "r"(dst), "l"(src));
}
__device__ __forceinline__ void cpcommit() {
    asm volatile("cp.async.commit_group;");
}
template <int N>
__device__ __forceinline__ void cpwait() {
    asm volatile("cp.async.wait_group %0;" :: "n"(N));
}
__device__ __forceinline__ void mma16(float* d, const uint32_t* a, const uint32_t* b) {
    asm volatile(
        "mma.sync.aligned.m16n8k16.row.col.f32.bf16.bf16.f32 "
        "{%0,%1,%2,%3}, {%4,%5,%6,%7}, {%8,%9}, {%0,%1,%2,%3};"
        : "+f"(d[0]), "+f"(d[1]), "+f"(d[2]), "+f"(d[3])
        : "r"(a[0]), "r"(a[1]), "r"(a[2]), "r"(a[3]), "r"(b[0]), "r"(b[1]));
}
__device__ __forceinline__ void ldsm4(uint32_t* r, uint32_t addr) {
    asm volatile("ldmatrix.sync.aligned.m8n8.x4.shared.b16 {%0,%1,%2,%3}, [%4];"
        : "=r"(r[0]), "=r"(r[1]), "=r"(r[2]), "=r"(r[3]) : "r"(addr));
}
__device__ __forceinline__ void bsplit(float v, bf16& h, bf16& l) {
    h = __float2bfloat16_rn(v);
    l = __float2bfloat16_rn(v - __bfloat162float(h));
}

// ---------------- shared GEMM mainloop (macro-free inline) -------------------
#define GSTB 40960

struct GemmAcc { float c[2][8][4]; };

__device__ __forceinline__ void gemm_mainloop(
    uint32_t sb, const uint32_t* smem_u,
    const bf16* Ah, const bf16* Al, const bf16* Bh, const bf16* Bl,
    int Kd, int m0, int n0, int tid, int lane, int wr, int wc, GemmAcc& A)
{
#pragma unroll
    for (int i = 0; i < 2; i++)
#pragma unroll
        for (int j = 0; j < 8; j++)
#pragma unroll
            for (int r = 0; r < 4; r++) A.c[i][j][r] = 0.f;

    const bf16* gsrc[4] = { Ah + (size_t)m0 * Kd, Al + (size_t)m0 * Kd,
                            Bh + (size_t)n0 * Kd, Bl + (size_t)n0 * Kd };
    int rld = tid >> 1, sgp = tid & 1;
    int NC = Kd >> 5;

    uint32_t aoff = (uint32_t)(wr * 32 + (lane & 7) + ((lane >> 3) & 1) * 8) * 80
                  + ((lane >> 4) & 1) * 16;
    uint32_t boff = (uint32_t)(wc * 64 + ((lane >> 4) & 1) * 8 + (lane & 7)) * 80
                  + ((lane >> 3) & 1) * 16;

    {
        uint32_t st = sb;
#pragma unroll
        for (int a4 = 0; a4 < 4; a4++) {
            uint32_t dst = st + a4 * 10240 + rld * 80 + sgp * 32;
            const bf16* src = gsrc[a4] + (size_t)rld * Kd + sgp * 16;
            cpa16(dst, src);
            cpa16(dst + 16, src + 8);
        }
        cpcommit();
    }

    for (int ch = 0; ch < NC; ch++) {
        int s = ch & 1;
        if (ch + 1 < NC) {
            int k0 = (ch + 1) << 5;
            uint32_t st = sb + ((ch + 1) & 1) * GSTB;
#pragma unroll
            for (int a4 = 0; a4 < 4; a4++) {
                uint32_t dst = st + a4 * 10240 + rld * 80 + sgp * 32;
                const bf16* src = gsrc[a4] + (size_t)rld * Kd + k0 + sgp * 16;
                cpa16(dst, src);
                cpa16(dst + 16, src + 8);
            }
            cpcommit();
            cpwait<1>();
        } else {
            cpwait<0>();
        }
        __syncthreads();

        uint32_t sbase = sb + s * GSTB;
#pragma unroll
        for (int st2 = 0; st2 < 2; st2++) {
            uint32_t kb = st2 * 32;
            uint32_t ah[2][4], al[2][4], bh4[4][4], bl4[4][4];
            ldsm4(ah[0], sbase + aoff + kb);
            ldsm4(ah[1], sbase + aoff + 16 * 80 + kb);
            ldsm4(al[0], sbase + 10240 + aoff + kb);
            ldsm4(al[1], sbase + 10240 + aoff + 16 * 80 + kb);
#pragma unroll
            for (int p = 0; p < 4; p++) {
                ldsm4(bh4[p], sbase + 20480 + boff + p * 16 * 80 + kb);
                ldsm4(bl4[p], sbase + 30720 + boff + p * 16 * 80 + kb);
            }
#pragma unroll
            for (int mt = 0; mt < 2; mt++)
#pragma unroll
                for (int nt = 0; nt < 8; nt++) {
                    const uint32_t* bh = &bh4[nt >> 1][(nt & 1) * 2];
                    const uint32_t* bl = &bl4[nt >> 1][(nt & 1) * 2];
                    mma16(A.c[mt][nt], ah[mt], bh);
                    mma16(A.c[mt][nt], ah[mt], bl);
                    mma16(A.c[mt][nt], al[mt], bh);
                }
        }
        __syncthreads();
    }
}

// ---------------- fused QKV GEMM: C = X @ [Wq|Wk|Wv]^T + bias ----------------
__global__ __launch_bounds__(256, 2) void gemm_qkv(
    const bf16* __restrict__ Ah, const bf16* __restrict__ Al,
    const bf16* __restrict__ Bh, const bf16* __restrict__ Bl,
    const float* __restrict__ bias,
    float* __restrict__ CQ, float* __restrict__ CK, float* __restrict__ CV,
    bf16* __restrict__ Qh, bf16* __restrict__ Ql)
{
    extern __shared__ uint32_t smem_u[];
    uint32_t sb = s2u(smem_u);
    int tid = threadIdx.x, lane = tid & 31, wid = tid >> 5;
    int m0 = blockIdx.y * 128, n0 = blockIdx.x * 128;
    int wr = wid >> 1, wc = wid & 1;

    GemmAcc A;
    gemm_mainloop(sb, smem_u, Ah, Al, Bh, Bl, Dc, m0, n0, tid, lane, wr, wc, A);

    int region = n0 >> 10;
    float* Cout = (region == 0) ? CQ : (region == 1) ? CK : CV;
    int nl0 = n0 & 1023;

#pragma unroll
    for (int mt = 0; mt < 2; mt++) {
        int row = m0 + wr * 32 + mt * 16 + (lane >> 2);
#pragma unroll
        for (int nt = 0; nt < 8; nt++) {
            int colg = n0 + wc * 64 + nt * 8 + (lane & 3) * 2;
            int col = nl0 + wc * 64 + nt * 8 + (lane & 3) * 2;
            float b0 = bias[colg], b1 = bias[colg + 1];
            float2 v0 = make_float2(A.c[mt][nt][0] + b0, A.c[mt][nt][1] + b1);
            float2 v1 = make_float2(A.c[mt][nt][2] + b0, A.c[mt][nt][3] + b1);
            *(float2*)(Cout + (size_t)row * Dc + col) = v0;
            *(float2*)(Cout + (size_t)(row + 8) * Dc + col) = v1;
            if (region == 0) {
                bf16 h0, l0, h1, l1;
                bsplit(v0.x, h0, l0); bsplit(v0.y, h1, l1);
                *(bf162*)(Qh + (size_t)row * Dc + col) = bf162(h0, h1);
                *(bf162*)(Ql + (size_t)row * Dc + col) = bf162(l0, l1);
                bsplit(v1.x, h0, l0); bsplit(v1.y, h1, l1);
                *(bf162*)(Qh + (size_t)(row + 8) * Dc + col) = bf162(h0, h1);
                *(bf162*)(Ql + (size_t)(row + 8) * Dc + col) = bf162(l0, l1);
            }
        }
    }
}

// ---------------- generic GEMM (FFN) -----------------------------------------
__global__ __launch_bounds__(256, 2) void gemm_bf(
    const bf16* __restrict__ Ah, const bf16* __restrict__ Al,
    const bf16* __restrict__ Bh, const bf16* __restrict__ Bl,
    const float* __restrict__ bias, float* __restrict__ C,
    bf16* __restrict__ Ch, bf16* __restrict__ Cl,
    int Kd, int Nd, int relu)
{
    extern __shared__ uint32_t smem_u[];
    uint32_t sb = s2u(smem_u);
    int tid = threadIdx.x, lane = tid & 31, wid = tid >> 5;
    int m0 = blockIdx.y * 128, n0 = blockIdx.x * 128;
    int wr = wid >> 1, wc = wid & 1;

    GemmAcc A;
    gemm_mainloop(sb, smem_u, Ah, Al, Bh, Bl, Kd, m0, n0, tid, lane, wr, wc, A);

#pragma unroll
    for (int mt = 0; mt < 2; mt++) {
        int row = m0 + wr * 32 + mt * 16 + (lane >> 2);
#pragma unroll
        for (int nt = 0; nt < 8; nt++) {
            int col = n0 + wc * 64 + nt * 8 + (lane & 3) * 2;
            float b0 = bias[col], b1 = bias[col + 1];
            float2 v0 = make_float2(A.c[mt][nt][0] + b0, A.c[mt][nt][1] + b1);
            float2 v1 = make_float2(A.c[mt][nt][2] + b0, A.c[mt][nt][3] + b1);
            if (relu) {
                v0.x = fmaxf(v0.x, 0.f); v0.y = fmaxf(v0.y, 0.f);
                v1.x = fmaxf(v1.x, 0.f); v1.y = fmaxf(v1.y, 0.f);
            }
            if (C) {
                *(float2*)(C + (size_t)row * Nd + col) = v0;
                *(float2*)(C + (size_t)(row + 8) * Nd + col) = v1;
            }
            if (Ch) {
                bf16 h0, l0, h1, l1;
                bsplit(v0.x, h0, l0); bsplit(v0.y, h1, l1);
                *(bf162*)(Ch + (size_t)row * Nd + col) = bf162(h0, h1);
                *(bf162*)(Cl + (size_t)row * Nd + col) = bf162(l0, l1);
                bsplit(v1.x, h0, l0); bsplit(v1.y, h1, l1);
                *(bf162*)(Ch + (size_t)(row + 8) * Nd + col) = bf162(h0, h1);
                *(bf162*)(Cl + (size_t)(row + 8) * Nd + col) = bf162(l0, l1);
            }
        }
    }
}

// ---------------- QK stats via bf16x3 + ldmatrix ----------------------------
__global__ __launch_bounds__(256, 1) void qk_bf(
    const bf16* __restrict__ Qh, const bf16* __restrict__ Ql,
    const bf16* __restrict__ Ksh, const bf16* __restrict__ Ksl,
    float* __restrict__ Mout)
{
    extern __shared__ uint32_t smem_u[];
    uint32_t sb = s2u(smem_u);
    int tid = threadIdx.x, lane = tid & 31, wid = tid >> 5;
    int m0 = blockIdx.x * 128, bh = blockIdx.y;
    int wr = wid >> 1, wc = wid & 1;

    {
        const bf16* qh = Qh + ((size_t)bh * Lc + m0) * 64;
        const bf16* ql = Ql + ((size_t)bh * Lc + m0) * 64;
#pragma unroll
        for (int i = 0; i < 4; i++) {
            int idx = tid + i * 256;
            int r = idx >> 3, c16 = idx & 7;
            float4 v = *(const float4*)(qh + (size_t)r * 64 + c16 * 8);
            *(float4*)(smem_u + r * 36 + c16 * 4) = v;
            v = *(const float4*)(ql + (size_t)r * 64 + c16 * 8);
            *(float4*)(smem_u + 4608 + r * 36 + c16 * 4) = v;
        }
    }

    const bf16* kh = Ksh + (size_t)bh * Uc * 64;
    const bf16* kl = Ksl + (size_t)bh * Uc * 64;
    int rld = tid >> 2, sgp = tid & 3;

    uint32_t aoff = (uint32_t)(wr * 32 + (lane & 7) + ((lane >> 3) & 1) * 8) * 144
                  + ((lane >> 4) & 1) * 16;
    uint32_t boff = (uint32_t)(wc * 32 + ((lane >> 4) & 1) * 8 + (lane & 7)) * 144
                  + ((lane >> 3) & 1) * 16;

#pragma unroll
    for (int pre = 0; pre < 2; pre++) {
        uint32_t st = sb + 36864 + pre * 18432;
        const bf16* s0 = kh + (size_t)(pre * 64 + rld) * 64 + sgp * 16;
        const bf16* s1 = kl + (size_t)(pre * 64 + rld) * 64 + sgp * 16;
        uint32_t d0 = st + rld * 144 + sgp * 32;
        cpa16(d0, s0); cpa16(d0 + 16, s0 + 8);
        uint32_t d1 = d0 + 9216;
        cpa16(d1, s1); cpa16(d1 + 16, s1 + 8);
        cpcommit();
    }
    __syncthreads();

    float rmax[2][2], rsum[2][2];
#pragma unroll
    for (int i = 0; i < 2; i++)
#pragma unroll
        for (int j = 0; j < 2; j++) { rmax[i][j] = -FLT_MAX; rsum[i][j] = 0.f; }

    for (int ch = 0; ch < 32; ch++) {
        int s = ch % 3;
        if (ch + 2 < 32) {
            uint32_t st = sb + 36864 + ((ch + 2) % 3) * 18432;
            const bf16* s0 = kh + (size_t)((ch + 2) * 64 + rld) * 64 + sgp * 16;
            const bf16* s1 = kl + (size_t)((ch + 2) * 64 + rld) * 64 + sgp * 16;
            uint32_t d0 = st + rld * 144 + sgp * 32;
            cpa16(d0, s0); cpa16(d0 + 16, s0 + 8);
            uint32_t d1 = d0 + 9216;
            cpa16(d1, s1); cpa16(d1 + 16, s1 + 8);
            cpcommit();
            cpwait<2>();
        } else if (ch + 2 == 32) {
            cpwait<1>();
        } else {
            cpwait<0>();
        }
        __syncthreads();

        uint32_t bbase = sb + 36864 + s * 18432;

        float c[2][4][4];
#pragma unroll
        for (int i = 0; i < 2; i++)
#pragma unroll
            for (int j = 0; j < 4; j++)
#pragma unroll
                for (int r = 0; r < 4; r++) c[i][j][r] = 0.f;

#pragma unroll
        for (int st = 0; st < 4; st++) {
            uint32_t kb = st * 32;
            uint32_t ah[2][4], al[2][4], bh4[2][4], bl4[2][4];
            ldsm4(ah[0], sb + aoff + kb);
            ldsm4(ah[1], sb + aoff + 16 * 144 + kb);
            ldsm4(al[0], sb + 18432 + aoff + kb);
            ldsm4(al[1], sb + 18432 + aoff + 16 * 144 + kb);
#pragma unroll
            for (int p = 0; p < 2; p++) {
                ldsm4(bh4[p], bbase + boff + p * 16 * 144 + kb);
                ldsm4(bl4[p], bbase + 9216 + boff + p * 16 * 144 + kb);
            }
#pragma unroll
            for (int mt = 0; mt < 2; mt++)
#pragma unroll
                for (int nt = 0; nt < 4; nt++) {
                    const uint32_t* bhp = &bh4[nt >> 1][(nt & 1) * 2];
                    const uint32_t* blp = &bl4[nt >> 1][(nt & 1) * 2];
                    mma16(c[mt][nt], ah[mt], bhp);
                    mma16(c[mt][nt], ah[mt], blp);
                    mma16(c[mt][nt], al[mt], bhp);
                }
        }

#pragma unroll
        for (int mt = 0; mt < 2; mt++)
#pragma unroll
            for (int hf = 0; hf < 2; hf++) {
                float mx = -FLT_MAX, sm = 0.f;
#pragma unroll
                for (int nt = 0; nt < 4; nt++) {
                    float v0 = c[mt][nt][hf * 2], v1 = c[mt][nt][hf * 2 + 1];
                    mx = fmaxf(mx, fmaxf(v0, v1));
                    sm += v0 + v1;
                }
                mx = fmaxf(mx, __shfl_xor_sync(0xffffffffu, mx, 1));
                sm += __shfl_xor_sync(0xffffffffu, sm, 1);
                mx = fmaxf(mx, __shfl_xor_sync(0xffffffffu, mx, 2));
                sm += __shfl_xor_sync(0xffffffffu, sm, 2);
                rmax[mt][hf] = fmaxf(rmax[mt][hf], mx);
                rsum[mt][hf] += sm;
            }
        __syncthreads();
    }

    float* red = (float*)(smem_u + 23040);
    if ((lane & 3) == 0) {
#pragma unroll
        for (int mt = 0; mt < 2; mt++)
#pragma unroll
            for (int hf = 0; hf < 2; hf++) {
                int row = wr * 32 + mt * 16 + (lane >> 2) + hf * 8;
                red[(wc * 128 + row) * 2 + 0] = rmax[mt][hf];
                red[(wc * 128 + row) * 2 + 1] = rsum[mt][hf];
            }
    }
    __syncthreads();
    if (tid < 128) {
        float m0v = red[tid * 2], s0v = red[tid * 2 + 1];
        float m1v = red[(128 + tid) * 2], s1v = red[(128 + tid) * 2 + 1];
        Mout[(size_t)bh * Lc + m0 + tid] =
            fmaxf(m0v, m1v) - (s0v + s1v) * (1.f / (float)Lc);
    }
}

// ---------------- merged weight prep: QKV concat + W1 + W2 ------------------
// flat grid: [0,3072) qkv -> Wqkv[3072][1024] | [3072,7168) w1 | [7168,11264) w2
__global__ void wsplit_all(
    const float* __restrict__ wq, const float* __restrict__ wk,
    const float* __restrict__ wv, const float* __restrict__ w1,
    const float* __restrict__ w2,
    bf16* __restrict__ Wqkvh, bf16* __restrict__ Wqkvl,
    bf16* __restrict__ W1h, bf16* __restrict__ W1l,
    bf16* __restrict__ W2h, bf16* __restrict__ W2l)
{
    int bid = blockIdx.x;
    const float* W; bf16 *Wh, *Wl; int Kd, Nd, bx, by; size_t nbase = 0;
    if (bid < 3072) {
        int w = bid >> 10, local = bid & 1023;
        W = (w == 0) ? wq : (w == 1) ? wk : wv;
        Wh = Wqkvh; Wl = Wqkvl; nbase = (size_t)w * Dc;
        Kd = Dc; Nd = Dc; bx = local & 31; by = local >> 5;
    } else if (bid < 7168) {
        int local = bid - 3072;
        W = w1; Wh = W1h; Wl = W1l;
        Kd = Dc; Nd = Fc; bx = local & 127; by = local >> 7;
    } else {
        int local = bid - 7168;
        W = w2; Wh = W2h; Wl = W2l;
        Kd = Fc; Nd = Dc; bx = local & 31; by = local >> 5;
    }
    __shared__ float t[32][33];
    int x = threadIdx.x, y = threadIdx.y;
    int n0 = bx * 32, k0 = by * 32;
#pragma unroll
    for (int i = 0; i < 32; i += 8)
        t[y + i][x] = W[(size_t)(k0 + y + i) * Nd + n0 + x];
    __syncthreads();
#pragma unroll
    for (int i = 0; i < 32; i += 8) {
        float v = t[x][y + i];
        bf16 h, l;
        bsplit(v, h, l);
        size_t o = (nbase + n0 + y + i) * Kd + k0 + x;
        Wh[o] = h;
        Wl[o] = l;
    }
}

__global__ void biascat_kernel(const float* __restrict__ bq, const float* __restrict__ bk,
                               const float* __restrict__ bv, float* __restrict__ dst)
{
    int i = blockIdx.x * 256 + threadIdx.x;       // 0..3071
    const float* s = (i < 1024) ? bq : (i < 2048) ? bk : bv;
    dst[i] = s[i & 1023];
}

__global__ void xsplit_kernel(const float* __restrict__ src, bf16* __restrict__ hi,
                              bf16* __restrict__ lo)
{
    int i = blockIdx.x * 256 + threadIdx.x;
    float4 v = ((const float4*)src)[i];
    bf16 h0, l0, h1, l1, h2, l2, h3, l3;
    bsplit(v.x, h0, l0); bsplit(v.y, h1, l1);
    bsplit(v.z, h2, l2); bsplit(v.w, h3, l3);
    ((bf162*)hi)[i * 2]     = bf162(h0, h1);
    ((bf162*)hi)[i * 2 + 1] = bf162(h2, h3);
    ((bf162*)lo)[i * 2]     = bf162(l0, l1);
    ((bf162*)lo)[i * 2 + 1] = bf162(l2, l3);
}

__global__ void gather_split_kernel(const float* __restrict__ K, const int* __restrict__ idx,
                                    bf16* __restrict__ Ksh, bf16* __restrict__ Ksl)
{
    int j = blockIdx.x, b = blockIdx.y, t = threadIdx.x;
    int src = idx[j];
    float4 v = *(const float4*)(K + ((size_t)b * Lc + src) * Dc + t * 4);
    int h = t >> 4, e = (t & 15) * 4;
    bf16 h0, l0, h1, l1, h2, l2, h3, l3;
    bsplit(v.x, h0, l0); bsplit(v.y, h1, l1);
    bsplit(v.z, h2, l2); bsplit(v.w, h3, l3);
    size_t o = (((size_t)(b * 16 + h)) * Uc + j) * 64 + e;
    *(bf162*)(Ksh + o)     = bf162(h0, h1);
    *(bf162*)(Ksh + o + 2) = bf162(h2, h3);
    *(bf162*)(Ksl + o)     = bf162(l0, l1);
    *(bf162*)(Ksl + o + 2) = bf162(l2, l3);
}

__global__ __launch_bounds__(256) void topk_kernel(const float* __restrict__ Mv,
                                                   int* __restrict__ Mtop)
{
    __shared__ float sv[Lc];
    __shared__ float rv[256];
    __shared__ int   ri[256];
    int bh = blockIdx.x, tid = threadIdx.x;
    for (int i = tid; i < Lc; i += 256) sv[i] = Mv[(size_t)bh * Lc + i];
    __syncthreads();
    for (int it = 0; it < TOPK; it++) {
        float bv = FLT_MAX; int bi = 0x7fffffff;
        for (int i = tid; i < Lc; i += 256) {
            float v = sv[i];
            if (v < bv || (v == bv && i < bi)) { bv = v; bi = i; }
        }
        rv[tid] = bv; ri[tid] = bi;
        __syncthreads();
        for (int s = 128; s > 0; s >>= 1) {
            if (tid < s) {
                float v2 = rv[tid + s]; int i2 = ri[tid + s];
                if (v2 < rv[tid] || (v2 == rv[tid] && i2 < ri[tid])) {
                    rv[tid] = v2; ri[tid] = i2;
                }
            }
            __syncthreads();
        }
        if (tid == 0) { Mtop[bh * TOPK + it] = ri[0]; sv[ri[0]] = FLT_MAX; }
        __syncthreads();
    }
}

// ---------------- sparse attention: 2 blocks per (b,h), 20 queries each -----
__global__ __launch_bounds__(128, 1) void sparse_attn2(
    const float* __restrict__ Q, const float* __restrict__ K, const float* __restrict__ V,
    const int* __restrict__ Mtop, float* __restrict__ outred)
{
    extern __shared__ float sm[];
    float* qs   = sm;
    float* ks   = sm + 1280;
    float* vs   = sm + 5440;
    float* wbuf = sm + 9536;

    int half = blockIdx.x, bh = blockIdx.y;
    int b = bh >> 4, h = bh & 15;
    int tid = threadIdx.x, lane = tid & 31, warp = tid >> 5;
    int qb = half * 20;

    for (int i = tid; i < 20 * 64; i += 128) {
        int q = i >> 6, d = i & 63;
        int qi = Mtop[bh * TOPK + qb + q];
        qs[i] = Q[((size_t)bh * Lc + qi) * 64 + d];
    }

    const float* kb = K + (size_t)b * Lc * Dc + h * 64;
    const float* vb = V + (size_t)b * Lc * Dc + h * 64;

    float m[5], sum[5], acc0[5], acc1[5];
#pragma unroll
    for (int q = 0; q < 5; q++) {
        m[q] = -FLT_MAX; sum[q] = 0.f; acc0[q] = 0.f; acc1[q] = 0.f;
    }
    float* wq = wbuf + warp * 320;

    for (int l0 = 0; l0 < Lc; l0 += 64) {
        __syncthreads();
        for (int i = tid; i < 64 * 64; i += 128) {
            int row = i >> 6, d = i & 63;
            ks[d * 65 + row] = kb[(size_t)(l0 + row) * Dc + d];
            vs[i] = vb[(size_t)(l0 + row) * Dc + d];
        }
        __syncthreads();

#pragma unroll
        for (int q = 0; q < 5; q++) {
            const float* qrow = qs + (warp * 5 + q) * 64;
            float s0 = 0.f, s1 = 0.f;
#pragma unroll
            for (int d = 0; d < 64; d++) {
                float qv = qrow[d];
                s0 = fmaf(qv, ks[d * 65 + lane], s0);
                s1 = fmaf(qv, ks[d * 65 + lane + 32], s1);
            }
            s0 *= 0.125f; s1 *= 0.125f;
            float cmx = fmaxf(s0, s1);
#pragma unroll
            for (int off = 16; off > 0; off >>= 1)
                cmx = fmaxf(cmx, __shfl_xor_sync(0xffffffffu, cmx, off));
            float nm = fmaxf(m[q], cmx);
            float scale = expf(m[q] - nm);
            float w0 = expf(s0 - nm), w1 = expf(s1 - nm);
            float csum = w0 + w1;
#pragma unroll
            for (int off = 16; off > 0; off >>= 1)
                csum += __shfl_xor_sync(0xffffffffu, csum, off);
            sum[q] = sum[q] * scale + csum;
            m[q] = nm;
            wq[q * 64 + lane] = w0;
            wq[q * 64 + lane + 32] = w1;
            __syncwarp();
            float a0 = acc0[q] * scale, a1 = acc1[q] * scale;
#pragma unroll
            for (int k = 0; k < 64; k++) {
                float wv = wq[q * 64 + k];
                a0 = fmaf(wv, vs[k * 64 + lane], a0);
                a1 = fmaf(wv, vs[k * 64 + lane + 32], a1);
            }
            acc0[q] = a0; acc1[q] = a1;
            __syncwarp();
        }
    }

#pragma unroll
    for (int q = 0; q < 5; q++) {
        float inv = 1.0f / sum[q];
        size_t o = ((size_t)bh * TOPK + qb + warp * 5 + q) * 64;
        outred[o + lane] = acc0[q] * inv;
        outred[o + lane + 32] = acc1[q] * inv;
    }
}

__global__ void init_bias_kernel(const float* __restrict__ bo, float* __restrict__ AO)
{
    float4 v = *(const float4*)(bo + threadIdx.x * 4);
    *(float4*)(AO + (size_t)blockIdx.x * Dc + threadIdx.x * 4) = v;
}

__global__ __launch_bounds__(256) void sparse_proj_kernel(
    const float* __restrict__ outred, const int* __restrict__ Mtop,
    const float* __restrict__ wo, float* __restrict__ AO)
{
    int ui = blockIdx.x, bh = blockIdx.y;
    int b = bh >> 4, h = bh & 15;
    int l = Mtop[bh * TOPK + ui];
    __shared__ float r[64];
    int tid = threadIdx.x;
    if (tid < 64) r[tid] = outred[((size_t)bh * TOPK + ui) * 64 + tid];
    __syncthreads();
    float a0 = 0.f, a1 = 0.f, a2 = 0.f, a3 = 0.f;
    const float* w = wo + (size_t)h * 64 * Dc + tid;
#pragma unroll 8
    for (int e = 0; e < 64; e++) {
        float re = r[e];
        const float* wr = w + (size_t)e * Dc;
        a0 = fmaf(re, wr[0],   a0);
        a1 = fmaf(re, wr[256], a1);
        a2 = fmaf(re, wr[512], a2);
        a3 = fmaf(re, wr[768], a3);
    }
    float* dst = AO + ((size_t)b * Lc + l) * Dc + tid;
    atomicAdd(dst,       a0);
    atomicAdd(dst + 256, a1);
    atomicAdd(dst + 512, a2);
    atomicAdd(dst + 768, a3);
}

__global__ __launch_bounds__(256) void add_ln_kernel(
    const float* __restrict__ X, const float* __restrict__ Y,
    const float* __restrict__ g, const float* __restrict__ be,
    float* __restrict__ out, bf16* __restrict__ oh, bf16* __restrict__ ol)
{
    int row = blockIdx.x, tid = threadIdx.x;
    __shared__ float red[256];
    float v[4];
    float s = 0.f;
#pragma unroll
    for (int c = 0; c < 4; c++) {
        size_t i = (size_t)row * Dc + tid + c * 256;
        v[c] = X[i] + Y[i];
        s += v[c];
    }
    red[tid] = s; __syncthreads();
    for (int st = 128; st > 0; st >>= 1) {
        if (tid < st) red[tid] += red[tid + st];
        __syncthreads();
    }
    float mean = red[0] * (1.f / 1024.f);
    __syncthreads();
    float s2 = 0.f;
#pragma unroll
    for (int c = 0; c < 4; c++) { float t = v[c] - mean; s2 = fmaf(t, t, s2); }
    red[tid] = s2; __syncthreads();
    for (int st = 128; st > 0; st >>= 1) {
        if (tid < st) red[tid] += red[tid + st];
        __syncthreads();
    }
    float var = red[0] * (1.f / 1024.f);
    float rstd = 1.0f / sqrtf(var + 1e-12f);
#pragma unroll
    for (int c = 0; c < 4; c++) {
        int col = tid + c * 256;
        float o = g[col] * ((v[c] - mean) * rstd) + be[col];
        out[(size_t)row * Dc + col] = o;
        if (oh) {
            bf16 h, l;
            bsplit(o, h, l);
            oh[(size_t)row * Dc + col] = h;
            ol[(size_t)row * Dc + col] = l;
        }
    }
}

// ---------------- launch ----------------------------------------------------
extern "C" void kernel_launch(void* const* d_in, const int* in_sizes, int n_in,
                              void* d_out, int out_size)
{
    const float* x   = (const float*)d_in[0];
    const float* wq  = (const float*)d_in[1];
    const float* bq  = (const float*)d_in[2];
    const float* wk  = (const float*)d_in[3];
    const float* bk  = (const float*)d_in[4];
    const float* wv  = (const float*)d_in[5];
    const float* bv  = (const float*)d_in[6];
    const float* wo  = (const float*)d_in[7];
    const float* bo  = (const float*)d_in[8];
    const float* w1  = (const float*)d_in[9];
    const float* b1  = (const float*)d_in[10];
    const float* w2  = (const float*)d_in[11];
    const float* b2  = (const float*)d_in[12];
    const float* ga1 = (const float*)d_in[13];
    const float* be1 = (const float*)d_in[14];
    const float* ga2 = (const float*)d_in[15];
    const float* be2 = (const float*)d_in[16];
    const int*   idx = (const int*)d_in[17];
    float* out = (float*)d_out;

    float *Q, *K, *V, *AO, *X1, *Y2, *Mv, *Or, *Bqkv;
    bf16 *Xbh, *Xbl, *Qbh, *Qbl, *X1bh, *X1bl, *Y1bh, *Y1bl, *Ksbh, *Ksbl;
    bf16 *Wqkvh, *Wqkvl, *W1h, *W1l, *W2h, *W2l;
    int* Mt;
    cudaGetSymbolAddress((void**)&Q,     g_Q);
    cudaGetSymbolAddress((void**)&K,     g_K);
    cudaGetSymbolAddress((void**)&V,     g_V);
    cudaGetSymbolAddress((void**)&AO,    g_AO);
    cudaGetSymbolAddress((void**)&X1,    g_X1);
    cudaGetSymbolAddress((void**)&Y2,    g_Y2);
    cudaGetSymbolAddress((void**)&Mv,    g_M);
    cudaGetSymbolAddress((void**)&Mt,    g_Mtop);
    cudaGetSymbolAddress((void**)&Or,    g_Or);
    cudaGetSymbolAddress((void**)&Bqkv,  g_bqkv);
    cudaGetSymbolAddress((void**)&Xbh,   g_Xbh);
    cudaGetSymbolAddress((void**)&Xbl,   g_Xbl);
    cudaGetSymbolAddress((void**)&Qbh,   g_Qbh);
    cudaGetSymbolAddress((void**)&Qbl,   g_Qbl);
    cudaGetSymbolAddress((void**)&X1bh,  g_X1bh);
    cudaGetSymbolAddress((void**)&X1bl,  g_X1bl);
    cudaGetSymbolAddress((void**)&Y1bh,  g_Y1bh);
    cudaGetSymbolAddress((void**)&Y1bl,  g_Y1bl);
    cudaGetSymbolAddress((void**)&Ksbh,  g_Ksbh);
    cudaGetSymbolAddress((void**)&Ksbl,  g_Ksbl);
    cudaGetSymbolAddress((void**)&Wqkvh, g_Wqkvh);
    cudaGetSymbolAddress((void**)&Wqkvl, g_Wqkvl);
    cudaGetSymbolAddress((void**)&W1h,   g_W1h);
    cudaGetSymbolAddress((void**)&W1l,   g_W1l);
    cudaGetSymbolAddress((void**)&W2h,   g_W2h);
    cudaGetSymbolAddress((void**)&W2l,   g_W2l);

    static cudaStream_t s_aux = 0;
    static cudaEvent_t evA = 0, evW = 0;
    if (!s_aux) {
        cudaStreamCreateWithFlags(&s_aux, cudaStreamNonBlocking);
        cudaEventCreateWithFlags(&evA, cudaEventDisableTiming);
        cudaEventCreateWithFlags(&evW, cudaEventDisableTiming);
    }

    cudaFuncSetAttribute(gemm_bf,  cudaFuncAttributeMaxDynamicSharedMemorySize, 2 * GSTB);
    cudaFuncSetAttribute(gemm_qkv, cudaFuncAttributeMaxDynamicSharedMemorySize, 2 * GSTB);
    cudaFuncSetAttribute(qk_bf,    cudaFuncAttributeMaxDynamicSharedMemorySize, 94208);
    cudaFuncSetAttribute(sparse_attn2, cudaFuncAttributeMaxDynamicSharedMemorySize, 43264);

    dim3 t32x8(32, 8);

    // fork: aux does weight prep + AO init while main does x split
    cudaEventRecord(evA, 0);
    cudaStreamWaitEvent(s_aux, evA, 0);
    wsplit_all<<<11264, t32x8, 0, s_aux>>>(wq, wk, wv, w1, w2,
                                           Wqkvh, Wqkvl, W1h, W1l, W2h, W2l);
    biascat_kernel<<<12, 256, 0, s_aux>>>(bq, bk, bv, Bqkv);
    init_bias_kernel<<<MR, 256, 0, s_aux>>>(bo, AO);
    cudaEventRecord(evW, s_aux);

    xsplit_kernel<<<(MR * Dc / 4) / 256, 256>>>(x, Xbh, Xbl);
    cudaStreamWaitEvent(0, evW, 0);

    // fused QKV projection (1536 CTAs)
    gemm_qkv<<<dim3(24, 64), 256, 2 * GSTB>>>(Xbh, Xbl, Wqkvh, Wqkvl, Bqkv,
                                              Q, K, V, Qbh, Qbl);

    gather_split_kernel<<<dim3(Uc, Bc), 256>>>(K, idx, Ksbh, Ksbl);
    qk_bf<<<dim3(Lc / 128, BHc), 256, 94208>>>(Qbh, Qbl, Ksbh, Ksbl, Mv);
    topk_kernel<<<BHc, 256>>>(Mv, Mt);

    sparse_attn2<<<dim3(2, BHc), 128, 43264>>>(Q, K, V, Mt, Or);
    sparse_proj_kernel<<<dim3(TOPK, BHc), 256>>>(Or, Mt, wo, AO);

    add_ln_kernel<<<MR, 256>>>(x, AO, ga1, be1, X1, X1bh, X1bl);

    gemm_bf<<<dim3(32, 64), 256, 2 * GSTB>>>(X1bh, X1bl, W1h, W1l, b1, (float*)0, Y1bh, Y1bl, Dc, Fc, 1);
    gemm_bf<<<dim3(8, 64), 256, 2 * GSTB>>>(Y1bh, Y1bl, W2h, W2l, b2, Y2, (bf16*)0, (bf16*)0, Fc, Dc, 0);

    add_ln_kernel<<<MR, 256>>>(X1, Y2, ga2, be2, out, (bf16*)0, (bf16*)0);
}